// round 11
// baseline (speedup 1.0000x reference)
#include <cuda_runtime.h>
#include <cuda_fp16.h>
#include <math.h>
#include <stdint.h>

#define NN 50000
#define EE 800000
#define IND 256
#define HIDD 64
#define H0 4
#define OUT1 256
#define NCLS 64
#define NEG 0.2f
#define NA_SPLIT 25088   // agg0 / GEMM1 pipeline split (multiple of 128)
#define NB_SPLIT 25088   // agg1 / classifier pipeline split (multiple of 128)

// ---------------- scratch (device globals; no allocation allowed) ----------
__device__ __half g_ft16[NN * 256];
__device__ float  g_h1[NN * 256];
__device__ float  g_el[NN * H0];
__device__ float  g_er[NN * H0];
__device__ float  g_el1[NN];
__device__ float  g_er1[NN];
__device__ float  g_wel0[8 * 256];
__device__ float  g_wel1[2 * 256];
__device__ int    g_cnt[NN];
__device__ int    g_rowptr[NN + 1];
__device__ int    g_bsum[64];
__device__ int    g_adj[EE];

// =================== CSR build ==============================================
__global__ void hist_kernel(const int* __restrict__ dst, int* __restrict__ cnt) {
    int e = blockIdx.x * blockDim.x + threadIdx.x;
    if (e < EE) atomicAdd(&cnt[dst[e]], 1);
}

__global__ void scan_block_kernel(const int* __restrict__ cnt,
                                  int* __restrict__ rowptr,
                                  int* __restrict__ bsum) {
    __shared__ int sh[1024];
    int t = threadIdx.x;
    int i = blockIdx.x * 1024 + t;
    int v = (i < NN) ? cnt[i] : 0;
    sh[t] = v;
    __syncthreads();
    for (int off = 1; off < 1024; off <<= 1) {
        int add = (t >= off) ? sh[t - off] : 0;
        __syncthreads();
        sh[t] += add;
        __syncthreads();
    }
    if (i < NN) rowptr[i] = sh[t] - v;
    if (t == 1023) bsum[blockIdx.x] = sh[t];
}

__global__ void scan_bsum_kernel(int* __restrict__ bsum, int nb) {
    __shared__ int sh[64];
    int t = threadIdx.x;
    int v = (t < nb) ? bsum[t] : 0;
    sh[t] = v;
    __syncthreads();
    for (int off = 1; off < 64; off <<= 1) {
        int add = (t >= off) ? sh[t - off] : 0;
        __syncthreads();
        sh[t] += add;
        __syncthreads();
    }
    if (t < nb) bsum[t] = sh[t] - v;
}

__global__ void scan_add_kernel(int* __restrict__ rowptr,
                                const int* __restrict__ bsum,
                                int* __restrict__ cursor) {
    int i = blockIdx.x * blockDim.x + threadIdx.x;
    if (i < NN) {
        int r = rowptr[i] + bsum[i >> 10];
        rowptr[i] = r;
        cursor[i] = r;
    }
    if (i == 0) rowptr[NN] = EE;
}

__global__ void csr_fill_kernel(const int* __restrict__ src,
                                const int* __restrict__ dst,
                                int* __restrict__ cursor,
                                int* __restrict__ adj) {
    int e = blockIdx.x * blockDim.x + threadIdx.x;
    if (e >= EE) return;
    int pos = atomicAdd(&cursor[dst[e]], 1);
    adj[pos] = src[e];
}

// =================== attention projection prep ==============================
__global__ void prep_wel_kernel(const float* __restrict__ W0,
                                const float* __restrict__ al0,
                                const float* __restrict__ ar0,
                                const float* __restrict__ W1,
                                const float* __restrict__ al1,
                                const float* __restrict__ ar1,
                                float* __restrict__ wel0,
                                float* __restrict__ wel1) {
    int k = threadIdx.x;
    if (blockIdx.x == 0) {
#pragma unroll
        for (int j = 0; j < 4; j++) {
            float sl = 0.f, sr = 0.f;
            for (int d = 0; d < 64; d++) {
                float wv = W0[k * 256 + j * 64 + d];
                sl += wv * al0[j * 64 + d];
                sr += wv * ar0[j * 64 + d];
            }
            wel0[j * 256 + k] = sl;
            wel0[(4 + j) * 256 + k] = sr;
        }
    } else {
        float sl = 0.f, sr = 0.f;
        for (int d = 0; d < 256; d++) {
            float wv = W1[k * 256 + d];
            sl += wv * al1[d];
            sr += wv * ar1[d];
        }
        wel1[k] = sl;
        wel1[256 + k] = sr;
    }
}

__global__ void __launch_bounds__(256)
eler0_kernel(const float* __restrict__ X, const float* __restrict__ WelT,
             float* __restrict__ el, float* __restrict__ er) {
    __shared__ float w[8][256];
    int tid = threadIdx.x;
    for (int i = tid; i < 8 * 256; i += 256) ((float*)w)[i] = WelT[i];
    __syncthreads();
    int n = blockIdx.x * 8 + (tid >> 5);
    int lane = tid & 31;
    if (n >= NN) return;
    const float* xr = X + (size_t)n * 256;
    float acc[8];
#pragma unroll
    for (int j = 0; j < 8; j++) acc[j] = 0.f;
#pragma unroll
    for (int it = 0; it < 8; it++) {
        float xv = xr[lane + it * 32];
#pragma unroll
        for (int j = 0; j < 8; j++) acc[j] += xv * w[j][lane + it * 32];
    }
#pragma unroll
    for (int o = 16; o; o >>= 1)
#pragma unroll
        for (int j = 0; j < 8; j++) acc[j] += __shfl_xor_sync(0xffffffffu, acc[j], o);
    if (lane == 0) {
#pragma unroll
        for (int j = 0; j < 4; j++) el[n * 4 + j] = acc[j];
#pragma unroll
        for (int j = 0; j < 4; j++) er[n * 4 + j] = acc[4 + j];
    }
}

// =================== GEMM helpers ===========================================
__device__ __forceinline__ uint32_t packbf(float f0, float f1) {
    uint32_t r;
    asm("cvt.rn.bf16x2.f32 %0, %1, %2;" : "=r"(r) : "f"(f1), "f"(f0));
    return r;
}
__device__ __forceinline__ uint32_t packh(float f0, float f1) {
    uint32_t r;
    asm("cvt.rn.f16x2.f32 %0, %1, %2;" : "=r"(r) : "f"(f1), "f"(f0));
    return r;
}
__device__ __forceinline__ void bfsplit2(float f0, float f1,
                                         uint32_t& h, uint32_t& l) {
    h = packbf(f0, f1);
    float h0 = __uint_as_float(h << 16);
    float h1 = __uint_as_float(h & 0xffff0000u);
    l = packbf(f0 - h0, f1 - h1);
}

#define MMA_BF16(d, a, b) \
    asm volatile("mma.sync.aligned.m16n8k16.row.col.f32.bf16.bf16.f32 " \
                 "{%0,%1,%2,%3}, {%4,%5,%6,%7}, {%8,%9}, {%0,%1,%2,%3};" \
                 : "+f"(d[0]), "+f"(d[1]), "+f"(d[2]), "+f"(d[3]) \
                 : "r"(a[0]), "r"(a[1]), "r"(a[2]), "r"(a[3]), \
                   "r"(b[0]), "r"(b[1]))

#define MMA_F16(d, a, b) \
    asm volatile("mma.sync.aligned.m16n8k16.row.col.f32.f16.f16.f32 " \
                 "{%0,%1,%2,%3}, {%4,%5,%6,%7}, {%8,%9}, {%0,%1,%2,%3};" \
                 : "+f"(d[0]), "+f"(d[1]), "+f"(d[2]), "+f"(d[3]) \
                 : "r"(a[0]), "r"(a[1]), "r"(a[2]), "r"(a[3]), \
                   "r"(b[0]), "r"(b[1]))

// ---- fp16 single-term GEMM: C16[Nr,M] = fp16(A[Nr,K] @ B[K,M]) --------------
template<int BM, int BN, int WARPS_M, int WARPS_N>
__global__ void __launch_bounds__(256, 2)
gemm_f16(const float* __restrict__ A, const float* __restrict__ B,
         __half* __restrict__ C16, int Nr, int K, int M) {
    constexpr int WM = BM / WARPS_M;
    constexpr int WN = BN / WARPS_N;
    constexpr int MF = WM / 16;
    constexpr int NF = WN / 8;
    constexpr int LD = 136;
    constexpr int STG = 8 * LD;
    constexpr int BQ = BN / 4;

    __shared__ uint32_t Ah[2][STG];
    __shared__ uint32_t Bh[2][STG];

    const int tid  = threadIdx.x;
    const int lane = tid & 31;
    const int warp = tid >> 5;
    const int wm = warp / WARPS_N;
    const int wn = warp % WARPS_N;
    const int rowBase = blockIdx.y * BM;
    const int colBase = blockIdx.x * BN;
    const int g  = lane >> 2;
    const int tg = lane & 3;

    float acc[MF][NF][4];
#pragma unroll
    for (int i = 0; i < MF; i++)
#pragma unroll
        for (int j = 0; j < NF; j++)
#pragma unroll
            for (int k = 0; k < 4; k++) acc[i][j][k] = 0.0f;

    float4 ra[2];
    float4 rb0, rb1;
    const int am[2]  = { (tid) >> 2, (tid + 256) >> 2 };
    const int akq = (tid & 3) << 2;
    const bool bact = tid < 8 * BQ;
    const int bkp = bact ? tid / BQ : 0;
    const int bnq = bact ? (tid % BQ) << 2 : 0;

    auto ldg_tile = [&](int k0) {
#pragma unroll
        for (int i = 0; i < 2; i++) {
            int gr = rowBase + am[i];
            int grc = (gr < Nr) ? gr : (Nr - 1);
            ra[i] = *(const float4*)(A + (size_t)grc * K + k0 + akq);
        }
        if (bact) {
            rb0 = *(const float4*)(B + (size_t)(k0 + 2 * bkp)     * M + colBase + bnq);
            rb1 = *(const float4*)(B + (size_t)(k0 + 2 * bkp + 1) * M + colBase + bnq);
        }
    };

    auto sts_tile = [&](int s) {
#pragma unroll
        for (int i = 0; i < 2; i++) {
            int kp0 = (akq >> 1);
            Ah[s][kp0 * LD + am[i]]       = packh(ra[i].x, ra[i].y);
            Ah[s][(kp0 + 1) * LD + am[i]] = packh(ra[i].z, ra[i].w);
        }
        if (bact) {
            const float* p0 = &rb0.x;
            const float* p1 = &rb1.x;
            uint32_t hh[4];
#pragma unroll
            for (int j = 0; j < 4; j++) hh[j] = packh(p0[j], p1[j]);
            *(uint4*)&Bh[s][bkp * LD + bnq] = make_uint4(hh[0], hh[1], hh[2], hh[3]);
        }
    };

    const int NIT = K / 16;
    ldg_tile(0);

    for (int it = 0; it < NIT; it++) {
        const int s = it & 1;
        sts_tile(s);
        __syncthreads();
        if (it + 1 < NIT) ldg_tile((it + 1) * 16);

        uint32_t bh[NF][2];
#pragma unroll
        for (int nf = 0; nf < NF; nf++) {
            int c0 = wn * WN + nf * 8 + g;
            bh[nf][0] = Bh[s][tg * LD + c0];
            bh[nf][1] = Bh[s][(tg + 4) * LD + c0];
        }
#pragma unroll
        for (int mf = 0; mf < MF; mf++) {
            int r0 = wm * WM + mf * 16 + g;
            uint32_t ah[4];
            ah[0] = Ah[s][tg * LD + r0];
            ah[1] = Ah[s][tg * LD + r0 + 8];
            ah[2] = Ah[s][(tg + 4) * LD + r0];
            ah[3] = Ah[s][(tg + 4) * LD + r0 + 8];
#pragma unroll
            for (int nf = 0; nf < NF; nf++)
                MMA_F16(acc[mf][nf], ah, bh[nf]);
        }
    }

#pragma unroll
    for (int mf = 0; mf < MF; mf++) {
#pragma unroll
        for (int nf = 0; nf < NF; nf++) {
            int row = rowBase + wm * WM + mf * 16 + g;
            int col = colBase + wn * WN + nf * 8 + tg * 2;
            if (row < Nr)
                *(uint32_t*)(C16 + (size_t)row * M + col) =
                    packh(acc[mf][nf][0], acc[mf][nf][1]);
            if (row + 8 < Nr)
                *(uint32_t*)(C16 + (size_t)(row + 8) * M + col) =
                    packh(acc[mf][nf][2], acc[mf][nf][3]);
        }
    }
}

// ---- bf16 3-term GEMM (classifier only): C[Nr,M] = A@B + bias --------------
template<int BM, int BN, int WARPS_M, int WARPS_N>
__global__ void __launch_bounds__(256, 2)
gemm_bf16x3(const float* __restrict__ A, const float* __restrict__ B,
            float* __restrict__ C, int Nr, int K, int M,
            const float* __restrict__ bias) {
    constexpr int WM = BM / WARPS_M;
    constexpr int WN = BN / WARPS_N;
    constexpr int MF = WM / 16;
    constexpr int NF = WN / 8;
    constexpr int LD = 136;
    constexpr int STG = 8 * LD;
    constexpr int BQ = BN / 4;

    __shared__ uint32_t Ah[2][STG], Al[2][STG];
    __shared__ uint32_t Bh[2][STG], Bl[2][STG];

    const int tid  = threadIdx.x;
    const int lane = tid & 31;
    const int warp = tid >> 5;
    const int wm = warp / WARPS_N;
    const int wn = warp % WARPS_N;
    const int rowBase = blockIdx.y * BM;
    const int colBase = blockIdx.x * BN;
    const int g  = lane >> 2;
    const int tg = lane & 3;

    float acc[MF][NF][4];
#pragma unroll
    for (int i = 0; i < MF; i++)
#pragma unroll
        for (int j = 0; j < NF; j++)
#pragma unroll
            for (int k = 0; k < 4; k++) acc[i][j][k] = 0.0f;

    float4 ra[2];
    float4 rb0, rb1;
    const int am[2]  = { (tid) >> 2, (tid + 256) >> 2 };
    const int akq = (tid & 3) << 2;
    const bool bact = tid < 8 * BQ;
    const int bkp = bact ? tid / BQ : 0;
    const int bnq = bact ? (tid % BQ) << 2 : 0;

    auto ldg_tile = [&](int k0) {
#pragma unroll
        for (int i = 0; i < 2; i++) {
            int gr = rowBase + am[i];
            int grc = (gr < Nr) ? gr : (Nr - 1);
            ra[i] = *(const float4*)(A + (size_t)grc * K + k0 + akq);
        }
        if (bact) {
            rb0 = *(const float4*)(B + (size_t)(k0 + 2 * bkp)     * M + colBase + bnq);
            rb1 = *(const float4*)(B + (size_t)(k0 + 2 * bkp + 1) * M + colBase + bnq);
        }
    };

    auto sts_tile = [&](int s) {
#pragma unroll
        for (int i = 0; i < 2; i++) {
            int kp0 = (akq >> 1);
            uint32_t h, l;
            bfsplit2(ra[i].x, ra[i].y, h, l);
            Ah[s][kp0 * LD + am[i]] = h;
            Al[s][kp0 * LD + am[i]] = l;
            bfsplit2(ra[i].z, ra[i].w, h, l);
            Ah[s][(kp0 + 1) * LD + am[i]] = h;
            Al[s][(kp0 + 1) * LD + am[i]] = l;
        }
        if (bact) {
            const float* p0 = &rb0.x;
            const float* p1 = &rb1.x;
            uint32_t hh[4], ll[4];
#pragma unroll
            for (int j = 0; j < 4; j++) bfsplit2(p0[j], p1[j], hh[j], ll[j]);
            *(uint4*)&Bh[s][bkp * LD + bnq] = make_uint4(hh[0], hh[1], hh[2], hh[3]);
            *(uint4*)&Bl[s][bkp * LD + bnq] = make_uint4(ll[0], ll[1], ll[2], ll[3]);
        }
    };

    const int NIT = K / 16;
    ldg_tile(0);

    for (int it = 0; it < NIT; it++) {
        const int s = it & 1;
        sts_tile(s);
        __syncthreads();
        if (it + 1 < NIT) ldg_tile((it + 1) * 16);

        uint32_t bh[NF][2], bl[NF][2];
#pragma unroll
        for (int nf = 0; nf < NF; nf++) {
            int c0 = wn * WN + nf * 8 + g;
            bh[nf][0] = Bh[s][tg * LD + c0];
            bh[nf][1] = Bh[s][(tg + 4) * LD + c0];
            bl[nf][0] = Bl[s][tg * LD + c0];
            bl[nf][1] = Bl[s][(tg + 4) * LD + c0];
        }
#pragma unroll
        for (int mf = 0; mf < MF; mf++) {
            int r0 = wm * WM + mf * 16 + g;
            uint32_t ah[4], al[4];
            ah[0] = Ah[s][tg * LD + r0];
            ah[1] = Ah[s][tg * LD + r0 + 8];
            ah[2] = Ah[s][(tg + 4) * LD + r0];
            ah[3] = Ah[s][(tg + 4) * LD + r0 + 8];
            al[0] = Al[s][tg * LD + r0];
            al[1] = Al[s][tg * LD + r0 + 8];
            al[2] = Al[s][(tg + 4) * LD + r0];
            al[3] = Al[s][(tg + 4) * LD + r0 + 8];
#pragma unroll
            for (int nf = 0; nf < NF; nf++) {
                MMA_BF16(acc[mf][nf], al, bh[nf]);
                MMA_BF16(acc[mf][nf], ah, bl[nf]);
                MMA_BF16(acc[mf][nf], ah, bh[nf]);
            }
        }
    }

#pragma unroll
    for (int mf = 0; mf < MF; mf++) {
#pragma unroll
        for (int nf = 0; nf < NF; nf++) {
            int row = rowBase + wm * WM + mf * 16 + g;
            int col = colBase + wn * WN + nf * 8 + tg * 2;
            float b0v = bias ? bias[col]     : 0.0f;
            float b1v = bias ? bias[col + 1] : 0.0f;
            if (row < Nr) {
                float2 o = make_float2(acc[mf][nf][0] + b0v, acc[mf][nf][1] + b1v);
                *(float2*)(C + (size_t)row * M + col) = o;
            }
            if (row + 8 < Nr) {
                float2 o = make_float2(acc[mf][nf][2] + b0v, acc[mf][nf][3] + b1v);
                *(float2*)(C + (size_t)(row + 8) * M + col) = o;
            }
        }
    }
}

// =================== aggregation: one WARP per dst node =====================
__device__ __forceinline__ void acc8(float* acc, float a, uint4 r) {
    float2 f0 = __half22float2(*reinterpret_cast<const half2*>(&r.x));
    float2 f1 = __half22float2(*reinterpret_cast<const half2*>(&r.y));
    float2 f2 = __half22float2(*reinterpret_cast<const half2*>(&r.z));
    float2 f3 = __half22float2(*reinterpret_cast<const half2*>(&r.w));
    acc[0] += a * f0.x; acc[1] += a * f0.y;
    acc[2] += a * f1.x; acc[3] += a * f1.y;
    acc[4] += a * f2.x; acc[5] += a * f2.y;
    acc[6] += a * f3.x; acc[7] += a * f3.y;
}

__global__ void __launch_bounds__(256)
agg0_kernel(const int* __restrict__ rowptr, const int* __restrict__ adj,
            const float* __restrict__ el, const float* __restrict__ er,
            const __half* __restrict__ ft, const float* __restrict__ b0,
            const float* __restrict__ wel1,
            float* __restrict__ h1,
            float* __restrict__ el1, float* __restrict__ er1,
            int nbase, int nend) {
    const int w = threadIdx.x >> 5;
    const int lane = threadIdx.x & 31;
    const int d = nbase + blockIdx.x * 8 + w;
    if (d >= nend) return;
    const int h = lane >> 3;
    const int start = rowptr[d], end = rowptr[d + 1];

    __shared__ float s_num[8][32][4];

    float4 erd = *(const float4*)(er + (size_t)d * 4);
    float lsum[4] = {0.f, 0.f, 0.f, 0.f};
    float acc[8] = {0.f, 0.f, 0.f, 0.f, 0.f, 0.f, 0.f, 0.f};

    for (int c = start; c < end; c += 32) {
        int n = min(32, end - c);
        int sidx = 0;
        if (lane < n) {
            sidx = adj[c + lane];
            float4 e4 = *(const float4*)(el + (size_t)sidx * 4);
            float v[4];
            v[0] = e4.x + erd.x; v[1] = e4.y + erd.y;
            v[2] = e4.z + erd.z; v[3] = e4.w + erd.w;
#pragma unroll
            for (int k = 0; k < 4; k++) {
                float vv = (v[k] >= 0.f) ? v[k] : NEG * v[k];
                float nu = expf(vv);
                s_num[w][lane][k] = nu;
                lsum[k] += nu;
            }
        }
        __syncwarp();
        int j = 0;
        for (; j + 4 <= n; j += 4) {
            int s0 = __shfl_sync(0xffffffffu, sidx, j);
            int s1 = __shfl_sync(0xffffffffu, sidx, j + 1);
            int s2 = __shfl_sync(0xffffffffu, sidx, j + 2);
            int s3 = __shfl_sync(0xffffffffu, sidx, j + 3);
            float a0 = s_num[w][j][h],     a1 = s_num[w][j + 1][h];
            float a2 = s_num[w][j + 2][h], a3 = s_num[w][j + 3][h];
            uint4 r0 = *(const uint4*)(ft + (size_t)s0 * 256 + lane * 8);
            uint4 r1 = *(const uint4*)(ft + (size_t)s1 * 256 + lane * 8);
            uint4 r2 = *(const uint4*)(ft + (size_t)s2 * 256 + lane * 8);
            uint4 r3 = *(const uint4*)(ft + (size_t)s3 * 256 + lane * 8);
            acc8(acc, a0, r0); acc8(acc, a1, r1);
            acc8(acc, a2, r2); acc8(acc, a3, r3);
        }
        for (; j < n; j++) {
            int s0 = __shfl_sync(0xffffffffu, sidx, j);
            float a0 = s_num[w][j][h];
            uint4 r0 = *(const uint4*)(ft + (size_t)s0 * 256 + lane * 8);
            acc8(acc, a0, r0);
        }
        __syncwarp();
    }

#pragma unroll
    for (int off = 16; off; off >>= 1)
#pragma unroll
        for (int k = 0; k < 4; k++)
            lsum[k] += __shfl_xor_sync(0xffffffffu, lsum[k], off);
    float tot = lsum[h];
    float inv = (tot > 0.f) ? (1.0f / tot) : 0.0f;

    float o[8];
    float sl = 0.f, sr = 0.f;
    const float* bb = b0 + lane * 8;
    const float* wl = wel1 + lane * 8;
    const float* wr = wel1 + 256 + lane * 8;
#pragma unroll
    for (int i = 0; i < 8; i++) {
        float v = acc[i] * inv + bb[i];
        v = (v > 0.f) ? v : expm1f(v);
        o[i] = v;
        sl += v * wl[i];
        sr += v * wr[i];
    }
    *(float4*)(h1 + (size_t)d * 256 + lane * 8)     = make_float4(o[0], o[1], o[2], o[3]);
    *(float4*)(h1 + (size_t)d * 256 + lane * 8 + 4) = make_float4(o[4], o[5], o[6], o[7]);
#pragma unroll
    for (int off = 16; off; off >>= 1) {
        sl += __shfl_xor_sync(0xffffffffu, sl, off);
        sr += __shfl_xor_sync(0xffffffffu, sr, off);
    }
    if (lane == 0) { el1[d] = sl; er1[d] = sr; }
}

__global__ void __launch_bounds__(256)
agg1_kernel(const int* __restrict__ rowptr, const int* __restrict__ adj,
            const float* __restrict__ el, const float* __restrict__ er,
            const __half* __restrict__ ft, const float* __restrict__ h1,
            const float* __restrict__ b1, float* __restrict__ hout,
            int nbase, int nend) {
    const int w = threadIdx.x >> 5;
    const int lane = threadIdx.x & 31;
    const int d = nbase + blockIdx.x * 8 + w;
    if (d >= nend) return;
    const int start = rowptr[d], end = rowptr[d + 1];

    float erd = er[d];
    float lsum = 0.f;
    float acc[8] = {0.f, 0.f, 0.f, 0.f, 0.f, 0.f, 0.f, 0.f};

    for (int c = start; c < end; c += 32) {
        int n = min(32, end - c);
        int sidx = 0;
        float nu = 0.f;
        if (lane < n) {
            sidx = adj[c + lane];
            float v = el[sidx] + erd;
            v = (v >= 0.f) ? v : NEG * v;
            nu = expf(v);
            lsum += nu;
        }
        int j = 0;
        for (; j + 4 <= n; j += 4) {
            int s0 = __shfl_sync(0xffffffffu, sidx, j);
            int s1 = __shfl_sync(0xffffffffu, sidx, j + 1);
            int s2 = __shfl_sync(0xffffffffu, sidx, j + 2);
            int s3 = __shfl_sync(0xffffffffu, sidx, j + 3);
            float a0 = __shfl_sync(0xffffffffu, nu, j);
            float a1 = __shfl_sync(0xffffffffu, nu, j + 1);
            float a2 = __shfl_sync(0xffffffffu, nu, j + 2);
            float a3 = __shfl_sync(0xffffffffu, nu, j + 3);
            uint4 r0 = *(const uint4*)(ft + (size_t)s0 * 256 + lane * 8);
            uint4 r1 = *(const uint4*)(ft + (size_t)s1 * 256 + lane * 8);
            uint4 r2 = *(const uint4*)(ft + (size_t)s2 * 256 + lane * 8);
            uint4 r3 = *(const uint4*)(ft + (size_t)s3 * 256 + lane * 8);
            acc8(acc, a0, r0); acc8(acc, a1, r1);
            acc8(acc, a2, r2); acc8(acc, a3, r3);
        }
        for (; j < n; j++) {
            int s0 = __shfl_sync(0xffffffffu, sidx, j);
            float a0 = __shfl_sync(0xffffffffu, nu, j);
            uint4 r0 = *(const uint4*)(ft + (size_t)s0 * 256 + lane * 8);
            acc8(acc, a0, r0);
        }
    }

#pragma unroll
    for (int off = 16; off; off >>= 1)
        lsum += __shfl_xor_sync(0xffffffffu, lsum, off);
    float inv = (lsum > 0.f) ? (1.0f / lsum) : 0.0f;

    float4 hr0 = *(const float4*)(h1 + (size_t)d * 256 + lane * 8);
    float4 hr1 = *(const float4*)(h1 + (size_t)d * 256 + lane * 8 + 4);
    float4 bb0 = *(const float4*)(b1 + lane * 8);
    float4 bb1 = *(const float4*)(b1 + lane * 8 + 4);
    float4 o0, o1;
    o0.x = acc[0] * inv + hr0.x + bb0.x;
    o0.y = acc[1] * inv + hr0.y + bb0.y;
    o0.z = acc[2] * inv + hr0.z + bb0.z;
    o0.w = acc[3] * inv + hr0.w + bb0.w;
    o1.x = acc[4] * inv + hr1.x + bb1.x;
    o1.y = acc[5] * inv + hr1.y + bb1.y;
    o1.z = acc[6] * inv + hr1.z + bb1.z;
    o1.w = acc[7] * inv + hr1.w + bb1.w;
    *(float4*)(hout + (size_t)d * 256 + lane * 8)     = o0;
    *(float4*)(hout + (size_t)d * 256 + lane * 8 + 4) = o1;
}

// =================== launch ==================================================
extern "C" void kernel_launch(void* const* d_in, const int* in_sizes, int n_in,
                              void* d_out, int out_size) {
    const float* x   = (const float*)d_in[0];
    const int*   src = (const int*)  d_in[1];
    const int*   dst = (const int*)  d_in[2];
    const float* W0  = (const float*)d_in[3];
    const float* al0 = (const float*)d_in[4];
    const float* ar0 = (const float*)d_in[5];
    const float* b0  = (const float*)d_in[6];
    const float* W1  = (const float*)d_in[7];
    const float* al1 = (const float*)d_in[8];
    const float* ar1 = (const float*)d_in[9];
    const float* b1  = (const float*)d_in[10];
    const float* Wl  = (const float*)d_in[11];
    const float* bl  = (const float*)d_in[12];

    float* out    = (float*)d_out;
    float* logits = out;
    float* hout   = out + (size_t)NN * NCLS;

    __half* ft16;
    float *h1v, *el, *er, *el1, *er1, *wel0, *wel1;
    int *cnt, *rowptr, *bsum, *adj;
    cudaGetSymbolAddress((void**)&ft16,   g_ft16);
    cudaGetSymbolAddress((void**)&h1v,    g_h1);
    cudaGetSymbolAddress((void**)&el,     g_el);
    cudaGetSymbolAddress((void**)&er,     g_er);
    cudaGetSymbolAddress((void**)&el1,    g_el1);
    cudaGetSymbolAddress((void**)&er1,    g_er1);
    cudaGetSymbolAddress((void**)&wel0,   g_wel0);
    cudaGetSymbolAddress((void**)&wel1,   g_wel1);
    cudaGetSymbolAddress((void**)&cnt,    g_cnt);
    cudaGetSymbolAddress((void**)&rowptr, g_rowptr);
    cudaGetSymbolAddress((void**)&bsum,   g_bsum);
    cudaGetSymbolAddress((void**)&adj,    g_adj);

    static cudaStream_t s1 = nullptr, s2 = nullptr;
    static cudaEvent_t ev_fork = nullptr, ev_csr = nullptr, ev_el0 = nullptr,
                       ev_g0 = nullptr, ev_a0b = nullptr, ev_g1 = nullptr,
                       ev_a1b = nullptr;
    if (s1 == nullptr) {
        cudaStreamCreateWithFlags(&s1, cudaStreamNonBlocking);
        cudaStreamCreateWithFlags(&s2, cudaStreamNonBlocking);
        cudaEventCreateWithFlags(&ev_fork, cudaEventDisableTiming);
        cudaEventCreateWithFlags(&ev_csr,  cudaEventDisableTiming);
        cudaEventCreateWithFlags(&ev_el0,  cudaEventDisableTiming);
        cudaEventCreateWithFlags(&ev_g0,   cudaEventDisableTiming);
        cudaEventCreateWithFlags(&ev_a0b,  cudaEventDisableTiming);
        cudaEventCreateWithFlags(&ev_g1,   cudaEventDisableTiming);
        cudaEventCreateWithFlags(&ev_a1b,  cudaEventDisableTiming);
    }

    const int T = 256;
    const int NB_SCAN = (NN + 1023) / 1024;

    cudaEventRecord(ev_fork, 0);

    // ---- s1: CSR build ----
    cudaStreamWaitEvent(s1, ev_fork, 0);
    cudaMemsetAsync(cnt, 0, NN * sizeof(int), s1);
    hist_kernel<<<(EE + T - 1) / T, T, 0, s1>>>(dst, cnt);
    scan_block_kernel<<<NB_SCAN, 1024, 0, s1>>>(cnt, rowptr, bsum);
    scan_bsum_kernel<<<1, 64, 0, s1>>>(bsum, NB_SCAN);
    scan_add_kernel<<<(NN + T - 1) / T, T, 0, s1>>>(rowptr, bsum, cnt);
    csr_fill_kernel<<<(EE + T - 1) / T, T, 0, s1>>>(src, dst, cnt, adj);
    cudaEventRecord(ev_csr, s1);

    // ---- s2: attention projections ----
    cudaStreamWaitEvent(s2, ev_fork, 0);
    prep_wel_kernel<<<2, 256, 0, s2>>>(W0, al0, ar0, W1, al1, ar1, wel0, wel1);
    eler0_kernel<<<(NN + 7) / 8, 256, 0, s2>>>(x, wel0, el, er);
    cudaEventRecord(ev_el0, s2);

    // ---- main: layer 0 projection (fp16 single-term) ----
    {
        dim3 grid(256 / 128, (NN + 127) / 128);
        gemm_f16<128, 128, 2, 4><<<grid, 256>>>(x, W0, ft16, NN, IND, 256);
    }
    cudaEventRecord(ev_g0, 0);

    // ---- agg0 chunk B on s2 (concurrent with agg0_A + GEMM1_A on main) ----
    cudaStreamWaitEvent(s2, ev_g0, 0);
    cudaStreamWaitEvent(s2, ev_csr, 0);
    {
        int nb = NN - NA_SPLIT;
        agg0_kernel<<<(nb + 7) / 8, 256, 0, s2>>>(rowptr, adj, el, er, ft16, b0,
                                                  wel1, h1v, el1, er1, NA_SPLIT, NN);
    }
    cudaEventRecord(ev_a0b, s2);

    // ---- main: agg0 chunk A, then GEMM1_A ----
    cudaStreamWaitEvent(0, ev_csr, 0);
    cudaStreamWaitEvent(0, ev_el0, 0);
    agg0_kernel<<<NA_SPLIT / 8, 256>>>(rowptr, adj, el, er, ft16, b0,
                                       wel1, h1v, el1, er1, 0, NA_SPLIT);
    {
        dim3 grid(256 / 128, NA_SPLIT / 128);
        gemm_f16<128, 128, 2, 4><<<grid, 256>>>(h1v, W1, ft16, NA_SPLIT, 256, 256);
    }

    // ---- main: GEMM1_B after agg0_B ----
    cudaStreamWaitEvent(0, ev_a0b, 0);
    {
        int nb = NN - NA_SPLIT;
        dim3 grid(256 / 128, (nb + 127) / 128);
        gemm_f16<128, 128, 2, 4><<<grid, 256>>>(
            h1v + (size_t)NA_SPLIT * 256, W1,
            ft16 + (size_t)NA_SPLIT * 256, nb, 256, 256);
    }
    cudaEventRecord(ev_g1, 0);

    // ---- agg1 chunk B on s2 (concurrent with agg1_A + cls_A on main) ----
    cudaStreamWaitEvent(s2, ev_g1, 0);
    {
        int nb = NN - NB_SPLIT;
        agg1_kernel<<<(nb + 7) / 8, 256, 0, s2>>>(rowptr, adj, el1, er1, ft16,
                                                  h1v, b1, hout, NB_SPLIT, NN);
    }
    cudaEventRecord(ev_a1b, s2);

    // ---- main: agg1 chunk A, then cls_A ----
    agg1_kernel<<<NB_SPLIT / 8, 256>>>(rowptr, adj, el1, er1, ft16,
                                       h1v, b1, hout, 0, NB_SPLIT);
    {
        dim3 grid(1, NB_SPLIT / 128);
        gemm_bf16x3<128, 64, 4, 2><<<grid, 256>>>(hout, Wl, logits, NB_SPLIT, OUT1, NCLS, bl);
    }

    // ---- main: cls_B after agg1_B ----
    cudaStreamWaitEvent(0, ev_a1b, 0);
    {
        int nb = NN - NB_SPLIT;
        dim3 grid(1, (nb + 127) / 128);
        gemm_bf16x3<128, 64, 4, 2><<<grid, 256>>>(
            hout + (size_t)NB_SPLIT * 256, Wl,
            logits + (size_t)NB_SPLIT * 64, nb, OUT1, NCLS, bl);
    }
}

// round 12
// speedup vs baseline: 1.0195x; 1.0195x over previous
#include <cuda_runtime.h>
#include <cuda_fp16.h>
#include <math.h>
#include <stdint.h>

#define NN 50000
#define EE 800000
#define IND 256
#define HIDD 64
#define H0 4
#define OUT1 256
#define NCLS 64
#define NEG 0.2f
#define NA_SPLIT 25088   // agg0 / GEMM1 pipeline split (multiple of 128)
#define NB_SPLIT 25088   // agg1 / classifier pipeline split (multiple of 128)

// ---------------- scratch (device globals; no allocation allowed) ----------
__device__ __half g_ft16[NN * 256];    // layer-0 projected features
__device__ __half g_ft16b[NN * 256];   // layer-1 projected features (race-free)
__device__ __half g_h116[NN * 256];    // h1 in fp16 (GEMM1 input + residual)
__device__ float  g_el[NN * H0];
__device__ float  g_er[NN * H0];
__device__ float  g_el1[NN];
__device__ float  g_er1[NN];
__device__ float  g_wel0[8 * 256];
__device__ float  g_wel1[2 * 256];
__device__ int    g_cnt[NN];
__device__ int    g_rowptr[NN + 1];
__device__ int    g_bsum[64];
__device__ int    g_adj[EE];

// =================== CSR build ==============================================
__global__ void hist_kernel(const int* __restrict__ dst, int* __restrict__ cnt) {
    int e = blockIdx.x * blockDim.x + threadIdx.x;
    if (e < EE) atomicAdd(&cnt[dst[e]], 1);
}

__global__ void scan_block_kernel(const int* __restrict__ cnt,
                                  int* __restrict__ rowptr,
                                  int* __restrict__ bsum) {
    __shared__ int sh[1024];
    int t = threadIdx.x;
    int i = blockIdx.x * 1024 + t;
    int v = (i < NN) ? cnt[i] : 0;
    sh[t] = v;
    __syncthreads();
    for (int off = 1; off < 1024; off <<= 1) {
        int add = (t >= off) ? sh[t - off] : 0;
        __syncthreads();
        sh[t] += add;
        __syncthreads();
    }
    if (i < NN) rowptr[i] = sh[t] - v;
    if (t == 1023) bsum[blockIdx.x] = sh[t];
}

__global__ void scan_bsum_kernel(int* __restrict__ bsum, int nb) {
    __shared__ int sh[64];
    int t = threadIdx.x;
    int v = (t < nb) ? bsum[t] : 0;
    sh[t] = v;
    __syncthreads();
    for (int off = 1; off < 64; off <<= 1) {
        int add = (t >= off) ? sh[t - off] : 0;
        __syncthreads();
        sh[t] += add;
        __syncthreads();
    }
    if (t < nb) bsum[t] = sh[t] - v;
}

__global__ void scan_add_kernel(int* __restrict__ rowptr,
                                const int* __restrict__ bsum,
                                int* __restrict__ cursor) {
    int i = blockIdx.x * blockDim.x + threadIdx.x;
    if (i < NN) {
        int r = rowptr[i] + bsum[i >> 10];
        rowptr[i] = r;
        cursor[i] = r;
    }
    if (i == 0) rowptr[NN] = EE;
}

__global__ void csr_fill_kernel(const int* __restrict__ src,
                                const int* __restrict__ dst,
                                int* __restrict__ cursor,
                                int* __restrict__ adj) {
    int e = blockIdx.x * blockDim.x + threadIdx.x;
    if (e >= EE) return;
    int pos = atomicAdd(&cursor[dst[e]], 1);
    adj[pos] = src[e];
}

// =================== attention projection prep ==============================
__global__ void prep_wel_kernel(const float* __restrict__ W0,
                                const float* __restrict__ al0,
                                const float* __restrict__ ar0,
                                const float* __restrict__ W1,
                                const float* __restrict__ al1,
                                const float* __restrict__ ar1,
                                float* __restrict__ wel0,
                                float* __restrict__ wel1) {
    int k = threadIdx.x;
    if (blockIdx.x == 0) {
#pragma unroll
        for (int j = 0; j < 4; j++) {
            float sl = 0.f, sr = 0.f;
            for (int d = 0; d < 64; d++) {
                float wv = W0[k * 256 + j * 64 + d];
                sl += wv * al0[j * 64 + d];
                sr += wv * ar0[j * 64 + d];
            }
            wel0[j * 256 + k] = sl;
            wel0[(4 + j) * 256 + k] = sr;
        }
    } else {
        float sl = 0.f, sr = 0.f;
        for (int d = 0; d < 256; d++) {
            float wv = W1[k * 256 + d];
            sl += wv * al1[d];
            sr += wv * ar1[d];
        }
        wel1[k] = sl;
        wel1[256 + k] = sr;
    }
}

__global__ void __launch_bounds__(256)
eler0_kernel(const float* __restrict__ X, const float* __restrict__ WelT,
             float* __restrict__ el, float* __restrict__ er) {
    __shared__ float w[8][256];
    int tid = threadIdx.x;
    for (int i = tid; i < 8 * 256; i += 256) ((float*)w)[i] = WelT[i];
    __syncthreads();
    int n = blockIdx.x * 8 + (tid >> 5);
    int lane = tid & 31;
    if (n >= NN) return;
    const float* xr = X + (size_t)n * 256;
    float acc[8];
#pragma unroll
    for (int j = 0; j < 8; j++) acc[j] = 0.f;
#pragma unroll
    for (int it = 0; it < 8; it++) {
        float xv = xr[lane + it * 32];
#pragma unroll
        for (int j = 0; j < 8; j++) acc[j] += xv * w[j][lane + it * 32];
    }
#pragma unroll
    for (int o = 16; o; o >>= 1)
#pragma unroll
        for (int j = 0; j < 8; j++) acc[j] += __shfl_xor_sync(0xffffffffu, acc[j], o);
    if (lane == 0) {
#pragma unroll
        for (int j = 0; j < 4; j++) el[n * 4 + j] = acc[j];
#pragma unroll
        for (int j = 0; j < 4; j++) er[n * 4 + j] = acc[4 + j];
    }
}

// =================== GEMM helpers ===========================================
__device__ __forceinline__ uint32_t packbf(float f0, float f1) {
    uint32_t r;
    asm("cvt.rn.bf16x2.f32 %0, %1, %2;" : "=r"(r) : "f"(f1), "f"(f0));
    return r;
}
__device__ __forceinline__ uint32_t packh(float f0, float f1) {
    uint32_t r;
    asm("cvt.rn.f16x2.f32 %0, %1, %2;" : "=r"(r) : "f"(f1), "f"(f0));
    return r;
}
__device__ __forceinline__ void bfsplit2(float f0, float f1,
                                         uint32_t& h, uint32_t& l) {
    h = packbf(f0, f1);
    float h0 = __uint_as_float(h << 16);
    float h1 = __uint_as_float(h & 0xffff0000u);
    l = packbf(f0 - h0, f1 - h1);
}

#define MMA_BF16(d, a, b) \
    asm volatile("mma.sync.aligned.m16n8k16.row.col.f32.bf16.bf16.f32 " \
                 "{%0,%1,%2,%3}, {%4,%5,%6,%7}, {%8,%9}, {%0,%1,%2,%3};" \
                 : "+f"(d[0]), "+f"(d[1]), "+f"(d[2]), "+f"(d[3]) \
                 : "r"(a[0]), "r"(a[1]), "r"(a[2]), "r"(a[3]), \
                   "r"(b[0]), "r"(b[1]))

#define MMA_F16(d, a, b) \
    asm volatile("mma.sync.aligned.m16n8k16.row.col.f32.f16.f16.f32 " \
                 "{%0,%1,%2,%3}, {%4,%5,%6,%7}, {%8,%9}, {%0,%1,%2,%3};" \
                 : "+f"(d[0]), "+f"(d[1]), "+f"(d[2]), "+f"(d[3]) \
                 : "r"(a[0]), "r"(a[1]), "r"(a[2]), "r"(a[3]), \
                   "r"(b[0]), "r"(b[1]))

// ---- fp16 single-term GEMM: C16 = fp16(A @ B). AHALF: A is fp16. ----------
template<int BM, int BN, int WARPS_M, int WARPS_N, bool AHALF>
__global__ void __launch_bounds__(256, 2)
gemm_f16(const void* __restrict__ Av, const float* __restrict__ B,
         __half* __restrict__ C16, int Nr, int K, int M) {
    constexpr int WM = BM / WARPS_M;
    constexpr int WN = BN / WARPS_N;
    constexpr int MF = WM / 16;
    constexpr int NF = WN / 8;
    constexpr int LD = 136;
    constexpr int STG = 8 * LD;
    constexpr int BQ = BN / 4;

    __shared__ uint32_t Ah[2][STG];
    __shared__ uint32_t Bh[2][STG];

    const float*  Af  = (const float*)Av;
    const __half* A16 = (const __half*)Av;

    const int tid  = threadIdx.x;
    const int lane = tid & 31;
    const int warp = tid >> 5;
    const int wm = warp / WARPS_N;
    const int wn = warp % WARPS_N;
    const int rowBase = blockIdx.y * BM;
    const int colBase = blockIdx.x * BN;
    const int g  = lane >> 2;
    const int tg = lane & 3;

    float acc[MF][NF][4];
#pragma unroll
    for (int i = 0; i < MF; i++)
#pragma unroll
        for (int j = 0; j < NF; j++)
#pragma unroll
            for (int k = 0; k < 4; k++) acc[i][j][k] = 0.0f;

    float4 ra[2];
    uint2  ra16[2];
    float4 rb0, rb1;
    const int am[2]  = { (tid) >> 2, (tid + 256) >> 2 };
    const int akq = (tid & 3) << 2;
    const bool bact = tid < 8 * BQ;
    const int bkp = bact ? tid / BQ : 0;
    const int bnq = bact ? (tid % BQ) << 2 : 0;

    auto ldg_tile = [&](int k0) {
#pragma unroll
        for (int i = 0; i < 2; i++) {
            int gr = rowBase + am[i];
            int grc = (gr < Nr) ? gr : (Nr - 1);
            if (AHALF)
                ra16[i] = *(const uint2*)(A16 + (size_t)grc * K + k0 + akq);
            else
                ra[i] = *(const float4*)(Af + (size_t)grc * K + k0 + akq);
        }
        if (bact) {
            rb0 = *(const float4*)(B + (size_t)(k0 + 2 * bkp)     * M + colBase + bnq);
            rb1 = *(const float4*)(B + (size_t)(k0 + 2 * bkp + 1) * M + colBase + bnq);
        }
    };

    auto sts_tile = [&](int s) {
#pragma unroll
        for (int i = 0; i < 2; i++) {
            int kp0 = (akq >> 1);
            if (AHALF) {
                Ah[s][kp0 * LD + am[i]]       = ra16[i].x;
                Ah[s][(kp0 + 1) * LD + am[i]] = ra16[i].y;
            } else {
                Ah[s][kp0 * LD + am[i]]       = packh(ra[i].x, ra[i].y);
                Ah[s][(kp0 + 1) * LD + am[i]] = packh(ra[i].z, ra[i].w);
            }
        }
        if (bact) {
            const float* p0 = &rb0.x;
            const float* p1 = &rb1.x;
            uint32_t hh[4];
#pragma unroll
            for (int j = 0; j < 4; j++) hh[j] = packh(p0[j], p1[j]);
            *(uint4*)&Bh[s][bkp * LD + bnq] = make_uint4(hh[0], hh[1], hh[2], hh[3]);
        }
    };

    const int NIT = K / 16;
    ldg_tile(0);

    for (int it = 0; it < NIT; it++) {
        const int s = it & 1;
        sts_tile(s);
        __syncthreads();
        if (it + 1 < NIT) ldg_tile((it + 1) * 16);

        uint32_t bh[NF][2];
#pragma unroll
        for (int nf = 0; nf < NF; nf++) {
            int c0 = wn * WN + nf * 8 + g;
            bh[nf][0] = Bh[s][tg * LD + c0];
            bh[nf][1] = Bh[s][(tg + 4) * LD + c0];
        }
#pragma unroll
        for (int mf = 0; mf < MF; mf++) {
            int r0 = wm * WM + mf * 16 + g;
            uint32_t ah[4];
            ah[0] = Ah[s][tg * LD + r0];
            ah[1] = Ah[s][tg * LD + r0 + 8];
            ah[2] = Ah[s][(tg + 4) * LD + r0];
            ah[3] = Ah[s][(tg + 4) * LD + r0 + 8];
#pragma unroll
            for (int nf = 0; nf < NF; nf++)
                MMA_F16(acc[mf][nf], ah, bh[nf]);
        }
    }

#pragma unroll
    for (int mf = 0; mf < MF; mf++) {
#pragma unroll
        for (int nf = 0; nf < NF; nf++) {
            int row = rowBase + wm * WM + mf * 16 + g;
            int col = colBase + wn * WN + nf * 8 + tg * 2;
            if (row < Nr)
                *(uint32_t*)(C16 + (size_t)row * M + col) =
                    packh(acc[mf][nf][0], acc[mf][nf][1]);
            if (row + 8 < Nr)
                *(uint32_t*)(C16 + (size_t)(row + 8) * M + col) =
                    packh(acc[mf][nf][2], acc[mf][nf][3]);
        }
    }
}

// ---- bf16 3-term GEMM (classifier only): C[Nr,M] = A@B + bias --------------
template<int BM, int BN, int WARPS_M, int WARPS_N>
__global__ void __launch_bounds__(256, 2)
gemm_bf16x3(const float* __restrict__ A, const float* __restrict__ B,
            float* __restrict__ C, int Nr, int K, int M,
            const float* __restrict__ bias) {
    constexpr int WM = BM / WARPS_M;
    constexpr int WN = BN / WARPS_N;
    constexpr int MF = WM / 16;
    constexpr int NF = WN / 8;
    constexpr int LD = 136;
    constexpr int STG = 8 * LD;
    constexpr int BQ = BN / 4;

    __shared__ uint32_t Ah[2][STG], Al[2][STG];
    __shared__ uint32_t Bh[2][STG], Bl[2][STG];

    const int tid  = threadIdx.x;
    const int lane = tid & 31;
    const int warp = tid >> 5;
    const int wm = warp / WARPS_N;
    const int wn = warp % WARPS_N;
    const int rowBase = blockIdx.y * BM;
    const int colBase = blockIdx.x * BN;
    const int g  = lane >> 2;
    const int tg = lane & 3;

    float acc[MF][NF][4];
#pragma unroll
    for (int i = 0; i < MF; i++)
#pragma unroll
        for (int j = 0; j < NF; j++)
#pragma unroll
            for (int k = 0; k < 4; k++) acc[i][j][k] = 0.0f;

    float4 ra[2];
    float4 rb0, rb1;
    const int am[2]  = { (tid) >> 2, (tid + 256) >> 2 };
    const int akq = (tid & 3) << 2;
    const bool bact = tid < 8 * BQ;
    const int bkp = bact ? tid / BQ : 0;
    const int bnq = bact ? (tid % BQ) << 2 : 0;

    auto ldg_tile = [&](int k0) {
#pragma unroll
        for (int i = 0; i < 2; i++) {
            int gr = rowBase + am[i];
            int grc = (gr < Nr) ? gr : (Nr - 1);
            ra[i] = *(const float4*)(A + (size_t)grc * K + k0 + akq);
        }
        if (bact) {
            rb0 = *(const float4*)(B + (size_t)(k0 + 2 * bkp)     * M + colBase + bnq);
            rb1 = *(const float4*)(B + (size_t)(k0 + 2 * bkp + 1) * M + colBase + bnq);
        }
    };

    auto sts_tile = [&](int s) {
#pragma unroll
        for (int i = 0; i < 2; i++) {
            int kp0 = (akq >> 1);
            uint32_t h, l;
            bfsplit2(ra[i].x, ra[i].y, h, l);
            Ah[s][kp0 * LD + am[i]] = h;
            Al[s][kp0 * LD + am[i]] = l;
            bfsplit2(ra[i].z, ra[i].w, h, l);
            Ah[s][(kp0 + 1) * LD + am[i]] = h;
            Al[s][(kp0 + 1) * LD + am[i]] = l;
        }
        if (bact) {
            const float* p0 = &rb0.x;
            const float* p1 = &rb1.x;
            uint32_t hh[4], ll[4];
#pragma unroll
            for (int j = 0; j < 4; j++) bfsplit2(p0[j], p1[j], hh[j], ll[j]);
            *(uint4*)&Bh[s][bkp * LD + bnq] = make_uint4(hh[0], hh[1], hh[2], hh[3]);
            *(uint4*)&Bl[s][bkp * LD + bnq] = make_uint4(ll[0], ll[1], ll[2], ll[3]);
        }
    };

    const int NIT = K / 16;
    ldg_tile(0);

    for (int it = 0; it < NIT; it++) {
        const int s = it & 1;
        sts_tile(s);
        __syncthreads();
        if (it + 1 < NIT) ldg_tile((it + 1) * 16);

        uint32_t bh[NF][2], bl[NF][2];
#pragma unroll
        for (int nf = 0; nf < NF; nf++) {
            int c0 = wn * WN + nf * 8 + g;
            bh[nf][0] = Bh[s][tg * LD + c0];
            bh[nf][1] = Bh[s][(tg + 4) * LD + c0];
            bl[nf][0] = Bl[s][tg * LD + c0];
            bl[nf][1] = Bl[s][(tg + 4) * LD + c0];
        }
#pragma unroll
        for (int mf = 0; mf < MF; mf++) {
            int r0 = wm * WM + mf * 16 + g;
            uint32_t ah[4], al[4];
            ah[0] = Ah[s][tg * LD + r0];
            ah[1] = Ah[s][tg * LD + r0 + 8];
            ah[2] = Ah[s][(tg + 4) * LD + r0];
            ah[3] = Ah[s][(tg + 4) * LD + r0 + 8];
            al[0] = Al[s][tg * LD + r0];
            al[1] = Al[s][tg * LD + r0 + 8];
            al[2] = Al[s][(tg + 4) * LD + r0];
            al[3] = Al[s][(tg + 4) * LD + r0 + 8];
#pragma unroll
            for (int nf = 0; nf < NF; nf++) {
                MMA_BF16(acc[mf][nf], al, bh[nf]);
                MMA_BF16(acc[mf][nf], ah, bl[nf]);
                MMA_BF16(acc[mf][nf], ah, bh[nf]);
            }
        }
    }

#pragma unroll
    for (int mf = 0; mf < MF; mf++) {
#pragma unroll
        for (int nf = 0; nf < NF; nf++) {
            int row = rowBase + wm * WM + mf * 16 + g;
            int col = colBase + wn * WN + nf * 8 + tg * 2;
            float b0v = bias ? bias[col]     : 0.0f;
            float b1v = bias ? bias[col + 1] : 0.0f;
            if (row < Nr) {
                float2 o = make_float2(acc[mf][nf][0] + b0v, acc[mf][nf][1] + b1v);
                *(float2*)(C + (size_t)row * M + col) = o;
            }
            if (row + 8 < Nr) {
                float2 o = make_float2(acc[mf][nf][2] + b0v, acc[mf][nf][3] + b1v);
                *(float2*)(C + (size_t)(row + 8) * M + col) = o;
            }
        }
    }
}

// =================== aggregation: one WARP per dst node =====================
__device__ __forceinline__ void acc8(float* acc, float a, uint4 r) {
    float2 f0 = __half22float2(*reinterpret_cast<const half2*>(&r.x));
    float2 f1 = __half22float2(*reinterpret_cast<const half2*>(&r.y));
    float2 f2 = __half22float2(*reinterpret_cast<const half2*>(&r.z));
    float2 f3 = __half22float2(*reinterpret_cast<const half2*>(&r.w));
    acc[0] += a * f0.x; acc[1] += a * f0.y;
    acc[2] += a * f1.x; acc[3] += a * f1.y;
    acc[4] += a * f2.x; acc[5] += a * f2.y;
    acc[6] += a * f3.x; acc[7] += a * f3.y;
}

// layer 0: H=4. Prefetch next chunk's adj+el; fp16 h1 output + fused el1/er1.
__global__ void __launch_bounds__(256)
agg0_kernel(const int* __restrict__ rowptr, const int* __restrict__ adj,
            const float* __restrict__ el, const float* __restrict__ er,
            const __half* __restrict__ ft, const float* __restrict__ b0,
            const float* __restrict__ wel1,
            __half* __restrict__ h116,
            float* __restrict__ el1, float* __restrict__ er1,
            int nbase, int nend) {
    const int w = threadIdx.x >> 5;
    const int lane = threadIdx.x & 31;
    const int d = nbase + blockIdx.x * 8 + w;
    if (d >= nend) return;
    const int h = lane >> 3;
    const int start = rowptr[d], end = rowptr[d + 1];

    __shared__ float s_num[8][32][4];

    float4 erd = *(const float4*)(er + (size_t)d * 4);
    float lsum[4] = {0.f, 0.f, 0.f, 0.f};
    float acc[8] = {0.f, 0.f, 0.f, 0.f, 0.f, 0.f, 0.f, 0.f};

    int c = start;
    int n = min(32, end - c);
    int sidx = 0;
    float4 e4 = make_float4(0.f, 0.f, 0.f, 0.f);
    if (c < end && lane < n) {
        sidx = adj[c + lane];
        e4 = *(const float4*)(el + (size_t)sidx * 4);
    }

    while (c < end) {
        if (lane < n) {
            float v[4];
            v[0] = e4.x + erd.x; v[1] = e4.y + erd.y;
            v[2] = e4.z + erd.z; v[3] = e4.w + erd.w;
#pragma unroll
            for (int k = 0; k < 4; k++) {
                float vv = (v[k] >= 0.f) ? v[k] : NEG * v[k];
                float nu = expf(vv);
                s_num[w][lane][k] = nu;
                lsum[k] += nu;
            }
        }
        __syncwarp();

        // prefetch next chunk (overlaps the gather loop below)
        int c2 = c + 32;
        int n2 = min(32, end - c2);
        int sidx2 = 0;
        float4 e42 = make_float4(0.f, 0.f, 0.f, 0.f);
        if (c2 < end && lane < n2) {
            sidx2 = adj[c2 + lane];
            e42 = *(const float4*)(el + (size_t)sidx2 * 4);
        }

        int j = 0;
        for (; j + 4 <= n; j += 4) {
            int s0 = __shfl_sync(0xffffffffu, sidx, j);
            int s1 = __shfl_sync(0xffffffffu, sidx, j + 1);
            int s2 = __shfl_sync(0xffffffffu, sidx, j + 2);
            int s3 = __shfl_sync(0xffffffffu, sidx, j + 3);
            float a0 = s_num[w][j][h],     a1 = s_num[w][j + 1][h];
            float a2 = s_num[w][j + 2][h], a3 = s_num[w][j + 3][h];
            uint4 r0 = *(const uint4*)(ft + (size_t)s0 * 256 + lane * 8);
            uint4 r1 = *(const uint4*)(ft + (size_t)s1 * 256 + lane * 8);
            uint4 r2 = *(const uint4*)(ft + (size_t)s2 * 256 + lane * 8);
            uint4 r3 = *(const uint4*)(ft + (size_t)s3 * 256 + lane * 8);
            acc8(acc, a0, r0); acc8(acc, a1, r1);
            acc8(acc, a2, r2); acc8(acc, a3, r3);
        }
        for (; j < n; j++) {
            int s0 = __shfl_sync(0xffffffffu, sidx, j);
            float a0 = s_num[w][j][h];
            uint4 r0 = *(const uint4*)(ft + (size_t)s0 * 256 + lane * 8);
            acc8(acc, a0, r0);
        }
        __syncwarp();
        sidx = sidx2; e4 = e42; n = n2; c = c2;
    }

#pragma unroll
    for (int off = 16; off; off >>= 1)
#pragma unroll
        for (int k = 0; k < 4; k++)
            lsum[k] += __shfl_xor_sync(0xffffffffu, lsum[k], off);
    float tot = lsum[h];
    float inv = (tot > 0.f) ? (1.0f / tot) : 0.0f;

    float o[8];
    float sl = 0.f, sr = 0.f;
    const float* bb = b0 + lane * 8;
    const float* wl = wel1 + lane * 8;
    const float* wr = wel1 + 256 + lane * 8;
#pragma unroll
    for (int i = 0; i < 8; i++) {
        float v = acc[i] * inv + bb[i];
        v = (v > 0.f) ? v : expm1f(v);
        o[i] = v;
        sl += v * wl[i];
        sr += v * wr[i];
    }
    uint4 hp;
    hp.x = packh(o[0], o[1]); hp.y = packh(o[2], o[3]);
    hp.z = packh(o[4], o[5]); hp.w = packh(o[6], o[7]);
    *(uint4*)(h116 + (size_t)d * 256 + lane * 8) = hp;
#pragma unroll
    for (int off = 16; off; off >>= 1) {
        sl += __shfl_xor_sync(0xffffffffu, sl, off);
        sr += __shfl_xor_sync(0xffffffffu, sr, off);
    }
    if (lane == 0) { el1[d] = sl; er1[d] = sr; }
}

// layer 1: H=1, prefetch, fp16 residual.
__global__ void __launch_bounds__(256)
agg1_kernel(const int* __restrict__ rowptr, const int* __restrict__ adj,
            const float* __restrict__ el, const float* __restrict__ er,
            const __half* __restrict__ ft, const __half* __restrict__ h116,
            const float* __restrict__ b1, float* __restrict__ hout,
            int nbase, int nend) {
    const int w = threadIdx.x >> 5;
    const int lane = threadIdx.x & 31;
    const int d = nbase + blockIdx.x * 8 + w;
    if (d >= nend) return;
    const int start = rowptr[d], end = rowptr[d + 1];

    float erd = er[d];
    float lsum = 0.f;
    float acc[8] = {0.f, 0.f, 0.f, 0.f, 0.f, 0.f, 0.f, 0.f};

    int c = start;
    int n = min(32, end - c);
    int sidx = 0;
    float elv = 0.f;
    if (c < end && lane < n) {
        sidx = adj[c + lane];
        elv = el[sidx];
    }

    while (c < end) {
        float nu = 0.f;
        if (lane < n) {
            float v = elv + erd;
            v = (v >= 0.f) ? v : NEG * v;
            nu = expf(v);
            lsum += nu;
        }

        int c2 = c + 32;
        int n2 = min(32, end - c2);
        int sidx2 = 0;
        float elv2 = 0.f;
        if (c2 < end && lane < n2) {
            sidx2 = adj[c2 + lane];
            elv2 = el[sidx2];
        }

        int j = 0;
        for (; j + 4 <= n; j += 4) {
            int s0 = __shfl_sync(0xffffffffu, sidx, j);
            int s1 = __shfl_sync(0xffffffffu, sidx, j + 1);
            int s2 = __shfl_sync(0xffffffffu, sidx, j + 2);
            int s3 = __shfl_sync(0xffffffffu, sidx, j + 3);
            float a0 = __shfl_sync(0xffffffffu, nu, j);
            float a1 = __shfl_sync(0xffffffffu, nu, j + 1);
            float a2 = __shfl_sync(0xffffffffu, nu, j + 2);
            float a3 = __shfl_sync(0xffffffffu, nu, j + 3);
            uint4 r0 = *(const uint4*)(ft + (size_t)s0 * 256 + lane * 8);
            uint4 r1 = *(const uint4*)(ft + (size_t)s1 * 256 + lane * 8);
            uint4 r2 = *(const uint4*)(ft + (size_t)s2 * 256 + lane * 8);
            uint4 r3 = *(const uint4*)(ft + (size_t)s3 * 256 + lane * 8);
            acc8(acc, a0, r0); acc8(acc, a1, r1);
            acc8(acc, a2, r2); acc8(acc, a3, r3);
        }
        for (; j < n; j++) {
            int s0 = __shfl_sync(0xffffffffu, sidx, j);
            float a0 = __shfl_sync(0xffffffffu, nu, j);
            uint4 r0 = *(const uint4*)(ft + (size_t)s0 * 256 + lane * 8);
            acc8(acc, a0, r0);
        }
        sidx = sidx2; elv = elv2; n = n2; c = c2;
    }

#pragma unroll
    for (int off = 16; off; off >>= 1)
        lsum += __shfl_xor_sync(0xffffffffu, lsum, off);
    float inv = (lsum > 0.f) ? (1.0f / lsum) : 0.0f;

    uint4 hr = *(const uint4*)(h116 + (size_t)d * 256 + lane * 8);
    float2 h0 = __half22float2(*reinterpret_cast<const half2*>(&hr.x));
    float2 h1p = __half22float2(*reinterpret_cast<const half2*>(&hr.y));
    float2 h2 = __half22float2(*reinterpret_cast<const half2*>(&hr.z));
    float2 h3 = __half22float2(*reinterpret_cast<const half2*>(&hr.w));
    float4 bb0 = *(const float4*)(b1 + lane * 8);
    float4 bb1 = *(const float4*)(b1 + lane * 8 + 4);
    float4 o0, o1;
    o0.x = acc[0] * inv + h0.x  + bb0.x;
    o0.y = acc[1] * inv + h0.y  + bb0.y;
    o0.z = acc[2] * inv + h1p.x + bb0.z;
    o0.w = acc[3] * inv + h1p.y + bb0.w;
    o1.x = acc[4] * inv + h2.x  + bb1.x;
    o1.y = acc[5] * inv + h2.y  + bb1.y;
    o1.z = acc[6] * inv + h3.x  + bb1.z;
    o1.w = acc[7] * inv + h3.y  + bb1.w;
    *(float4*)(hout + (size_t)d * 256 + lane * 8)     = o0;
    *(float4*)(hout + (size_t)d * 256 + lane * 8 + 4) = o1;
}

// =================== launch ==================================================
extern "C" void kernel_launch(void* const* d_in, const int* in_sizes, int n_in,
                              void* d_out, int out_size) {
    const float* x   = (const float*)d_in[0];
    const int*   src = (const int*)  d_in[1];
    const int*   dst = (const int*)  d_in[2];
    const float* W0  = (const float*)d_in[3];
    const float* al0 = (const float*)d_in[4];
    const float* ar0 = (const float*)d_in[5];
    const float* b0  = (const float*)d_in[6];
    const float* W1  = (const float*)d_in[7];
    const float* al1 = (const float*)d_in[8];
    const float* ar1 = (const float*)d_in[9];
    const float* b1  = (const float*)d_in[10];
    const float* Wl  = (const float*)d_in[11];
    const float* bl  = (const float*)d_in[12];

    float* out    = (float*)d_out;
    float* logits = out;
    float* hout   = out + (size_t)NN * NCLS;

    __half *ft16, *ft16b, *h116;
    float *el, *er, *el1, *er1, *wel0, *wel1;
    int *cnt, *rowptr, *bsum, *adj;
    cudaGetSymbolAddress((void**)&ft16,   g_ft16);
    cudaGetSymbolAddress((void**)&ft16b,  g_ft16b);
    cudaGetSymbolAddress((void**)&h116,   g_h116);
    cudaGetSymbolAddress((void**)&el,     g_el);
    cudaGetSymbolAddress((void**)&er,     g_er);
    cudaGetSymbolAddress((void**)&el1,    g_el1);
    cudaGetSymbolAddress((void**)&er1,    g_er1);
    cudaGetSymbolAddress((void**)&wel0,   g_wel0);
    cudaGetSymbolAddress((void**)&wel1,   g_wel1);
    cudaGetSymbolAddress((void**)&cnt,    g_cnt);
    cudaGetSymbolAddress((void**)&rowptr, g_rowptr);
    cudaGetSymbolAddress((void**)&bsum,   g_bsum);
    cudaGetSymbolAddress((void**)&adj,    g_adj);

    static cudaStream_t s1 = nullptr, s2 = nullptr;
    static cudaEvent_t ev_fork = nullptr, ev_csr = nullptr, ev_el0 = nullptr,
                       ev_g0 = nullptr, ev_a0b = nullptr, ev_g1 = nullptr,
                       ev_a1b = nullptr;
    if (s1 == nullptr) {
        cudaStreamCreateWithFlags(&s1, cudaStreamNonBlocking);
        cudaStreamCreateWithFlags(&s2, cudaStreamNonBlocking);
        cudaEventCreateWithFlags(&ev_fork, cudaEventDisableTiming);
        cudaEventCreateWithFlags(&ev_csr,  cudaEventDisableTiming);
        cudaEventCreateWithFlags(&ev_el0,  cudaEventDisableTiming);
        cudaEventCreateWithFlags(&ev_g0,   cudaEventDisableTiming);
        cudaEventCreateWithFlags(&ev_a0b,  cudaEventDisableTiming);
        cudaEventCreateWithFlags(&ev_g1,   cudaEventDisableTiming);
        cudaEventCreateWithFlags(&ev_a1b,  cudaEventDisableTiming);
    }

    const int T = 256;
    const int NB_SCAN = (NN + 1023) / 1024;

    cudaEventRecord(ev_fork, 0);

    // ---- s1: CSR build ----
    cudaStreamWaitEvent(s1, ev_fork, 0);
    cudaMemsetAsync(cnt, 0, NN * sizeof(int), s1);
    hist_kernel<<<(EE + T - 1) / T, T, 0, s1>>>(dst, cnt);
    scan_block_kernel<<<NB_SCAN, 1024, 0, s1>>>(cnt, rowptr, bsum);
    scan_bsum_kernel<<<1, 64, 0, s1>>>(bsum, NB_SCAN);
    scan_add_kernel<<<(NN + T - 1) / T, T, 0, s1>>>(rowptr, bsum, cnt);
    csr_fill_kernel<<<(EE + T - 1) / T, T, 0, s1>>>(src, dst, cnt, adj);
    cudaEventRecord(ev_csr, s1);

    // ---- s2: attention projections ----
    cudaStreamWaitEvent(s2, ev_fork, 0);
    prep_wel_kernel<<<2, 256, 0, s2>>>(W0, al0, ar0, W1, al1, ar1, wel0, wel1);
    eler0_kernel<<<(NN + 7) / 8, 256, 0, s2>>>(x, wel0, el, er);
    cudaEventRecord(ev_el0, s2);

    // ---- main: layer 0 projection ----
    {
        dim3 grid(256 / 128, (NN + 127) / 128);
        gemm_f16<128, 128, 2, 4, false><<<grid, 256>>>(x, W0, ft16, NN, IND, 256);
    }
    cudaEventRecord(ev_g0, 0);

    // ---- agg0 chunk B on s2 ----
    cudaStreamWaitEvent(s2, ev_g0, 0);
    cudaStreamWaitEvent(s2, ev_csr, 0);
    {
        int nb = NN - NA_SPLIT;
        agg0_kernel<<<(nb + 7) / 8, 256, 0, s2>>>(rowptr, adj, el, er, ft16, b0,
                                                  wel1, h116, el1, er1, NA_SPLIT, NN);
    }
    cudaEventRecord(ev_a0b, s2);

    // ---- main: agg0 chunk A, then GEMM1_A (writes ft16b — race-free) ----
    cudaStreamWaitEvent(0, ev_csr, 0);
    cudaStreamWaitEvent(0, ev_el0, 0);
    agg0_kernel<<<NA_SPLIT / 8, 256>>>(rowptr, adj, el, er, ft16, b0,
                                       wel1, h116, el1, er1, 0, NA_SPLIT);
    {
        dim3 grid(256 / 128, NA_SPLIT / 128);
        gemm_f16<128, 128, 2, 4, true><<<grid, 256>>>(h116, W1, ft16b, NA_SPLIT, 256, 256);
    }

    // ---- main: GEMM1_B after agg0_B ----
    cudaStreamWaitEvent(0, ev_a0b, 0);
    {
        int nb = NN - NA_SPLIT;
        dim3 grid(256 / 128, (nb + 127) / 128);
        gemm_f16<128, 128, 2, 4, true><<<grid, 256>>>(
            h116 + (size_t)NA_SPLIT * 256, W1,
            ft16b + (size_t)NA_SPLIT * 256, nb, 256, 256);
    }
    cudaEventRecord(ev_g1, 0);

    // ---- agg1 chunk B on s2 ----
    cudaStreamWaitEvent(s2, ev_g1, 0);
    {
        int nb = NN - NB_SPLIT;
        agg1_kernel<<<(nb + 7) / 8, 256, 0, s2>>>(rowptr, adj, el1, er1, ft16b,
                                                  h116, b1, hout, NB_SPLIT, NN);
    }
    cudaEventRecord(ev_a1b, s2);

    // ---- main: agg1 chunk A, then cls_A ----
    agg1_kernel<<<NB_SPLIT / 8, 256>>>(rowptr, adj, el1, er1, ft16b,
                                       h116, b1, hout, 0, NB_SPLIT);
    {
        dim3 grid(1, NB_SPLIT / 128);
        gemm_bf16x3<128, 64, 4, 2><<<grid, 256>>>(hout, Wl, logits, NB_SPLIT, OUT1, NCLS, bl);
    }

    // ---- main: cls_B after agg1_B ----
    cudaStreamWaitEvent(0, ev_a1b, 0);
    {
        int nb = NN - NB_SPLIT;
        dim3 grid(1, (nb + 127) / 128);
        gemm_bf16x3<128, 64, 4, 2><<<grid, 256>>>(
            hout + (size_t)NB_SPLIT * 256, Wl,
            logits + (size_t)NB_SPLIT * 64, nb, OUT1, NCLS, bl);
    }
}

// round 13
// speedup vs baseline: 1.0246x; 1.0050x over previous
#include <cuda_runtime.h>
#include <cuda_fp16.h>
#include <math.h>
#include <stdint.h>

#define NN 50000
#define EE 800000
#define IND 256
#define HIDD 64
#define H0 4
#define OUT1 256
#define NCLS 64
#define NEG 0.2f
#define NCHUNK 12544   // pipeline chunk (98*128)

// ---------------- scratch (device globals; no allocation allowed) ----------
__device__ __half g_ft16[NN * 256];    // layer-0 projected features
__device__ __half g_ft16b[NN * 256];   // layer-1 projected features
__device__ __half g_h116[NN * 256];    // h1 in fp16
__device__ float  g_el[NN * H0];
__device__ float  g_er[NN * H0];
__device__ float  g_el1[NN];
__device__ float  g_er1[NN];
__device__ float  g_wel0[8 * 256];
__device__ float  g_wel1[2 * 256];
__device__ int    g_cnt[NN];
__device__ int    g_rowptr[NN + 1];
__device__ int    g_adj[EE];

// =================== CSR build ==============================================
__global__ void hist_kernel(const int* __restrict__ dst, int* __restrict__ cnt) {
    int e = blockIdx.x * blockDim.x + threadIdx.x;
    if (e < EE) atomicAdd(&cnt[dst[e]], 1);
}

// single-block fused exclusive scan over NN counters -> rowptr + cursor
__global__ void __launch_bounds__(1024)
scan_fused_kernel(const int* __restrict__ cnt,
                  int* __restrict__ rowptr, int* __restrict__ cursor) {
    __shared__ int s_warp[32];
    __shared__ int s_off;
    const int t = threadIdx.x;
    const int lane = t & 31;
    const int wid = t >> 5;
    if (t == 0) s_off = 0;
    __syncthreads();

    for (int base = 0; base < NN; base += 1024) {
        int i = base + t;
        int v = (i < NN) ? cnt[i] : 0;
        // inclusive warp scan
        int ws = v;
#pragma unroll
        for (int o = 1; o < 32; o <<= 1) {
            int u = __shfl_up_sync(0xffffffffu, ws, o);
            if (lane >= o) ws += u;
        }
        if (lane == 31) s_warp[wid] = ws;
        __syncthreads();
        if (wid == 0) {
            int wv = s_warp[lane];
            int wscan = wv;
#pragma unroll
            for (int o = 1; o < 32; o <<= 1) {
                int u = __shfl_up_sync(0xffffffffu, wscan, o);
                if (lane >= o) wscan += u;
            }
            s_warp[lane] = wscan;
        }
        __syncthreads();
        int ex = ws - v + (wid > 0 ? s_warp[wid - 1] : 0) + s_off;
        if (i < NN) { rowptr[i] = ex; cursor[i] = ex; }
        __syncthreads();                 // everyone read s_off / s_warp
        if (t == 0) s_off += s_warp[31];
        __syncthreads();
    }
    if (t == 0) rowptr[NN] = EE;
}

__global__ void csr_fill_kernel(const int* __restrict__ src,
                                const int* __restrict__ dst,
                                int* __restrict__ cursor,
                                int* __restrict__ adj) {
    int e = blockIdx.x * blockDim.x + threadIdx.x;
    if (e >= EE) return;
    int pos = atomicAdd(&cursor[dst[e]], 1);
    adj[pos] = src[e];
}

// =================== attention projection prep ==============================
__global__ void prep_wel_kernel(const float* __restrict__ W0,
                                const float* __restrict__ al0,
                                const float* __restrict__ ar0,
                                const float* __restrict__ W1,
                                const float* __restrict__ al1,
                                const float* __restrict__ ar1,
                                float* __restrict__ wel0,
                                float* __restrict__ wel1) {
    int k = threadIdx.x;
    if (blockIdx.x == 0) {
#pragma unroll
        for (int j = 0; j < 4; j++) {
            float sl = 0.f, sr = 0.f;
            for (int d = 0; d < 64; d++) {
                float wv = W0[k * 256 + j * 64 + d];
                sl += wv * al0[j * 64 + d];
                sr += wv * ar0[j * 64 + d];
            }
            wel0[j * 256 + k] = sl;
            wel0[(4 + j) * 256 + k] = sr;
        }
    } else {
        float sl = 0.f, sr = 0.f;
        for (int d = 0; d < 256; d++) {
            float wv = W1[k * 256 + d];
            sl += wv * al1[d];
            sr += wv * ar1[d];
        }
        wel1[k] = sl;
        wel1[256 + k] = sr;
    }
}

__global__ void __launch_bounds__(256)
eler0_kernel(const float* __restrict__ X, const float* __restrict__ WelT,
             float* __restrict__ el, float* __restrict__ er) {
    __shared__ float w[8][256];
    int tid = threadIdx.x;
    for (int i = tid; i < 8 * 256; i += 256) ((float*)w)[i] = WelT[i];
    __syncthreads();
    int n = blockIdx.x * 8 + (tid >> 5);
    int lane = tid & 31;
    if (n >= NN) return;
    const float* xr = X + (size_t)n * 256;
    float acc[8];
#pragma unroll
    for (int j = 0; j < 8; j++) acc[j] = 0.f;
#pragma unroll
    for (int it = 0; it < 8; it++) {
        float xv = xr[lane + it * 32];
#pragma unroll
        for (int j = 0; j < 8; j++) acc[j] += xv * w[j][lane + it * 32];
    }
#pragma unroll
    for (int o = 16; o; o >>= 1)
#pragma unroll
        for (int j = 0; j < 8; j++) acc[j] += __shfl_xor_sync(0xffffffffu, acc[j], o);
    if (lane == 0) {
#pragma unroll
        for (int j = 0; j < 4; j++) el[n * 4 + j] = acc[j];
#pragma unroll
        for (int j = 0; j < 4; j++) er[n * 4 + j] = acc[4 + j];
    }
}

// =================== GEMM helpers ===========================================
__device__ __forceinline__ uint32_t packbf(float f0, float f1) {
    uint32_t r;
    asm("cvt.rn.bf16x2.f32 %0, %1, %2;" : "=r"(r) : "f"(f1), "f"(f0));
    return r;
}
__device__ __forceinline__ uint32_t packh(float f0, float f1) {
    uint32_t r;
    asm("cvt.rn.f16x2.f32 %0, %1, %2;" : "=r"(r) : "f"(f1), "f"(f0));
    return r;
}
__device__ __forceinline__ void bfsplit2(float f0, float f1,
                                         uint32_t& h, uint32_t& l) {
    h = packbf(f0, f1);
    float h0 = __uint_as_float(h << 16);
    float h1 = __uint_as_float(h & 0xffff0000u);
    l = packbf(f0 - h0, f1 - h1);
}

#define MMA_BF16(d, a, b) \
    asm volatile("mma.sync.aligned.m16n8k16.row.col.f32.bf16.bf16.f32 " \
                 "{%0,%1,%2,%3}, {%4,%5,%6,%7}, {%8,%9}, {%0,%1,%2,%3};" \
                 : "+f"(d[0]), "+f"(d[1]), "+f"(d[2]), "+f"(d[3]) \
                 : "r"(a[0]), "r"(a[1]), "r"(a[2]), "r"(a[3]), \
                   "r"(b[0]), "r"(b[1]))

#define MMA_F16(d, a, b) \
    asm volatile("mma.sync.aligned.m16n8k16.row.col.f32.f16.f16.f32 " \
                 "{%0,%1,%2,%3}, {%4,%5,%6,%7}, {%8,%9}, {%0,%1,%2,%3};" \
                 : "+f"(d[0]), "+f"(d[1]), "+f"(d[2]), "+f"(d[3]) \
                 : "r"(a[0]), "r"(a[1]), "r"(a[2]), "r"(a[3]), \
                   "r"(b[0]), "r"(b[1]))

// ---- fp16 single-term GEMM: C16 = fp16(A @ B). AHALF: A is fp16. ----------
template<int BM, int BN, int WARPS_M, int WARPS_N, bool AHALF>
__global__ void __launch_bounds__(256, 2)
gemm_f16(const void* __restrict__ Av, const float* __restrict__ B,
         __half* __restrict__ C16, int Nr, int K, int M) {
    constexpr int WM = BM / WARPS_M;
    constexpr int WN = BN / WARPS_N;
    constexpr int MF = WM / 16;
    constexpr int NF = WN / 8;
    constexpr int LD = 136;
    constexpr int STG = 8 * LD;
    constexpr int BQ = BN / 4;

    __shared__ uint32_t Ah[2][STG];
    __shared__ uint32_t Bh[2][STG];

    const float*  Af  = (const float*)Av;
    const __half* A16 = (const __half*)Av;

    const int tid  = threadIdx.x;
    const int lane = tid & 31;
    const int warp = tid >> 5;
    const int wm = warp / WARPS_N;
    const int wn = warp % WARPS_N;
    const int rowBase = blockIdx.y * BM;
    const int colBase = blockIdx.x * BN;
    const int g  = lane >> 2;
    const int tg = lane & 3;

    float acc[MF][NF][4];
#pragma unroll
    for (int i = 0; i < MF; i++)
#pragma unroll
        for (int j = 0; j < NF; j++)
#pragma unroll
            for (int k = 0; k < 4; k++) acc[i][j][k] = 0.0f;

    float4 ra[2];
    uint2  ra16[2];
    float4 rb0, rb1;
    const int am[2]  = { (tid) >> 2, (tid + 256) >> 2 };
    const int akq = (tid & 3) << 2;
    const bool bact = tid < 8 * BQ;
    const int bkp = bact ? tid / BQ : 0;
    const int bnq = bact ? (tid % BQ) << 2 : 0;

    auto ldg_tile = [&](int k0) {
#pragma unroll
        for (int i = 0; i < 2; i++) {
            int gr = rowBase + am[i];
            int grc = (gr < Nr) ? gr : (Nr - 1);
            if (AHALF)
                ra16[i] = *(const uint2*)(A16 + (size_t)grc * K + k0 + akq);
            else
                ra[i] = *(const float4*)(Af + (size_t)grc * K + k0 + akq);
        }
        if (bact) {
            rb0 = *(const float4*)(B + (size_t)(k0 + 2 * bkp)     * M + colBase + bnq);
            rb1 = *(const float4*)(B + (size_t)(k0 + 2 * bkp + 1) * M + colBase + bnq);
        }
    };

    auto sts_tile = [&](int s) {
#pragma unroll
        for (int i = 0; i < 2; i++) {
            int kp0 = (akq >> 1);
            if (AHALF) {
                Ah[s][kp0 * LD + am[i]]       = ra16[i].x;
                Ah[s][(kp0 + 1) * LD + am[i]] = ra16[i].y;
            } else {
                Ah[s][kp0 * LD + am[i]]       = packh(ra[i].x, ra[i].y);
                Ah[s][(kp0 + 1) * LD + am[i]] = packh(ra[i].z, ra[i].w);
            }
        }
        if (bact) {
            const float* p0 = &rb0.x;
            const float* p1 = &rb1.x;
            uint32_t hh[4];
#pragma unroll
            for (int j = 0; j < 4; j++) hh[j] = packh(p0[j], p1[j]);
            *(uint4*)&Bh[s][bkp * LD + bnq] = make_uint4(hh[0], hh[1], hh[2], hh[3]);
        }
    };

    const int NIT = K / 16;
    ldg_tile(0);

    for (int it = 0; it < NIT; it++) {
        const int s = it & 1;
        sts_tile(s);
        __syncthreads();
        if (it + 1 < NIT) ldg_tile((it + 1) * 16);

        uint32_t bh[NF][2];
#pragma unroll
        for (int nf = 0; nf < NF; nf++) {
            int c0 = wn * WN + nf * 8 + g;
            bh[nf][0] = Bh[s][tg * LD + c0];
            bh[nf][1] = Bh[s][(tg + 4) * LD + c0];
        }
#pragma unroll
        for (int mf = 0; mf < MF; mf++) {
            int r0 = wm * WM + mf * 16 + g;
            uint32_t ah[4];
            ah[0] = Ah[s][tg * LD + r0];
            ah[1] = Ah[s][tg * LD + r0 + 8];
            ah[2] = Ah[s][(tg + 4) * LD + r0];
            ah[3] = Ah[s][(tg + 4) * LD + r0 + 8];
#pragma unroll
            for (int nf = 0; nf < NF; nf++)
                MMA_F16(acc[mf][nf], ah, bh[nf]);
        }
    }

#pragma unroll
    for (int mf = 0; mf < MF; mf++) {
#pragma unroll
        for (int nf = 0; nf < NF; nf++) {
            int row = rowBase + wm * WM + mf * 16 + g;
            int col = colBase + wn * WN + nf * 8 + tg * 2;
            if (row < Nr)
                *(uint32_t*)(C16 + (size_t)row * M + col) =
                    packh(acc[mf][nf][0], acc[mf][nf][1]);
            if (row + 8 < Nr)
                *(uint32_t*)(C16 + (size_t)(row + 8) * M + col) =
                    packh(acc[mf][nf][2], acc[mf][nf][3]);
        }
    }
}

// ---- bf16 3-term GEMM (classifier): C[Nr,M] = A@B + bias -------------------
template<int BM, int BN, int WARPS_M, int WARPS_N>
__global__ void __launch_bounds__(256, 2)
gemm_bf16x3(const float* __restrict__ A, const float* __restrict__ B,
            float* __restrict__ C, int Nr, int K, int M,
            const float* __restrict__ bias) {
    constexpr int WM = BM / WARPS_M;
    constexpr int WN = BN / WARPS_N;
    constexpr int MF = WM / 16;
    constexpr int NF = WN / 8;
    constexpr int LD = 136;
    constexpr int STG = 8 * LD;
    constexpr int BQ = BN / 4;

    __shared__ uint32_t Ah[2][STG], Al[2][STG];
    __shared__ uint32_t Bh[2][STG], Bl[2][STG];

    const int tid  = threadIdx.x;
    const int lane = tid & 31;
    const int warp = tid >> 5;
    const int wm = warp / WARPS_N;
    const int wn = warp % WARPS_N;
    const int rowBase = blockIdx.y * BM;
    const int colBase = blockIdx.x * BN;
    const int g  = lane >> 2;
    const int tg = lane & 3;

    float acc[MF][NF][4];
#pragma unroll
    for (int i = 0; i < MF; i++)
#pragma unroll
        for (int j = 0; j < NF; j++)
#pragma unroll
            for (int k = 0; k < 4; k++) acc[i][j][k] = 0.0f;

    float4 ra[2];
    float4 rb0, rb1;
    const int am[2]  = { (tid) >> 2, (tid + 256) >> 2 };
    const int akq = (tid & 3) << 2;
    const bool bact = tid < 8 * BQ;
    const int bkp = bact ? tid / BQ : 0;
    const int bnq = bact ? (tid % BQ) << 2 : 0;

    auto ldg_tile = [&](int k0) {
#pragma unroll
        for (int i = 0; i < 2; i++) {
            int gr = rowBase + am[i];
            int grc = (gr < Nr) ? gr : (Nr - 1);
            ra[i] = *(const float4*)(A + (size_t)grc * K + k0 + akq);
        }
        if (bact) {
            rb0 = *(const float4*)(B + (size_t)(k0 + 2 * bkp)     * M + colBase + bnq);
            rb1 = *(const float4*)(B + (size_t)(k0 + 2 * bkp + 1) * M + colBase + bnq);
        }
    };

    auto sts_tile = [&](int s) {
#pragma unroll
        for (int i = 0; i < 2; i++) {
            int kp0 = (akq >> 1);
            uint32_t h, l;
            bfsplit2(ra[i].x, ra[i].y, h, l);
            Ah[s][kp0 * LD + am[i]] = h;
            Al[s][kp0 * LD + am[i]] = l;
            bfsplit2(ra[i].z, ra[i].w, h, l);
            Ah[s][(kp0 + 1) * LD + am[i]] = h;
            Al[s][(kp0 + 1) * LD + am[i]] = l;
        }
        if (bact) {
            const float* p0 = &rb0.x;
            const float* p1 = &rb1.x;
            uint32_t hh[4], ll[4];
#pragma unroll
            for (int j = 0; j < 4; j++) bfsplit2(p0[j], p1[j], hh[j], ll[j]);
            *(uint4*)&Bh[s][bkp * LD + bnq] = make_uint4(hh[0], hh[1], hh[2], hh[3]);
            *(uint4*)&Bl[s][bkp * LD + bnq] = make_uint4(ll[0], ll[1], ll[2], ll[3]);
        }
    };

    const int NIT = K / 16;
    ldg_tile(0);

    for (int it = 0; it < NIT; it++) {
        const int s = it & 1;
        sts_tile(s);
        __syncthreads();
        if (it + 1 < NIT) ldg_tile((it + 1) * 16);

        uint32_t bh[NF][2], bl[NF][2];
#pragma unroll
        for (int nf = 0; nf < NF; nf++) {
            int c0 = wn * WN + nf * 8 + g;
            bh[nf][0] = Bh[s][tg * LD + c0];
            bh[nf][1] = Bh[s][(tg + 4) * LD + c0];
            bl[nf][0] = Bl[s][tg * LD + c0];
            bl[nf][1] = Bl[s][(tg + 4) * LD + c0];
        }
#pragma unroll
        for (int mf = 0; mf < MF; mf++) {
            int r0 = wm * WM + mf * 16 + g;
            uint32_t ah[4], al[4];
            ah[0] = Ah[s][tg * LD + r0];
            ah[1] = Ah[s][tg * LD + r0 + 8];
            ah[2] = Ah[s][(tg + 4) * LD + r0];
            ah[3] = Ah[s][(tg + 4) * LD + r0 + 8];
            al[0] = Al[s][tg * LD + r0];
            al[1] = Al[s][tg * LD + r0 + 8];
            al[2] = Al[s][(tg + 4) * LD + r0];
            al[3] = Al[s][(tg + 4) * LD + r0 + 8];
#pragma unroll
            for (int nf = 0; nf < NF; nf++) {
                MMA_BF16(acc[mf][nf], al, bh[nf]);
                MMA_BF16(acc[mf][nf], ah, bl[nf]);
                MMA_BF16(acc[mf][nf], ah, bh[nf]);
            }
        }
    }

#pragma unroll
    for (int mf = 0; mf < MF; mf++) {
#pragma unroll
        for (int nf = 0; nf < NF; nf++) {
            int row = rowBase + wm * WM + mf * 16 + g;
            int col = colBase + wn * WN + nf * 8 + tg * 2;
            float b0v = bias ? bias[col]     : 0.0f;
            float b1v = bias ? bias[col + 1] : 0.0f;
            if (row < Nr) {
                float2 o = make_float2(acc[mf][nf][0] + b0v, acc[mf][nf][1] + b1v);
                *(float2*)(C + (size_t)row * M + col) = o;
            }
            if (row + 8 < Nr) {
                float2 o = make_float2(acc[mf][nf][2] + b0v, acc[mf][nf][3] + b1v);
                *(float2*)(C + (size_t)(row + 8) * M + col) = o;
            }
        }
    }
}

// =================== aggregation: one WARP per dst node =====================
__device__ __forceinline__ void acc8(float* acc, float a, uint4 r) {
    float2 f0 = __half22float2(*reinterpret_cast<const half2*>(&r.x));
    float2 f1 = __half22float2(*reinterpret_cast<const half2*>(&r.y));
    float2 f2 = __half22float2(*reinterpret_cast<const half2*>(&r.z));
    float2 f3 = __half22float2(*reinterpret_cast<const half2*>(&r.w));
    acc[0] += a * f0.x; acc[1] += a * f0.y;
    acc[2] += a * f1.x; acc[3] += a * f1.y;
    acc[4] += a * f2.x; acc[5] += a * f2.y;
    acc[6] += a * f3.x; acc[7] += a * f3.y;
}

__global__ void __launch_bounds__(256)
agg0_kernel(const int* __restrict__ rowptr, const int* __restrict__ adj,
            const float* __restrict__ el, const float* __restrict__ er,
            const __half* __restrict__ ft, const float* __restrict__ b0,
            const float* __restrict__ wel1,
            __half* __restrict__ h116,
            float* __restrict__ el1, float* __restrict__ er1,
            int nbase, int nend) {
    const int w = threadIdx.x >> 5;
    const int lane = threadIdx.x & 31;
    const int d = nbase + blockIdx.x * 8 + w;
    if (d >= nend) return;
    const int h = lane >> 3;
    const int start = rowptr[d], end = rowptr[d + 1];

    __shared__ float s_num[8][32][4];

    float4 erd = *(const float4*)(er + (size_t)d * 4);
    float lsum[4] = {0.f, 0.f, 0.f, 0.f};
    float acc[8] = {0.f, 0.f, 0.f, 0.f, 0.f, 0.f, 0.f, 0.f};

    int c = start;
    int n = min(32, end - c);
    int sidx = 0;
    float4 e4 = make_float4(0.f, 0.f, 0.f, 0.f);
    if (c < end && lane < n) {
        sidx = adj[c + lane];
        e4 = *(const float4*)(el + (size_t)sidx * 4);
    }

    while (c < end) {
        if (lane < n) {
            float v[4];
            v[0] = e4.x + erd.x; v[1] = e4.y + erd.y;
            v[2] = e4.z + erd.z; v[3] = e4.w + erd.w;
#pragma unroll
            for (int k = 0; k < 4; k++) {
                float vv = (v[k] >= 0.f) ? v[k] : NEG * v[k];
                float nu = expf(vv);
                s_num[w][lane][k] = nu;
                lsum[k] += nu;
            }
        }
        __syncwarp();

        int c2 = c + 32;
        int n2 = min(32, end - c2);
        int sidx2 = 0;
        float4 e42 = make_float4(0.f, 0.f, 0.f, 0.f);
        if (c2 < end && lane < n2) {
            sidx2 = adj[c2 + lane];
            e42 = *(const float4*)(el + (size_t)sidx2 * 4);
        }

        int j = 0;
        for (; j + 4 <= n; j += 4) {
            int s0 = __shfl_sync(0xffffffffu, sidx, j);
            int s1 = __shfl_sync(0xffffffffu, sidx, j + 1);
            int s2 = __shfl_sync(0xffffffffu, sidx, j + 2);
            int s3 = __shfl_sync(0xffffffffu, sidx, j + 3);
            float a0 = s_num[w][j][h],     a1 = s_num[w][j + 1][h];
            float a2 = s_num[w][j + 2][h], a3 = s_num[w][j + 3][h];
            uint4 r0 = *(const uint4*)(ft + (size_t)s0 * 256 + lane * 8);
            uint4 r1 = *(const uint4*)(ft + (size_t)s1 * 256 + lane * 8);
            uint4 r2 = *(const uint4*)(ft + (size_t)s2 * 256 + lane * 8);
            uint4 r3 = *(const uint4*)(ft + (size_t)s3 * 256 + lane * 8);
            acc8(acc, a0, r0); acc8(acc, a1, r1);
            acc8(acc, a2, r2); acc8(acc, a3, r3);
        }
        for (; j < n; j++) {
            int s0 = __shfl_sync(0xffffffffu, sidx, j);
            float a0 = s_num[w][j][h];
            uint4 r0 = *(const uint4*)(ft + (size_t)s0 * 256 + lane * 8);
            acc8(acc, a0, r0);
        }
        __syncwarp();
        sidx = sidx2; e4 = e42; n = n2; c = c2;
    }

#pragma unroll
    for (int off = 16; off; off >>= 1)
#pragma unroll
        for (int k = 0; k < 4; k++)
            lsum[k] += __shfl_xor_sync(0xffffffffu, lsum[k], off);
    float tot = lsum[h];
    float inv = (tot > 0.f) ? (1.0f / tot) : 0.0f;

    float o[8];
    float sl = 0.f, sr = 0.f;
    const float* bb = b0 + lane * 8;
    const float* wl = wel1 + lane * 8;
    const float* wr = wel1 + 256 + lane * 8;
#pragma unroll
    for (int i = 0; i < 8; i++) {
        float v = acc[i] * inv + bb[i];
        v = (v > 0.f) ? v : expm1f(v);
        o[i] = v;
        sl += v * wl[i];
        sr += v * wr[i];
    }
    uint4 hp;
    hp.x = packh(o[0], o[1]); hp.y = packh(o[2], o[3]);
    hp.z = packh(o[4], o[5]); hp.w = packh(o[6], o[7]);
    *(uint4*)(h116 + (size_t)d * 256 + lane * 8) = hp;
#pragma unroll
    for (int off = 16; off; off >>= 1) {
        sl += __shfl_xor_sync(0xffffffffu, sl, off);
        sr += __shfl_xor_sync(0xffffffffu, sr, off);
    }
    if (lane == 0) { el1[d] = sl; er1[d] = sr; }
}

__global__ void __launch_bounds__(256)
agg1_kernel(const int* __restrict__ rowptr, const int* __restrict__ adj,
            const float* __restrict__ el, const float* __restrict__ er,
            const __half* __restrict__ ft, const __half* __restrict__ h116,
            const float* __restrict__ b1, float* __restrict__ hout,
            int nbase, int nend) {
    const int w = threadIdx.x >> 5;
    const int lane = threadIdx.x & 31;
    const int d = nbase + blockIdx.x * 8 + w;
    if (d >= nend) return;
    const int start = rowptr[d], end = rowptr[d + 1];

    float erd = er[d];
    float lsum = 0.f;
    float acc[8] = {0.f, 0.f, 0.f, 0.f, 0.f, 0.f, 0.f, 0.f};

    int c = start;
    int n = min(32, end - c);
    int sidx = 0;
    float elv = 0.f;
    if (c < end && lane < n) {
        sidx = adj[c + lane];
        elv = el[sidx];
    }

    while (c < end) {
        float nu = 0.f;
        if (lane < n) {
            float v = elv + erd;
            v = (v >= 0.f) ? v : NEG * v;
            nu = expf(v);
            lsum += nu;
        }

        int c2 = c + 32;
        int n2 = min(32, end - c2);
        int sidx2 = 0;
        float elv2 = 0.f;
        if (c2 < end && lane < n2) {
            sidx2 = adj[c2 + lane];
            elv2 = el[sidx2];
        }

        int j = 0;
        for (; j + 4 <= n; j += 4) {
            int s0 = __shfl_sync(0xffffffffu, sidx, j);
            int s1 = __shfl_sync(0xffffffffu, sidx, j + 1);
            int s2 = __shfl_sync(0xffffffffu, sidx, j + 2);
            int s3 = __shfl_sync(0xffffffffu, sidx, j + 3);
            float a0 = __shfl_sync(0xffffffffu, nu, j);
            float a1 = __shfl_sync(0xffffffffu, nu, j + 1);
            float a2 = __shfl_sync(0xffffffffu, nu, j + 2);
            float a3 = __shfl_sync(0xffffffffu, nu, j + 3);
            uint4 r0 = *(const uint4*)(ft + (size_t)s0 * 256 + lane * 8);
            uint4 r1 = *(const uint4*)(ft + (size_t)s1 * 256 + lane * 8);
            uint4 r2 = *(const uint4*)(ft + (size_t)s2 * 256 + lane * 8);
            uint4 r3 = *(const uint4*)(ft + (size_t)s3 * 256 + lane * 8);
            acc8(acc, a0, r0); acc8(acc, a1, r1);
            acc8(acc, a2, r2); acc8(acc, a3, r3);
        }
        for (; j < n; j++) {
            int s0 = __shfl_sync(0xffffffffu, sidx, j);
            float a0 = __shfl_sync(0xffffffffu, nu, j);
            uint4 r0 = *(const uint4*)(ft + (size_t)s0 * 256 + lane * 8);
            acc8(acc, a0, r0);
        }
        sidx = sidx2; elv = elv2; n = n2; c = c2;
    }

#pragma unroll
    for (int off = 16; off; off >>= 1)
        lsum += __shfl_xor_sync(0xffffffffu, lsum, off);
    float inv = (lsum > 0.f) ? (1.0f / lsum) : 0.0f;

    uint4 hr = *(const uint4*)(h116 + (size_t)d * 256 + lane * 8);
    float2 h0 = __half22float2(*reinterpret_cast<const half2*>(&hr.x));
    float2 h1p = __half22float2(*reinterpret_cast<const half2*>(&hr.y));
    float2 h2 = __half22float2(*reinterpret_cast<const half2*>(&hr.z));
    float2 h3 = __half22float2(*reinterpret_cast<const half2*>(&hr.w));
    float4 bb0 = *(const float4*)(b1 + lane * 8);
    float4 bb1 = *(const float4*)(b1 + lane * 8 + 4);
    float4 o0, o1;
    o0.x = acc[0] * inv + h0.x  + bb0.x;
    o0.y = acc[1] * inv + h0.y  + bb0.y;
    o0.z = acc[2] * inv + h1p.x + bb0.z;
    o0.w = acc[3] * inv + h1p.y + bb0.w;
    o1.x = acc[4] * inv + h2.x  + bb1.x;
    o1.y = acc[5] * inv + h2.y  + bb1.y;
    o1.z = acc[6] * inv + h3.x  + bb1.z;
    o1.w = acc[7] * inv + h3.y  + bb1.w;
    *(float4*)(hout + (size_t)d * 256 + lane * 8)     = o0;
    *(float4*)(hout + (size_t)d * 256 + lane * 8 + 4) = o1;
}

// =================== launch ==================================================
extern "C" void kernel_launch(void* const* d_in, const int* in_sizes, int n_in,
                              void* d_out, int out_size) {
    const float* x   = (const float*)d_in[0];
    const int*   src = (const int*)  d_in[1];
    const int*   dst = (const int*)  d_in[2];
    const float* W0  = (const float*)d_in[3];
    const float* al0 = (const float*)d_in[4];
    const float* ar0 = (const float*)d_in[5];
    const float* b0  = (const float*)d_in[6];
    const float* W1  = (const float*)d_in[7];
    const float* al1 = (const float*)d_in[8];
    const float* ar1 = (const float*)d_in[9];
    const float* b1  = (const float*)d_in[10];
    const float* Wl  = (const float*)d_in[11];
    const float* bl  = (const float*)d_in[12];

    float* out    = (float*)d_out;
    float* logits = out;
    float* hout   = out + (size_t)NN * NCLS;

    __half *ft16, *ft16b, *h116;
    float *el, *er, *el1, *er1, *wel0, *wel1;
    int *cnt, *rowptr, *adj;
    cudaGetSymbolAddress((void**)&ft16,   g_ft16);
    cudaGetSymbolAddress((void**)&ft16b,  g_ft16b);
    cudaGetSymbolAddress((void**)&h116,   g_h116);
    cudaGetSymbolAddress((void**)&el,     g_el);
    cudaGetSymbolAddress((void**)&er,     g_er);
    cudaGetSymbolAddress((void**)&el1,    g_el1);
    cudaGetSymbolAddress((void**)&er1,    g_er1);
    cudaGetSymbolAddress((void**)&wel0,   g_wel0);
    cudaGetSymbolAddress((void**)&wel1,   g_wel1);
    cudaGetSymbolAddress((void**)&cnt,    g_cnt);
    cudaGetSymbolAddress((void**)&rowptr, g_rowptr);
    cudaGetSymbolAddress((void**)&adj,    g_adj);

    static cudaStream_t s1 = nullptr, s2 = nullptr;
    static cudaEvent_t ev_fork = nullptr, ev_csr = nullptr, ev_el0 = nullptr,
                       ev_g0 = nullptr, ev_pa_m = nullptr, ev_pa_s = nullptr,
                       ev_end = nullptr;
    if (s1 == nullptr) {
        cudaStreamCreateWithFlags(&s1, cudaStreamNonBlocking);
        cudaStreamCreateWithFlags(&s2, cudaStreamNonBlocking);
        cudaEventCreateWithFlags(&ev_fork, cudaEventDisableTiming);
        cudaEventCreateWithFlags(&ev_csr,  cudaEventDisableTiming);
        cudaEventCreateWithFlags(&ev_el0,  cudaEventDisableTiming);
        cudaEventCreateWithFlags(&ev_g0,   cudaEventDisableTiming);
        cudaEventCreateWithFlags(&ev_pa_m, cudaEventDisableTiming);
        cudaEventCreateWithFlags(&ev_pa_s, cudaEventDisableTiming);
        cudaEventCreateWithFlags(&ev_end,  cudaEventDisableTiming);
    }

    const int T = 256;
    const int cs[5] = {0, NCHUNK, 2 * NCHUNK, 3 * NCHUNK, NN};

    cudaEventRecord(ev_fork, 0);

    // ---- s1: CSR build (fused scan) ----
    cudaStreamWaitEvent(s1, ev_fork, 0);
    cudaMemsetAsync(cnt, 0, NN * sizeof(int), s1);
    hist_kernel<<<(EE + T - 1) / T, T, 0, s1>>>(dst, cnt);
    scan_fused_kernel<<<1, 1024, 0, s1>>>(cnt, rowptr, cnt);  // cursor reuses cnt
    csr_fill_kernel<<<(EE + T - 1) / T, T, 0, s1>>>(src, dst, cnt, adj);
    cudaEventRecord(ev_csr, s1);

    // ---- s2: attention projections ----
    cudaStreamWaitEvent(s2, ev_fork, 0);
    prep_wel_kernel<<<2, 256, 0, s2>>>(W0, al0, ar0, W1, al1, ar1, wel0, wel1);
    eler0_kernel<<<(NN + 7) / 8, 256, 0, s2>>>(x, wel0, el, er);
    cudaEventRecord(ev_el0, s2);

    // ---- main: layer 0 projection ----
    {
        dim3 grid(2, (NN + 127) / 128);
        gemm_f16<128, 128, 2, 4, false><<<grid, 256>>>(x, W0, ft16, NN, IND, 256);
    }
    cudaEventRecord(ev_g0, 0);

    // ---- phase A: agg0(Ci) -> GEMM1(Ci), C0/C2 on main, C1/C3 on s2 ----
    cudaStreamWaitEvent(0, ev_csr, 0);
    cudaStreamWaitEvent(0, ev_el0, 0);
    cudaStreamWaitEvent(s2, ev_g0, 0);
    cudaStreamWaitEvent(s2, ev_csr, 0);   // el0 already ordered on s2

    for (int i = 0; i < 4; i++) {
        cudaStream_t st = (i & 1) ? s2 : 0;
        int s = cs[i], e = cs[i + 1], nc = e - s;
        agg0_kernel<<<(nc + 7) / 8, 256, 0, st>>>(rowptr, adj, el, er, ft16, b0,
                                                  wel1, h116, el1, er1, s, e);
        dim3 grid(2, (nc + 127) / 128);
        gemm_f16<128, 128, 2, 4, true><<<grid, 256, 0, st>>>(
            h116 + (size_t)s * 256, W1, ft16b + (size_t)s * 256, nc, 256, 256);
    }
    cudaEventRecord(ev_pa_m, 0);
    cudaEventRecord(ev_pa_s, s2);
    // hard join: agg1 gathers arbitrary ft16b rows
    cudaStreamWaitEvent(0, ev_pa_s, 0);
    cudaStreamWaitEvent(s2, ev_pa_m, 0);

    // ---- phase B: agg1(Ci) -> cls(Ci), C0/C2 on main, C1/C3 on s2 ----
    for (int i = 0; i < 4; i++) {
        cudaStream_t st = (i & 1) ? s2 : 0;
        int s = cs[i], e = cs[i + 1], nc = e - s;
        agg1_kernel<<<(nc + 7) / 8, 256, 0, st>>>(rowptr, adj, el1, er1, ft16b,
                                                  h116, b1, hout, s, e);
        dim3 grid(1, (nc + 127) / 128);
        gemm_bf16x3<128, 64, 4, 2><<<grid, 256, 0, st>>>(
            hout + (size_t)s * 256, Wl, logits + (size_t)s * 64, nc, OUT1, NCLS, bl);
    }
    cudaEventRecord(ev_end, s2);
    cudaStreamWaitEvent(0, ev_end, 0);
}

// round 14
// speedup vs baseline: 1.0719x; 1.0462x over previous
#include <cuda_runtime.h>
#include <cuda_fp16.h>
#include <math.h>
#include <stdint.h>

#define NN 50000
#define EE 800000
#define IND 256
#define HIDD 64
#define H0 4
#define OUT1 256
#define NCLS 64
#define NEG 0.2f
#define NCHUNK 12544   // pipeline chunk (98*128)

// ---------------- scratch (device globals; no allocation allowed) ----------
__device__ __half g_ft16[NN * 256];    // layer-0 projected features
__device__ __half g_ft16b[NN * 256];   // layer-1 projected features
__device__ __half g_h116[NN * 256];    // h1 in fp16
__device__ float  g_el[NN * H0];
__device__ float  g_er[NN * H0];
__device__ float  g_el1[NN];
__device__ float  g_er1[NN];
__device__ float  g_wel0[8 * 256];
__device__ float  g_wel1[2 * 256];
__device__ int    g_cnt[NN];
__device__ int    g_rowptr[NN + 1];
__device__ int    g_adj[EE];

// =================== CSR build ==============================================
__global__ void hist_kernel(const int* __restrict__ dst, int* __restrict__ cnt) {
    int e = blockIdx.x * blockDim.x + threadIdx.x;
    if (e < EE) atomicAdd(&cnt[dst[e]], 1);
}

// single-block fused exclusive scan over NN counters -> rowptr + cursor
__global__ void __launch_bounds__(1024)
scan_fused_kernel(const int* __restrict__ cnt,
                  int* __restrict__ rowptr, int* __restrict__ cursor) {
    __shared__ int s_warp[32];
    __shared__ int s_off;
    const int t = threadIdx.x;
    const int lane = t & 31;
    const int wid = t >> 5;
    if (t == 0) s_off = 0;
    __syncthreads();

    for (int base = 0; base < NN; base += 1024) {
        int i = base + t;
        int v = (i < NN) ? cnt[i] : 0;
        int ws = v;
#pragma unroll
        for (int o = 1; o < 32; o <<= 1) {
            int u = __shfl_up_sync(0xffffffffu, ws, o);
            if (lane >= o) ws += u;
        }
        if (lane == 31) s_warp[wid] = ws;
        __syncthreads();
        if (wid == 0) {
            int wv = s_warp[lane];
            int wscan = wv;
#pragma unroll
            for (int o = 1; o < 32; o <<= 1) {
                int u = __shfl_up_sync(0xffffffffu, wscan, o);
                if (lane >= o) wscan += u;
            }
            s_warp[lane] = wscan;
        }
        __syncthreads();
        int ex = ws - v + (wid > 0 ? s_warp[wid - 1] : 0) + s_off;
        if (i < NN) { rowptr[i] = ex; cursor[i] = ex; }
        __syncthreads();
        if (t == 0) s_off += s_warp[31];
        __syncthreads();
    }
    if (t == 0) rowptr[NN] = EE;
}

__global__ void csr_fill_kernel(const int* __restrict__ src,
                                const int* __restrict__ dst,
                                int* __restrict__ cursor,
                                int* __restrict__ adj) {
    int e = blockIdx.x * blockDim.x + threadIdx.x;
    if (e >= EE) return;
    int pos = atomicAdd(&cursor[dst[e]], 1);
    adj[pos] = src[e];
}

// =================== attention projection prep (warp-parallel) =============
// blocks 0..31: wel0 (warp per k); blocks 32..63: wel1 (warp per k)
__global__ void __launch_bounds__(256)
prep_wel_kernel(const float* __restrict__ W0,
                const float* __restrict__ al0,
                const float* __restrict__ ar0,
                const float* __restrict__ W1,
                const float* __restrict__ al1,
                const float* __restrict__ ar1,
                float* __restrict__ wel0,
                float* __restrict__ wel1) {
    const int warp = threadIdx.x >> 5;
    const int lane = threadIdx.x & 31;
    if (blockIdx.x < 32) {
        const int k = blockIdx.x * 8 + warp;
        const float* wrow = W0 + (size_t)k * 256;
#pragma unroll
        for (int j = 0; j < 4; j++) {
            float w0v = wrow[j * 64 + lane];
            float w1v = wrow[j * 64 + 32 + lane];
            float sl = w0v * al0[j * 64 + lane] + w1v * al0[j * 64 + 32 + lane];
            float sr = w0v * ar0[j * 64 + lane] + w1v * ar0[j * 64 + 32 + lane];
#pragma unroll
            for (int o = 16; o; o >>= 1) {
                sl += __shfl_xor_sync(0xffffffffu, sl, o);
                sr += __shfl_xor_sync(0xffffffffu, sr, o);
            }
            if (lane == 0) {
                wel0[j * 256 + k]       = sl;
                wel0[(4 + j) * 256 + k] = sr;
            }
        }
    } else {
        const int k = (blockIdx.x - 32) * 8 + warp;
        const float* wrow = W1 + (size_t)k * 256;
        float sl = 0.f, sr = 0.f;
#pragma unroll
        for (int it = 0; it < 8; it++) {
            float wv = wrow[it * 32 + lane];
            sl += wv * al1[it * 32 + lane];
            sr += wv * ar1[it * 32 + lane];
        }
#pragma unroll
        for (int o = 16; o; o >>= 1) {
            sl += __shfl_xor_sync(0xffffffffu, sl, o);
            sr += __shfl_xor_sync(0xffffffffu, sr, o);
        }
        if (lane == 0) {
            wel1[k]       = sl;
            wel1[256 + k] = sr;
        }
    }
}

__global__ void __launch_bounds__(256)
eler0_kernel(const float* __restrict__ X, const float* __restrict__ WelT,
             float* __restrict__ el, float* __restrict__ er) {
    __shared__ float w[8][256];
    int tid = threadIdx.x;
    for (int i = tid; i < 8 * 256; i += 256) ((float*)w)[i] = WelT[i];
    __syncthreads();
    int n = blockIdx.x * 8 + (tid >> 5);
    int lane = tid & 31;
    if (n >= NN) return;
    const float* xr = X + (size_t)n * 256;
    float acc[8];
#pragma unroll
    for (int j = 0; j < 8; j++) acc[j] = 0.f;
#pragma unroll
    for (int it = 0; it < 8; it++) {
        float xv = xr[lane + it * 32];
#pragma unroll
        for (int j = 0; j < 8; j++) acc[j] += xv * w[j][lane + it * 32];
    }
#pragma unroll
    for (int o = 16; o; o >>= 1)
#pragma unroll
        for (int j = 0; j < 8; j++) acc[j] += __shfl_xor_sync(0xffffffffu, acc[j], o);
    if (lane == 0) {
#pragma unroll
        for (int j = 0; j < 4; j++) el[n * 4 + j] = acc[j];
#pragma unroll
        for (int j = 0; j < 4; j++) er[n * 4 + j] = acc[4 + j];
    }
}

// =================== GEMM helpers ===========================================
__device__ __forceinline__ uint32_t packbf(float f0, float f1) {
    uint32_t r;
    asm("cvt.rn.bf16x2.f32 %0, %1, %2;" : "=r"(r) : "f"(f1), "f"(f0));
    return r;
}
__device__ __forceinline__ uint32_t packh(float f0, float f1) {
    uint32_t r;
    asm("cvt.rn.f16x2.f32 %0, %1, %2;" : "=r"(r) : "f"(f1), "f"(f0));
    return r;
}
__device__ __forceinline__ void bfsplit2(float f0, float f1,
                                         uint32_t& h, uint32_t& l) {
    h = packbf(f0, f1);
    float h0 = __uint_as_float(h << 16);
    float h1 = __uint_as_float(h & 0xffff0000u);
    l = packbf(f0 - h0, f1 - h1);
}

#define MMA_BF16(d, a, b) \
    asm volatile("mma.sync.aligned.m16n8k16.row.col.f32.bf16.bf16.f32 " \
                 "{%0,%1,%2,%3}, {%4,%5,%6,%7}, {%8,%9}, {%0,%1,%2,%3};" \
                 : "+f"(d[0]), "+f"(d[1]), "+f"(d[2]), "+f"(d[3]) \
                 : "r"(a[0]), "r"(a[1]), "r"(a[2]), "r"(a[3]), \
                   "r"(b[0]), "r"(b[1]))

#define MMA_F16(d, a, b) \
    asm volatile("mma.sync.aligned.m16n8k16.row.col.f32.f16.f16.f32 " \
                 "{%0,%1,%2,%3}, {%4,%5,%6,%7}, {%8,%9}, {%0,%1,%2,%3};" \
                 : "+f"(d[0]), "+f"(d[1]), "+f"(d[2]), "+f"(d[3]) \
                 : "r"(a[0]), "r"(a[1]), "r"(a[2]), "r"(a[3]), \
                   "r"(b[0]), "r"(b[1]))

// ---- fp16 single-term GEMM: C16 = fp16(A @ B). AHALF: A is fp16. ----------
template<int BM, int BN, int WARPS_M, int WARPS_N, bool AHALF>
__global__ void __launch_bounds__(256, 2)
gemm_f16(const void* __restrict__ Av, const float* __restrict__ B,
         __half* __restrict__ C16, int Nr, int K, int M) {
    constexpr int WM = BM / WARPS_M;
    constexpr int WN = BN / WARPS_N;
    constexpr int MF = WM / 16;
    constexpr int NF = WN / 8;
    constexpr int LD = 136;
    constexpr int STG = 8 * LD;
    constexpr int BQ = BN / 4;

    __shared__ uint32_t Ah[2][STG];
    __shared__ uint32_t Bh[2][STG];

    const float*  Af  = (const float*)Av;
    const __half* A16 = (const __half*)Av;

    const int tid  = threadIdx.x;
    const int lane = tid & 31;
    const int warp = tid >> 5;
    const int wm = warp / WARPS_N;
    const int wn = warp % WARPS_N;
    const int rowBase = blockIdx.y * BM;
    const int colBase = blockIdx.x * BN;
    const int g  = lane >> 2;
    const int tg = lane & 3;

    float acc[MF][NF][4];
#pragma unroll
    for (int i = 0; i < MF; i++)
#pragma unroll
        for (int j = 0; j < NF; j++)
#pragma unroll
            for (int k = 0; k < 4; k++) acc[i][j][k] = 0.0f;

    float4 ra[2];
    uint2  ra16[2];
    float4 rb0, rb1;
    const int am[2]  = { (tid) >> 2, (tid + 256) >> 2 };
    const int akq = (tid & 3) << 2;
    const bool bact = tid < 8 * BQ;
    const int bkp = bact ? tid / BQ : 0;
    const int bnq = bact ? (tid % BQ) << 2 : 0;

    auto ldg_tile = [&](int k0) {
#pragma unroll
        for (int i = 0; i < 2; i++) {
            int gr = rowBase + am[i];
            int grc = (gr < Nr) ? gr : (Nr - 1);
            if (AHALF)
                ra16[i] = *(const uint2*)(A16 + (size_t)grc * K + k0 + akq);
            else
                ra[i] = *(const float4*)(Af + (size_t)grc * K + k0 + akq);
        }
        if (bact) {
            rb0 = *(const float4*)(B + (size_t)(k0 + 2 * bkp)     * M + colBase + bnq);
            rb1 = *(const float4*)(B + (size_t)(k0 + 2 * bkp + 1) * M + colBase + bnq);
        }
    };

    auto sts_tile = [&](int s) {
#pragma unroll
        for (int i = 0; i < 2; i++) {
            int kp0 = (akq >> 1);
            if (AHALF) {
                Ah[s][kp0 * LD + am[i]]       = ra16[i].x;
                Ah[s][(kp0 + 1) * LD + am[i]] = ra16[i].y;
            } else {
                Ah[s][kp0 * LD + am[i]]       = packh(ra[i].x, ra[i].y);
                Ah[s][(kp0 + 1) * LD + am[i]] = packh(ra[i].z, ra[i].w);
            }
        }
        if (bact) {
            const float* p0 = &rb0.x;
            const float* p1 = &rb1.x;
            uint32_t hh[4];
#pragma unroll
            for (int j = 0; j < 4; j++) hh[j] = packh(p0[j], p1[j]);
            *(uint4*)&Bh[s][bkp * LD + bnq] = make_uint4(hh[0], hh[1], hh[2], hh[3]);
        }
    };

    const int NIT = K / 16;
    ldg_tile(0);

    for (int it = 0; it < NIT; it++) {
        const int s = it & 1;
        sts_tile(s);
        __syncthreads();
        if (it + 1 < NIT) ldg_tile((it + 1) * 16);

        uint32_t bh[NF][2];
#pragma unroll
        for (int nf = 0; nf < NF; nf++) {
            int c0 = wn * WN + nf * 8 + g;
            bh[nf][0] = Bh[s][tg * LD + c0];
            bh[nf][1] = Bh[s][(tg + 4) * LD + c0];
        }
#pragma unroll
        for (int mf = 0; mf < MF; mf++) {
            int r0 = wm * WM + mf * 16 + g;
            uint32_t ah[4];
            ah[0] = Ah[s][tg * LD + r0];
            ah[1] = Ah[s][tg * LD + r0 + 8];
            ah[2] = Ah[s][(tg + 4) * LD + r0];
            ah[3] = Ah[s][(tg + 4) * LD + r0 + 8];
#pragma unroll
            for (int nf = 0; nf < NF; nf++)
                MMA_F16(acc[mf][nf], ah, bh[nf]);
        }
    }

#pragma unroll
    for (int mf = 0; mf < MF; mf++) {
#pragma unroll
        for (int nf = 0; nf < NF; nf++) {
            int row = rowBase + wm * WM + mf * 16 + g;
            int col = colBase + wn * WN + nf * 8 + tg * 2;
            if (row < Nr)
                *(uint32_t*)(C16 + (size_t)row * M + col) =
                    packh(acc[mf][nf][0], acc[mf][nf][1]);
            if (row + 8 < Nr)
                *(uint32_t*)(C16 + (size_t)(row + 8) * M + col) =
                    packh(acc[mf][nf][2], acc[mf][nf][3]);
        }
    }
}

// ---- bf16 3-term GEMM (classifier): C[Nr,M] = A@B + bias -------------------
template<int BM, int BN, int WARPS_M, int WARPS_N>
__global__ void __launch_bounds__(256, 2)
gemm_bf16x3(const float* __restrict__ A, const float* __restrict__ B,
            float* __restrict__ C, int Nr, int K, int M,
            const float* __restrict__ bias) {
    constexpr int WM = BM / WARPS_M;
    constexpr int WN = BN / WARPS_N;
    constexpr int MF = WM / 16;
    constexpr int NF = WN / 8;
    constexpr int LD = 136;
    constexpr int STG = 8 * LD;
    constexpr int BQ = BN / 4;

    __shared__ uint32_t Ah[2][STG], Al[2][STG];
    __shared__ uint32_t Bh[2][STG], Bl[2][STG];

    const int tid  = threadIdx.x;
    const int lane = tid & 31;
    const int warp = tid >> 5;
    const int wm = warp / WARPS_N;
    const int wn = warp % WARPS_N;
    const int rowBase = blockIdx.y * BM;
    const int colBase = blockIdx.x * BN;
    const int g  = lane >> 2;
    const int tg = lane & 3;

    float acc[MF][NF][4];
#pragma unroll
    for (int i = 0; i < MF; i++)
#pragma unroll
        for (int j = 0; j < NF; j++)
#pragma unroll
            for (int k = 0; k < 4; k++) acc[i][j][k] = 0.0f;

    float4 ra[2];
    float4 rb0, rb1;
    const int am[2]  = { (tid) >> 2, (tid + 256) >> 2 };
    const int akq = (tid & 3) << 2;
    const bool bact = tid < 8 * BQ;
    const int bkp = bact ? tid / BQ : 0;
    const int bnq = bact ? (tid % BQ) << 2 : 0;

    auto ldg_tile = [&](int k0) {
#pragma unroll
        for (int i = 0; i < 2; i++) {
            int gr = rowBase + am[i];
            int grc = (gr < Nr) ? gr : (Nr - 1);
            ra[i] = *(const float4*)(A + (size_t)grc * K + k0 + akq);
        }
        if (bact) {
            rb0 = *(const float4*)(B + (size_t)(k0 + 2 * bkp)     * M + colBase + bnq);
            rb1 = *(const float4*)(B + (size_t)(k0 + 2 * bkp + 1) * M + colBase + bnq);
        }
    };

    auto sts_tile = [&](int s) {
#pragma unroll
        for (int i = 0; i < 2; i++) {
            int kp0 = (akq >> 1);
            uint32_t h, l;
            bfsplit2(ra[i].x, ra[i].y, h, l);
            Ah[s][kp0 * LD + am[i]] = h;
            Al[s][kp0 * LD + am[i]] = l;
            bfsplit2(ra[i].z, ra[i].w, h, l);
            Ah[s][(kp0 + 1) * LD + am[i]] = h;
            Al[s][(kp0 + 1) * LD + am[i]] = l;
        }
        if (bact) {
            const float* p0 = &rb0.x;
            const float* p1 = &rb1.x;
            uint32_t hh[4], ll[4];
#pragma unroll
            for (int j = 0; j < 4; j++) bfsplit2(p0[j], p1[j], hh[j], ll[j]);
            *(uint4*)&Bh[s][bkp * LD + bnq] = make_uint4(hh[0], hh[1], hh[2], hh[3]);
            *(uint4*)&Bl[s][bkp * LD + bnq] = make_uint4(ll[0], ll[1], ll[2], ll[3]);
        }
    };

    const int NIT = K / 16;
    ldg_tile(0);

    for (int it = 0; it < NIT; it++) {
        const int s = it & 1;
        sts_tile(s);
        __syncthreads();
        if (it + 1 < NIT) ldg_tile((it + 1) * 16);

        uint32_t bh[NF][2], bl[NF][2];
#pragma unroll
        for (int nf = 0; nf < NF; nf++) {
            int c0 = wn * WN + nf * 8 + g;
            bh[nf][0] = Bh[s][tg * LD + c0];
            bh[nf][1] = Bh[s][(tg + 4) * LD + c0];
            bl[nf][0] = Bl[s][tg * LD + c0];
            bl[nf][1] = Bl[s][(tg + 4) * LD + c0];
        }
#pragma unroll
        for (int mf = 0; mf < MF; mf++) {
            int r0 = wm * WM + mf * 16 + g;
            uint32_t ah[4], al[4];
            ah[0] = Ah[s][tg * LD + r0];
            ah[1] = Ah[s][tg * LD + r0 + 8];
            ah[2] = Ah[s][(tg + 4) * LD + r0];
            ah[3] = Ah[s][(tg + 4) * LD + r0 + 8];
            al[0] = Al[s][tg * LD + r0];
            al[1] = Al[s][tg * LD + r0 + 8];
            al[2] = Al[s][(tg + 4) * LD + r0];
            al[3] = Al[s][(tg + 4) * LD + r0 + 8];
#pragma unroll
            for (int nf = 0; nf < NF; nf++) {
                MMA_BF16(acc[mf][nf], al, bh[nf]);
                MMA_BF16(acc[mf][nf], ah, bl[nf]);
                MMA_BF16(acc[mf][nf], ah, bh[nf]);
            }
        }
    }

#pragma unroll
    for (int mf = 0; mf < MF; mf++) {
#pragma unroll
        for (int nf = 0; nf < NF; nf++) {
            int row = rowBase + wm * WM + mf * 16 + g;
            int col = colBase + wn * WN + nf * 8 + tg * 2;
            float b0v = bias ? bias[col]     : 0.0f;
            float b1v = bias ? bias[col + 1] : 0.0f;
            if (row < Nr) {
                float2 o = make_float2(acc[mf][nf][0] + b0v, acc[mf][nf][1] + b1v);
                *(float2*)(C + (size_t)row * M + col) = o;
            }
            if (row + 8 < Nr) {
                float2 o = make_float2(acc[mf][nf][2] + b0v, acc[mf][nf][3] + b1v);
                *(float2*)(C + (size_t)(row + 8) * M + col) = o;
            }
        }
    }
}

// =================== aggregation: one WARP per dst node =====================
__device__ __forceinline__ void acc8(float* acc, float a, uint4 r) {
    float2 f0 = __half22float2(*reinterpret_cast<const half2*>(&r.x));
    float2 f1 = __half22float2(*reinterpret_cast<const half2*>(&r.y));
    float2 f2 = __half22float2(*reinterpret_cast<const half2*>(&r.z));
    float2 f3 = __half22float2(*reinterpret_cast<const half2*>(&r.w));
    acc[0] += a * f0.x; acc[1] += a * f0.y;
    acc[2] += a * f1.x; acc[3] += a * f1.y;
    acc[4] += a * f2.x; acc[5] += a * f2.y;
    acc[6] += a * f3.x; acc[7] += a * f3.y;
}

__global__ void __launch_bounds__(256)
agg0_kernel(const int* __restrict__ rowptr, const int* __restrict__ adj,
            const float* __restrict__ el, const float* __restrict__ er,
            const __half* __restrict__ ft, const float* __restrict__ b0,
            const float* __restrict__ wel1,
            __half* __restrict__ h116,
            float* __restrict__ el1, float* __restrict__ er1,
            int nbase, int nend) {
    const int w = threadIdx.x >> 5;
    const int lane = threadIdx.x & 31;
    const int d = nbase + blockIdx.x * 8 + w;
    if (d >= nend) return;
    const int h = lane >> 3;
    const int start = rowptr[d], end = rowptr[d + 1];

    __shared__ float s_num[8][32][4];

    float4 erd = *(const float4*)(er + (size_t)d * 4);
    float lsum[4] = {0.f, 0.f, 0.f, 0.f};
    float acc[8] = {0.f, 0.f, 0.f, 0.f, 0.f, 0.f, 0.f, 0.f};

    int c = start;
    int n = min(32, end - c);
    int sidx = 0;
    float4 e4 = make_float4(0.f, 0.f, 0.f, 0.f);
    if (c < end && lane < n) {
        sidx = adj[c + lane];
        e4 = *(const float4*)(el + (size_t)sidx * 4);
    }

    while (c < end) {
        if (lane < n) {
            float v[4];
            v[0] = e4.x + erd.x; v[1] = e4.y + erd.y;
            v[2] = e4.z + erd.z; v[3] = e4.w + erd.w;
#pragma unroll
            for (int k = 0; k < 4; k++) {
                float vv = (v[k] >= 0.f) ? v[k] : NEG * v[k];
                float nu = expf(vv);
                s_num[w][lane][k] = nu;
                lsum[k] += nu;
            }
        }
        __syncwarp();

        int c2 = c + 32;
        int n2 = min(32, end - c2);
        int sidx2 = 0;
        float4 e42 = make_float4(0.f, 0.f, 0.f, 0.f);
        if (c2 < end && lane < n2) {
            sidx2 = adj[c2 + lane];
            e42 = *(const float4*)(el + (size_t)sidx2 * 4);
        }

        int j = 0;
        for (; j + 4 <= n; j += 4) {
            int s0 = __shfl_sync(0xffffffffu, sidx, j);
            int s1 = __shfl_sync(0xffffffffu, sidx, j + 1);
            int s2 = __shfl_sync(0xffffffffu, sidx, j + 2);
            int s3 = __shfl_sync(0xffffffffu, sidx, j + 3);
            float a0 = s_num[w][j][h],     a1 = s_num[w][j + 1][h];
            float a2 = s_num[w][j + 2][h], a3 = s_num[w][j + 3][h];
            uint4 r0 = *(const uint4*)(ft + (size_t)s0 * 256 + lane * 8);
            uint4 r1 = *(const uint4*)(ft + (size_t)s1 * 256 + lane * 8);
            uint4 r2 = *(const uint4*)(ft + (size_t)s2 * 256 + lane * 8);
            uint4 r3 = *(const uint4*)(ft + (size_t)s3 * 256 + lane * 8);
            acc8(acc, a0, r0); acc8(acc, a1, r1);
            acc8(acc, a2, r2); acc8(acc, a3, r3);
        }
        for (; j < n; j++) {
            int s0 = __shfl_sync(0xffffffffu, sidx, j);
            float a0 = s_num[w][j][h];
            uint4 r0 = *(const uint4*)(ft + (size_t)s0 * 256 + lane * 8);
            acc8(acc, a0, r0);
        }
        __syncwarp();
        sidx = sidx2; e4 = e42; n = n2; c = c2;
    }

#pragma unroll
    for (int off = 16; off; off >>= 1)
#pragma unroll
        for (int k = 0; k < 4; k++)
            lsum[k] += __shfl_xor_sync(0xffffffffu, lsum[k], off);
    float tot = lsum[h];
    float inv = (tot > 0.f) ? (1.0f / tot) : 0.0f;

    float o[8];
    float sl = 0.f, sr = 0.f;
    const float* bb = b0 + lane * 8;
    const float* wl = wel1 + lane * 8;
    const float* wr = wel1 + 256 + lane * 8;
#pragma unroll
    for (int i = 0; i < 8; i++) {
        float v = acc[i] * inv + bb[i];
        v = (v > 0.f) ? v : expm1f(v);
        o[i] = v;
        sl += v * wl[i];
        sr += v * wr[i];
    }
    uint4 hp;
    hp.x = packh(o[0], o[1]); hp.y = packh(o[2], o[3]);
    hp.z = packh(o[4], o[5]); hp.w = packh(o[6], o[7]);
    *(uint4*)(h116 + (size_t)d * 256 + lane * 8) = hp;
#pragma unroll
    for (int off = 16; off; off >>= 1) {
        sl += __shfl_xor_sync(0xffffffffu, sl, off);
        sr += __shfl_xor_sync(0xffffffffu, sr, off);
    }
    if (lane == 0) { el1[d] = sl; er1[d] = sr; }
}

__global__ void __launch_bounds__(256)
agg1_kernel(const int* __restrict__ rowptr, const int* __restrict__ adj,
            const float* __restrict__ el, const float* __restrict__ er,
            const __half* __restrict__ ft, const __half* __restrict__ h116,
            const float* __restrict__ b1, float* __restrict__ hout,
            int nbase, int nend) {
    const int w = threadIdx.x >> 5;
    const int lane = threadIdx.x & 31;
    const int d = nbase + blockIdx.x * 8 + w;
    if (d >= nend) return;
    const int start = rowptr[d], end = rowptr[d + 1];

    float erd = er[d];
    float lsum = 0.f;
    float acc[8] = {0.f, 0.f, 0.f, 0.f, 0.f, 0.f, 0.f, 0.f};

    int c = start;
    int n = min(32, end - c);
    int sidx = 0;
    float elv = 0.f;
    if (c < end && lane < n) {
        sidx = adj[c + lane];
        elv = el[sidx];
    }

    while (c < end) {
        float nu = 0.f;
        if (lane < n) {
            float v = elv + erd;
            v = (v >= 0.f) ? v : NEG * v;
            nu = expf(v);
            lsum += nu;
        }

        int c2 = c + 32;
        int n2 = min(32, end - c2);
        int sidx2 = 0;
        float elv2 = 0.f;
        if (c2 < end && lane < n2) {
            sidx2 = adj[c2 + lane];
            elv2 = el[sidx2];
        }

        int j = 0;
        for (; j + 4 <= n; j += 4) {
            int s0 = __shfl_sync(0xffffffffu, sidx, j);
            int s1 = __shfl_sync(0xffffffffu, sidx, j + 1);
            int s2 = __shfl_sync(0xffffffffu, sidx, j + 2);
            int s3 = __shfl_sync(0xffffffffu, sidx, j + 3);
            float a0 = __shfl_sync(0xffffffffu, nu, j);
            float a1 = __shfl_sync(0xffffffffu, nu, j + 1);
            float a2 = __shfl_sync(0xffffffffu, nu, j + 2);
            float a3 = __shfl_sync(0xffffffffu, nu, j + 3);
            uint4 r0 = *(const uint4*)(ft + (size_t)s0 * 256 + lane * 8);
            uint4 r1 = *(const uint4*)(ft + (size_t)s1 * 256 + lane * 8);
            uint4 r2 = *(const uint4*)(ft + (size_t)s2 * 256 + lane * 8);
            uint4 r3 = *(const uint4*)(ft + (size_t)s3 * 256 + lane * 8);
            acc8(acc, a0, r0); acc8(acc, a1, r1);
            acc8(acc, a2, r2); acc8(acc, a3, r3);
        }
        for (; j < n; j++) {
            int s0 = __shfl_sync(0xffffffffu, sidx, j);
            float a0 = __shfl_sync(0xffffffffu, nu, j);
            uint4 r0 = *(const uint4*)(ft + (size_t)s0 * 256 + lane * 8);
            acc8(acc, a0, r0);
        }
        sidx = sidx2; elv = elv2; n = n2; c = c2;
    }

#pragma unroll
    for (int off = 16; off; off >>= 1)
        lsum += __shfl_xor_sync(0xffffffffu, lsum, off);
    float inv = (lsum > 0.f) ? (1.0f / lsum) : 0.0f;

    uint4 hr = *(const uint4*)(h116 + (size_t)d * 256 + lane * 8);
    float2 h0 = __half22float2(*reinterpret_cast<const half2*>(&hr.x));
    float2 h1p = __half22float2(*reinterpret_cast<const half2*>(&hr.y));
    float2 h2 = __half22float2(*reinterpret_cast<const half2*>(&hr.z));
    float2 h3 = __half22float2(*reinterpret_cast<const half2*>(&hr.w));
    float4 bb0 = *(const float4*)(b1 + lane * 8);
    float4 bb1 = *(const float4*)(b1 + lane * 8 + 4);
    float4 o0, o1;
    o0.x = acc[0] * inv + h0.x  + bb0.x;
    o0.y = acc[1] * inv + h0.y  + bb0.y;
    o0.z = acc[2] * inv + h1p.x + bb0.z;
    o0.w = acc[3] * inv + h1p.y + bb0.w;
    o1.x = acc[4] * inv + h2.x  + bb1.x;
    o1.y = acc[5] * inv + h2.y  + bb1.y;
    o1.z = acc[6] * inv + h3.x  + bb1.z;
    o1.w = acc[7] * inv + h3.y  + bb1.w;
    *(float4*)(hout + (size_t)d * 256 + lane * 8)     = o0;
    *(float4*)(hout + (size_t)d * 256 + lane * 8 + 4) = o1;
}

// =================== launch ==================================================
extern "C" void kernel_launch(void* const* d_in, const int* in_sizes, int n_in,
                              void* d_out, int out_size) {
    const float* x   = (const float*)d_in[0];
    const int*   src = (const int*)  d_in[1];
    const int*   dst = (const int*)  d_in[2];
    const float* W0  = (const float*)d_in[3];
    const float* al0 = (const float*)d_in[4];
    const float* ar0 = (const float*)d_in[5];
    const float* b0  = (const float*)d_in[6];
    const float* W1  = (const float*)d_in[7];
    const float* al1 = (const float*)d_in[8];
    const float* ar1 = (const float*)d_in[9];
    const float* b1  = (const float*)d_in[10];
    const float* Wl  = (const float*)d_in[11];
    const float* bl  = (const float*)d_in[12];

    float* out    = (float*)d_out;
    float* logits = out;
    float* hout   = out + (size_t)NN * NCLS;

    __half *ft16, *ft16b, *h116;
    float *el, *er, *el1, *er1, *wel0, *wel1;
    int *cnt, *rowptr, *adj;
    cudaGetSymbolAddress((void**)&ft16,   g_ft16);
    cudaGetSymbolAddress((void**)&ft16b,  g_ft16b);
    cudaGetSymbolAddress((void**)&h116,   g_h116);
    cudaGetSymbolAddress((void**)&el,     g_el);
    cudaGetSymbolAddress((void**)&er,     g_er);
    cudaGetSymbolAddress((void**)&el1,    g_el1);
    cudaGetSymbolAddress((void**)&er1,    g_er1);
    cudaGetSymbolAddress((void**)&wel0,   g_wel0);
    cudaGetSymbolAddress((void**)&wel1,   g_wel1);
    cudaGetSymbolAddress((void**)&cnt,    g_cnt);
    cudaGetSymbolAddress((void**)&rowptr, g_rowptr);
    cudaGetSymbolAddress((void**)&adj,    g_adj);

    static cudaStream_t s1 = nullptr, s2 = nullptr;
    static cudaEvent_t ev_fork = nullptr, ev_csr = nullptr, ev_el0 = nullptr,
                       ev_g0 = nullptr, ev_pa_m = nullptr, ev_pa_s = nullptr,
                       ev_end = nullptr;
    if (s1 == nullptr) {
        cudaStreamCreateWithFlags(&s1, cudaStreamNonBlocking);
        cudaStreamCreateWithFlags(&s2, cudaStreamNonBlocking);
        cudaEventCreateWithFlags(&ev_fork, cudaEventDisableTiming);
        cudaEventCreateWithFlags(&ev_csr,  cudaEventDisableTiming);
        cudaEventCreateWithFlags(&ev_el0,  cudaEventDisableTiming);
        cudaEventCreateWithFlags(&ev_g0,   cudaEventDisableTiming);
        cudaEventCreateWithFlags(&ev_pa_m, cudaEventDisableTiming);
        cudaEventCreateWithFlags(&ev_pa_s, cudaEventDisableTiming);
        cudaEventCreateWithFlags(&ev_end,  cudaEventDisableTiming);
    }

    const int T = 256;
    const int cs[5] = {0, NCHUNK, 2 * NCHUNK, 3 * NCHUNK, NN};

    cudaEventRecord(ev_fork, 0);

    // ---- s1: CSR build (fused scan) ----
    cudaStreamWaitEvent(s1, ev_fork, 0);
    cudaMemsetAsync(cnt, 0, NN * sizeof(int), s1);
    hist_kernel<<<(EE + T - 1) / T, T, 0, s1>>>(dst, cnt);
    scan_fused_kernel<<<1, 1024, 0, s1>>>(cnt, rowptr, cnt);  // cursor reuses cnt
    csr_fill_kernel<<<(EE + T - 1) / T, T, 0, s1>>>(src, dst, cnt, adj);
    cudaEventRecord(ev_csr, s1);

    // ---- s2: attention projections (warp-parallel prep) ----
    cudaStreamWaitEvent(s2, ev_fork, 0);
    prep_wel_kernel<<<64, 256, 0, s2>>>(W0, al0, ar0, W1, al1, ar1, wel0, wel1);
    eler0_kernel<<<(NN + 7) / 8, 256, 0, s2>>>(x, wel0, el, er);
    cudaEventRecord(ev_el0, s2);

    // ---- main: layer 0 projection ----
    {
        dim3 grid(2, (NN + 127) / 128);
        gemm_f16<128, 128, 2, 4, false><<<grid, 256>>>(x, W0, ft16, NN, IND, 256);
    }
    cudaEventRecord(ev_g0, 0);

    // ---- phase A: agg0(Ci) -> GEMM1(Ci), C0/C2 on main, C1/C3 on s2 ----
    cudaStreamWaitEvent(0, ev_csr, 0);
    cudaStreamWaitEvent(0, ev_el0, 0);
    cudaStreamWaitEvent(s2, ev_g0, 0);
    cudaStreamWaitEvent(s2, ev_csr, 0);

    for (int i = 0; i < 4; i++) {
        cudaStream_t st = (i & 1) ? s2 : 0;
        int s = cs[i], e = cs[i + 1], nc = e - s;
        agg0_kernel<<<(nc + 7) / 8, 256, 0, st>>>(rowptr, adj, el, er, ft16, b0,
                                                  wel1, h116, el1, er1, s, e);
        dim3 grid(2, (nc + 127) / 128);
        gemm_f16<128, 128, 2, 4, true><<<grid, 256, 0, st>>>(
            h116 + (size_t)s * 256, W1, ft16b + (size_t)s * 256, nc, 256, 256);
    }
    cudaEventRecord(ev_pa_m, 0);
    cudaEventRecord(ev_pa_s, s2);
    cudaStreamWaitEvent(0, ev_pa_s, 0);
    cudaStreamWaitEvent(s2, ev_pa_m, 0);

    // ---- phase B: agg1(Ci) -> cls(Ci), C0/C2 on main, C1/C3 on s2 ----
    for (int i = 0; i < 4; i++) {
        cudaStream_t st = (i & 1) ? s2 : 0;
        int s = cs[i], e = cs[i + 1], nc = e - s;
        agg1_kernel<<<(nc + 7) / 8, 256, 0, st>>>(rowptr, adj, el1, er1, ft16b,
                                                  h116, b1, hout, s, e);
        dim3 grid(1, (nc + 127) / 128);
        gemm_bf16x3<128, 64, 4, 2><<<grid, 256, 0, st>>>(
            hout + (size_t)s * 256, Wl, logits + (size_t)s * 64, nc, OUT1, NCLS, bl);
    }
    cudaEventRecord(ev_end, s2);
    cudaStreamWaitEvent(0, ev_end, 0);
}

// round 15
// speedup vs baseline: 1.1010x; 1.0271x over previous
#include <cuda_runtime.h>
#include <cuda_fp16.h>
#include <math.h>
#include <stdint.h>

#define NN 50000
#define EE 800000
#define IND 256
#define HIDD 64
#define H0 4
#define OUT1 256
#define NCLS 64
#define NEG 0.2f
#define NCHUNK 12544   // pipeline chunk (98*128)

// ---------------- scratch (device globals; no allocation allowed) ----------
__device__ __half g_ft16[NN * 256];    // layer-0 projected features
__device__ __half g_ft16b[NN * 256];   // layer-1 projected features
__device__ __half g_h116[NN * 256];    // h1 in fp16
__device__ float  g_el[NN * H0];
__device__ float  g_er[NN * H0];
__device__ float  g_el1[NN];
__device__ float  g_er1[NN];
__device__ float  g_wel0[8 * 256];
__device__ float  g_wel1[2 * 256];
__device__ int    g_cnt[NN];
__device__ int    g_rowptr[NN + 1];
__device__ int    g_adj[EE];

// =================== CSR build ==============================================
__global__ void hist_kernel(const int* __restrict__ dst, int* __restrict__ cnt) {
    int e = blockIdx.x * blockDim.x + threadIdx.x;
    if (e < EE) atomicAdd(&cnt[dst[e]], 1);
}

__global__ void __launch_bounds__(1024)
scan_fused_kernel(const int* __restrict__ cnt,
                  int* __restrict__ rowptr, int* __restrict__ cursor) {
    __shared__ int s_warp[32];
    __shared__ int s_off;
    const int t = threadIdx.x;
    const int lane = t & 31;
    const int wid = t >> 5;
    if (t == 0) s_off = 0;
    __syncthreads();

    for (int base = 0; base < NN; base += 1024) {
        int i = base + t;
        int v = (i < NN) ? cnt[i] : 0;
        int ws = v;
#pragma unroll
        for (int o = 1; o < 32; o <<= 1) {
            int u = __shfl_up_sync(0xffffffffu, ws, o);
            if (lane >= o) ws += u;
        }
        if (lane == 31) s_warp[wid] = ws;
        __syncthreads();
        if (wid == 0) {
            int wv = s_warp[lane];
            int wscan = wv;
#pragma unroll
            for (int o = 1; o < 32; o <<= 1) {
                int u = __shfl_up_sync(0xffffffffu, wscan, o);
                if (lane >= o) wscan += u;
            }
            s_warp[lane] = wscan;
        }
        __syncthreads();
        int ex = ws - v + (wid > 0 ? s_warp[wid - 1] : 0) + s_off;
        if (i < NN) { rowptr[i] = ex; cursor[i] = ex; }
        __syncthreads();
        if (t == 0) s_off += s_warp[31];
        __syncthreads();
    }
    if (t == 0) rowptr[NN] = EE;
}

__global__ void csr_fill_kernel(const int* __restrict__ src,
                                const int* __restrict__ dst,
                                int* __restrict__ cursor,
                                int* __restrict__ adj) {
    int e = blockIdx.x * blockDim.x + threadIdx.x;
    if (e >= EE) return;
    int pos = atomicAdd(&cursor[dst[e]], 1);
    adj[pos] = src[e];
}

// =================== attention projection prep (warp-parallel) =============
__global__ void __launch_bounds__(256)
prep_wel_kernel(const float* __restrict__ W0,
                const float* __restrict__ al0,
                const float* __restrict__ ar0,
                const float* __restrict__ W1,
                const float* __restrict__ al1,
                const float* __restrict__ ar1,
                float* __restrict__ wel0,
                float* __restrict__ wel1) {
    const int warp = threadIdx.x >> 5;
    const int lane = threadIdx.x & 31;
    if (blockIdx.x < 32) {
        const int k = blockIdx.x * 8 + warp;
        const float* wrow = W0 + (size_t)k * 256;
#pragma unroll
        for (int j = 0; j < 4; j++) {
            float w0v = wrow[j * 64 + lane];
            float w1v = wrow[j * 64 + 32 + lane];
            float sl = w0v * al0[j * 64 + lane] + w1v * al0[j * 64 + 32 + lane];
            float sr = w0v * ar0[j * 64 + lane] + w1v * ar0[j * 64 + 32 + lane];
#pragma unroll
            for (int o = 16; o; o >>= 1) {
                sl += __shfl_xor_sync(0xffffffffu, sl, o);
                sr += __shfl_xor_sync(0xffffffffu, sr, o);
            }
            if (lane == 0) {
                wel0[j * 256 + k]       = sl;
                wel0[(4 + j) * 256 + k] = sr;
            }
        }
    } else {
        const int k = (blockIdx.x - 32) * 8 + warp;
        const float* wrow = W1 + (size_t)k * 256;
        float sl = 0.f, sr = 0.f;
#pragma unroll
        for (int it = 0; it < 8; it++) {
            float wv = wrow[it * 32 + lane];
            sl += wv * al1[it * 32 + lane];
            sr += wv * ar1[it * 32 + lane];
        }
#pragma unroll
        for (int o = 16; o; o >>= 1) {
            sl += __shfl_xor_sync(0xffffffffu, sl, o);
            sr += __shfl_xor_sync(0xffffffffu, sr, o);
        }
        if (lane == 0) {
            wel1[k]       = sl;
            wel1[256 + k] = sr;
        }
    }
}

__global__ void __launch_bounds__(256)
eler0_kernel(const float* __restrict__ X, const float* __restrict__ WelT,
             float* __restrict__ el, float* __restrict__ er) {
    __shared__ float w[8][256];
    int tid = threadIdx.x;
    for (int i = tid; i < 8 * 256; i += 256) ((float*)w)[i] = WelT[i];
    __syncthreads();
    int n = blockIdx.x * 8 + (tid >> 5);
    int lane = tid & 31;
    if (n >= NN) return;
    const float* xr = X + (size_t)n * 256;
    float acc[8];
#pragma unroll
    for (int j = 0; j < 8; j++) acc[j] = 0.f;
#pragma unroll
    for (int it = 0; it < 8; it++) {
        float xv = xr[lane + it * 32];
#pragma unroll
        for (int j = 0; j < 8; j++) acc[j] += xv * w[j][lane + it * 32];
    }
#pragma unroll
    for (int o = 16; o; o >>= 1)
#pragma unroll
        for (int j = 0; j < 8; j++) acc[j] += __shfl_xor_sync(0xffffffffu, acc[j], o);
    if (lane == 0) {
#pragma unroll
        for (int j = 0; j < 4; j++) el[n * 4 + j] = acc[j];
#pragma unroll
        for (int j = 0; j < 4; j++) er[n * 4 + j] = acc[4 + j];
    }
}

// =================== GEMM helpers ===========================================
__device__ __forceinline__ uint32_t packbf(float f0, float f1) {
    uint32_t r;
    asm("cvt.rn.bf16x2.f32 %0, %1, %2;" : "=r"(r) : "f"(f1), "f"(f0));
    return r;
}
__device__ __forceinline__ uint32_t packh(float f0, float f1) {
    uint32_t r;
    asm("cvt.rn.f16x2.f32 %0, %1, %2;" : "=r"(r) : "f"(f1), "f"(f0));
    return r;
}
__device__ __forceinline__ void bfsplit2(float f0, float f1,
                                         uint32_t& h, uint32_t& l) {
    h = packbf(f0, f1);
    float h0 = __uint_as_float(h << 16);
    float h1 = __uint_as_float(h & 0xffff0000u);
    l = packbf(f0 - h0, f1 - h1);
}

#define MMA_BF16(d, a, b) \
    asm volatile("mma.sync.aligned.m16n8k16.row.col.f32.bf16.bf16.f32 " \
                 "{%0,%1,%2,%3}, {%4,%5,%6,%7}, {%8,%9}, {%0,%1,%2,%3};" \
                 : "+f"(d[0]), "+f"(d[1]), "+f"(d[2]), "+f"(d[3]) \
                 : "r"(a[0]), "r"(a[1]), "r"(a[2]), "r"(a[3]), \
                   "r"(b[0]), "r"(b[1]))

#define MMA_F16(d, a, b) \
    asm volatile("mma.sync.aligned.m16n8k16.row.col.f32.f16.f16.f32 " \
                 "{%0,%1,%2,%3}, {%4,%5,%6,%7}, {%8,%9}, {%0,%1,%2,%3};" \
                 : "+f"(d[0]), "+f"(d[1]), "+f"(d[2]), "+f"(d[3]) \
                 : "r"(a[0]), "r"(a[1]), "r"(a[2]), "r"(a[3]), \
                   "r"(b[0]), "r"(b[1]))

// ---- fp16 single-term GEMM: C16 = fp16(A @ B). AHALF: A is fp16. ----------
template<int BM, int BN, int WARPS_M, int WARPS_N, bool AHALF>
__global__ void __launch_bounds__(256, 2)
gemm_f16(const void* __restrict__ Av, const float* __restrict__ B,
         __half* __restrict__ C16, int Nr, int K, int M) {
    constexpr int WM = BM / WARPS_M;
    constexpr int WN = BN / WARPS_N;
    constexpr int MF = WM / 16;
    constexpr int NF = WN / 8;
    constexpr int LD = 136;
    constexpr int STG = 8 * LD;
    constexpr int BQ = BN / 4;

    __shared__ uint32_t Ah[2][STG];
    __shared__ uint32_t Bh[2][STG];

    const float*  Af  = (const float*)Av;
    const __half* A16 = (const __half*)Av;

    const int tid  = threadIdx.x;
    const int lane = tid & 31;
    const int warp = tid >> 5;
    const int wm = warp / WARPS_N;
    const int wn = warp % WARPS_N;
    const int rowBase = blockIdx.y * BM;
    const int colBase = blockIdx.x * BN;
    const int g  = lane >> 2;
    const int tg = lane & 3;

    float acc[MF][NF][4];
#pragma unroll
    for (int i = 0; i < MF; i++)
#pragma unroll
        for (int j = 0; j < NF; j++)
#pragma unroll
            for (int k = 0; k < 4; k++) acc[i][j][k] = 0.0f;

    float4 ra[2];
    uint2  ra16[2];
    float4 rb0, rb1;
    const int am[2]  = { (tid) >> 2, (tid + 256) >> 2 };
    const int akq = (tid & 3) << 2;
    const bool bact = tid < 8 * BQ;
    const int bkp = bact ? tid / BQ : 0;
    const int bnq = bact ? (tid % BQ) << 2 : 0;

    auto ldg_tile = [&](int k0) {
#pragma unroll
        for (int i = 0; i < 2; i++) {
            int gr = rowBase + am[i];
            int grc = (gr < Nr) ? gr : (Nr - 1);
            if (AHALF)
                ra16[i] = *(const uint2*)(A16 + (size_t)grc * K + k0 + akq);
            else
                ra[i] = *(const float4*)(Af + (size_t)grc * K + k0 + akq);
        }
        if (bact) {
            rb0 = *(const float4*)(B + (size_t)(k0 + 2 * bkp)     * M + colBase + bnq);
            rb1 = *(const float4*)(B + (size_t)(k0 + 2 * bkp + 1) * M + colBase + bnq);
        }
    };

    auto sts_tile = [&](int s) {
#pragma unroll
        for (int i = 0; i < 2; i++) {
            int kp0 = (akq >> 1);
            if (AHALF) {
                Ah[s][kp0 * LD + am[i]]       = ra16[i].x;
                Ah[s][(kp0 + 1) * LD + am[i]] = ra16[i].y;
            } else {
                Ah[s][kp0 * LD + am[i]]       = packh(ra[i].x, ra[i].y);
                Ah[s][(kp0 + 1) * LD + am[i]] = packh(ra[i].z, ra[i].w);
            }
        }
        if (bact) {
            const float* p0 = &rb0.x;
            const float* p1 = &rb1.x;
            uint32_t hh[4];
#pragma unroll
            for (int j = 0; j < 4; j++) hh[j] = packh(p0[j], p1[j]);
            *(uint4*)&Bh[s][bkp * LD + bnq] = make_uint4(hh[0], hh[1], hh[2], hh[3]);
        }
    };

    const int NIT = K / 16;
    ldg_tile(0);

    for (int it = 0; it < NIT; it++) {
        const int s = it & 1;
        sts_tile(s);
        __syncthreads();
        if (it + 1 < NIT) ldg_tile((it + 1) * 16);

        uint32_t bh[NF][2];
#pragma unroll
        for (int nf = 0; nf < NF; nf++) {
            int c0 = wn * WN + nf * 8 + g;
            bh[nf][0] = Bh[s][tg * LD + c0];
            bh[nf][1] = Bh[s][(tg + 4) * LD + c0];
        }
#pragma unroll
        for (int mf = 0; mf < MF; mf++) {
            int r0 = wm * WM + mf * 16 + g;
            uint32_t ah[4];
            ah[0] = Ah[s][tg * LD + r0];
            ah[1] = Ah[s][tg * LD + r0 + 8];
            ah[2] = Ah[s][(tg + 4) * LD + r0];
            ah[3] = Ah[s][(tg + 4) * LD + r0 + 8];
#pragma unroll
            for (int nf = 0; nf < NF; nf++)
                MMA_F16(acc[mf][nf], ah, bh[nf]);
        }
    }

#pragma unroll
    for (int mf = 0; mf < MF; mf++) {
#pragma unroll
        for (int nf = 0; nf < NF; nf++) {
            int row = rowBase + wm * WM + mf * 16 + g;
            int col = colBase + wn * WN + nf * 8 + tg * 2;
            if (row < Nr)
                *(uint32_t*)(C16 + (size_t)row * M + col) =
                    packh(acc[mf][nf][0], acc[mf][nf][1]);
            if (row + 8 < Nr)
                *(uint32_t*)(C16 + (size_t)(row + 8) * M + col) =
                    packh(acc[mf][nf][2], acc[mf][nf][3]);
        }
    }
}

// ---- bf16 3-term GEMM (classifier): C[Nr,M] = A@B + bias -------------------
template<int BM, int BN, int WARPS_M, int WARPS_N>
__global__ void __launch_bounds__(256, 2)
gemm_bf16x3(const float* __restrict__ A, const float* __restrict__ B,
            float* __restrict__ C, int Nr, int K, int M,
            const float* __restrict__ bias) {
    constexpr int WM = BM / WARPS_M;
    constexpr int WN = BN / WARPS_N;
    constexpr int MF = WM / 16;
    constexpr int NF = WN / 8;
    constexpr int LD = 136;
    constexpr int STG = 8 * LD;
    constexpr int BQ = BN / 4;

    __shared__ uint32_t Ah[2][STG], Al[2][STG];
    __shared__ uint32_t Bh[2][STG], Bl[2][STG];

    const int tid  = threadIdx.x;
    const int lane = tid & 31;
    const int warp = tid >> 5;
    const int wm = warp / WARPS_N;
    const int wn = warp % WARPS_N;
    const int rowBase = blockIdx.y * BM;
    const int colBase = blockIdx.x * BN;
    const int g  = lane >> 2;
    const int tg = lane & 3;

    float acc[MF][NF][4];
#pragma unroll
    for (int i = 0; i < MF; i++)
#pragma unroll
        for (int j = 0; j < NF; j++)
#pragma unroll
            for (int k = 0; k < 4; k++) acc[i][j][k] = 0.0f;

    float4 ra[2];
    float4 rb0, rb1;
    const int am[2]  = { (tid) >> 2, (tid + 256) >> 2 };
    const int akq = (tid & 3) << 2;
    const bool bact = tid < 8 * BQ;
    const int bkp = bact ? tid / BQ : 0;
    const int bnq = bact ? (tid % BQ) << 2 : 0;

    auto ldg_tile = [&](int k0) {
#pragma unroll
        for (int i = 0; i < 2; i++) {
            int gr = rowBase + am[i];
            int grc = (gr < Nr) ? gr : (Nr - 1);
            ra[i] = *(const float4*)(A + (size_t)grc * K + k0 + akq);
        }
        if (bact) {
            rb0 = *(const float4*)(B + (size_t)(k0 + 2 * bkp)     * M + colBase + bnq);
            rb1 = *(const float4*)(B + (size_t)(k0 + 2 * bkp + 1) * M + colBase + bnq);
        }
    };

    auto sts_tile = [&](int s) {
#pragma unroll
        for (int i = 0; i < 2; i++) {
            int kp0 = (akq >> 1);
            uint32_t h, l;
            bfsplit2(ra[i].x, ra[i].y, h, l);
            Ah[s][kp0 * LD + am[i]] = h;
            Al[s][kp0 * LD + am[i]] = l;
            bfsplit2(ra[i].z, ra[i].w, h, l);
            Ah[s][(kp0 + 1) * LD + am[i]] = h;
            Al[s][(kp0 + 1) * LD + am[i]] = l;
        }
        if (bact) {
            const float* p0 = &rb0.x;
            const float* p1 = &rb1.x;
            uint32_t hh[4], ll[4];
#pragma unroll
            for (int j = 0; j < 4; j++) bfsplit2(p0[j], p1[j], hh[j], ll[j]);
            *(uint4*)&Bh[s][bkp * LD + bnq] = make_uint4(hh[0], hh[1], hh[2], hh[3]);
            *(uint4*)&Bl[s][bkp * LD + bnq] = make_uint4(ll[0], ll[1], ll[2], ll[3]);
        }
    };

    const int NIT = K / 16;
    ldg_tile(0);

    for (int it = 0; it < NIT; it++) {
        const int s = it & 1;
        sts_tile(s);
        __syncthreads();
        if (it + 1 < NIT) ldg_tile((it + 1) * 16);

        uint32_t bh[NF][2], bl[NF][2];
#pragma unroll
        for (int nf = 0; nf < NF; nf++) {
            int c0 = wn * WN + nf * 8 + g;
            bh[nf][0] = Bh[s][tg * LD + c0];
            bh[nf][1] = Bh[s][(tg + 4) * LD + c0];
            bl[nf][0] = Bl[s][tg * LD + c0];
            bl[nf][1] = Bl[s][(tg + 4) * LD + c0];
        }
#pragma unroll
        for (int mf = 0; mf < MF; mf++) {
            int r0 = wm * WM + mf * 16 + g;
            uint32_t ah[4], al[4];
            ah[0] = Ah[s][tg * LD + r0];
            ah[1] = Ah[s][tg * LD + r0 + 8];
            ah[2] = Ah[s][(tg + 4) * LD + r0];
            ah[3] = Ah[s][(tg + 4) * LD + r0 + 8];
            al[0] = Al[s][tg * LD + r0];
            al[1] = Al[s][tg * LD + r0 + 8];
            al[2] = Al[s][(tg + 4) * LD + r0];
            al[3] = Al[s][(tg + 4) * LD + r0 + 8];
#pragma unroll
            for (int nf = 0; nf < NF; nf++) {
                MMA_BF16(acc[mf][nf], al, bh[nf]);
                MMA_BF16(acc[mf][nf], ah, bl[nf]);
                MMA_BF16(acc[mf][nf], ah, bh[nf]);
            }
        }
    }

#pragma unroll
    for (int mf = 0; mf < MF; mf++) {
#pragma unroll
        for (int nf = 0; nf < NF; nf++) {
            int row = rowBase + wm * WM + mf * 16 + g;
            int col = colBase + wn * WN + nf * 8 + tg * 2;
            float b0v = bias ? bias[col]     : 0.0f;
            float b1v = bias ? bias[col + 1] : 0.0f;
            if (row < Nr) {
                float2 o = make_float2(acc[mf][nf][0] + b0v, acc[mf][nf][1] + b1v);
                *(float2*)(C + (size_t)row * M + col) = o;
            }
            if (row + 8 < Nr) {
                float2 o = make_float2(acc[mf][nf][2] + b0v, acc[mf][nf][3] + b1v);
                *(float2*)(C + (size_t)(row + 8) * M + col) = o;
            }
        }
    }
}

// =================== aggregation: one WARP per dst node =====================
__device__ __forceinline__ void acc8(float* acc, float a, uint4 r) {
    float2 f0 = __half22float2(*reinterpret_cast<const half2*>(&r.x));
    float2 f1 = __half22float2(*reinterpret_cast<const half2*>(&r.y));
    float2 f2 = __half22float2(*reinterpret_cast<const half2*>(&r.z));
    float2 f3 = __half22float2(*reinterpret_cast<const half2*>(&r.w));
    acc[0] += a * f0.x; acc[1] += a * f0.y;
    acc[2] += a * f1.x; acc[3] += a * f1.y;
    acc[4] += a * f2.x; acc[5] += a * f2.y;
    acc[6] += a * f3.x; acc[7] += a * f3.y;
}

__global__ void __launch_bounds__(256)
agg0_kernel(const int* __restrict__ rowptr, const int* __restrict__ adj,
            const float* __restrict__ el, const float* __restrict__ er,
            const __half* __restrict__ ft, const float* __restrict__ b0,
            const float* __restrict__ wel1,
            __half* __restrict__ h116,
            float* __restrict__ el1, float* __restrict__ er1,
            int nbase, int nend) {
    const int w = threadIdx.x >> 5;
    const int lane = threadIdx.x & 31;
    const int d = nbase + blockIdx.x * 8 + w;
    if (d >= nend) return;
    const int h = lane >> 3;
    const int start = rowptr[d], end = rowptr[d + 1];

    __shared__ float s_num[8][32][4];

    float4 erd = *(const float4*)(er + (size_t)d * 4);
    float lsum[4] = {0.f, 0.f, 0.f, 0.f};
    float acc[8] = {0.f, 0.f, 0.f, 0.f, 0.f, 0.f, 0.f, 0.f};

    int c = start;
    int n = min(32, end - c);
    int sidx = 0;
    float4 e4 = make_float4(0.f, 0.f, 0.f, 0.f);
    if (c < end && lane < n) {
        sidx = adj[c + lane];
        e4 = *(const float4*)(el + (size_t)sidx * 4);
    }

    while (c < end) {
        if (lane < n) {
            float v[4];
            v[0] = e4.x + erd.x; v[1] = e4.y + erd.y;
            v[2] = e4.z + erd.z; v[3] = e4.w + erd.w;
#pragma unroll
            for (int k = 0; k < 4; k++) {
                float vv = (v[k] >= 0.f) ? v[k] : NEG * v[k];
                float nu = __expf(vv);
                s_num[w][lane][k] = nu;
                lsum[k] += nu;
            }
        }
        __syncwarp();

        int c2 = c + 32;
        int n2 = min(32, end - c2);
        int sidx2 = 0;
        float4 e42 = make_float4(0.f, 0.f, 0.f, 0.f);
        if (c2 < end && lane < n2) {
            sidx2 = adj[c2 + lane];
            e42 = *(const float4*)(el + (size_t)sidx2 * 4);
        }

        int j = 0;
        for (; j + 4 <= n; j += 4) {
            int s0 = __shfl_sync(0xffffffffu, sidx, j);
            int s1 = __shfl_sync(0xffffffffu, sidx, j + 1);
            int s2 = __shfl_sync(0xffffffffu, sidx, j + 2);
            int s3 = __shfl_sync(0xffffffffu, sidx, j + 3);
            float a0 = s_num[w][j][h],     a1 = s_num[w][j + 1][h];
            float a2 = s_num[w][j + 2][h], a3 = s_num[w][j + 3][h];
            uint4 r0 = *(const uint4*)(ft + (size_t)s0 * 256 + lane * 8);
            uint4 r1 = *(const uint4*)(ft + (size_t)s1 * 256 + lane * 8);
            uint4 r2 = *(const uint4*)(ft + (size_t)s2 * 256 + lane * 8);
            uint4 r3 = *(const uint4*)(ft + (size_t)s3 * 256 + lane * 8);
            acc8(acc, a0, r0); acc8(acc, a1, r1);
            acc8(acc, a2, r2); acc8(acc, a3, r3);
        }
        for (; j < n; j++) {
            int s0 = __shfl_sync(0xffffffffu, sidx, j);
            float a0 = s_num[w][j][h];
            uint4 r0 = *(const uint4*)(ft + (size_t)s0 * 256 + lane * 8);
            acc8(acc, a0, r0);
        }
        __syncwarp();
        sidx = sidx2; e4 = e42; n = n2; c = c2;
    }

#pragma unroll
    for (int off = 16; off; off >>= 1)
#pragma unroll
        for (int k = 0; k < 4; k++)
            lsum[k] += __shfl_xor_sync(0xffffffffu, lsum[k], off);
    float tot = lsum[h];
    float inv = (tot > 0.f) ? (1.0f / tot) : 0.0f;

    float o[8];
    float sl = 0.f, sr = 0.f;
    const float* bb = b0 + lane * 8;
    const float* wl = wel1 + lane * 8;
    const float* wr = wel1 + 256 + lane * 8;
#pragma unroll
    for (int i = 0; i < 8; i++) {
        float v = acc[i] * inv + bb[i];
        v = (v > 0.f) ? v : expm1f(v);
        o[i] = v;
        sl += v * wl[i];
        sr += v * wr[i];
    }
    uint4 hp;
    hp.x = packh(o[0], o[1]); hp.y = packh(o[2], o[3]);
    hp.z = packh(o[4], o[5]); hp.w = packh(o[6], o[7]);
    *(uint4*)(h116 + (size_t)d * 256 + lane * 8) = hp;
#pragma unroll
    for (int off = 16; off; off >>= 1) {
        sl += __shfl_xor_sync(0xffffffffu, sl, off);
        sr += __shfl_xor_sync(0xffffffffu, sr, off);
    }
    if (lane == 0) { el1[d] = sl; er1[d] = sr; }
}

__global__ void __launch_bounds__(256)
agg1_kernel(const int* __restrict__ rowptr, const int* __restrict__ adj,
            const float* __restrict__ el, const float* __restrict__ er,
            const __half* __restrict__ ft, const __half* __restrict__ h116,
            const float* __restrict__ b1, float* __restrict__ hout,
            int nbase, int nend) {
    const int w = threadIdx.x >> 5;
    const int lane = threadIdx.x & 31;
    const int d = nbase + blockIdx.x * 8 + w;
    if (d >= nend) return;
    const int start = rowptr[d], end = rowptr[d + 1];

    float erd = er[d];
    float lsum = 0.f;
    float acc[8] = {0.f, 0.f, 0.f, 0.f, 0.f, 0.f, 0.f, 0.f};

    int c = start;
    int n = min(32, end - c);
    int sidx = 0;
    float elv = 0.f;
    if (c < end && lane < n) {
        sidx = adj[c + lane];
        elv = el[sidx];
    }

    while (c < end) {
        float nu = 0.f;
        if (lane < n) {
            float v = elv + erd;
            v = (v >= 0.f) ? v : NEG * v;
            nu = __expf(v);
            lsum += nu;
        }

        int c2 = c + 32;
        int n2 = min(32, end - c2);
        int sidx2 = 0;
        float elv2 = 0.f;
        if (c2 < end && lane < n2) {
            sidx2 = adj[c2 + lane];
            elv2 = el[sidx2];
        }

        int j = 0;
        for (; j + 4 <= n; j += 4) {
            int s0 = __shfl_sync(0xffffffffu, sidx, j);
            int s1 = __shfl_sync(0xffffffffu, sidx, j + 1);
            int s2 = __shfl_sync(0xffffffffu, sidx, j + 2);
            int s3 = __shfl_sync(0xffffffffu, sidx, j + 3);
            float a0 = __shfl_sync(0xffffffffu, nu, j);
            float a1 = __shfl_sync(0xffffffffu, nu, j + 1);
            float a2 = __shfl_sync(0xffffffffu, nu, j + 2);
            float a3 = __shfl_sync(0xffffffffu, nu, j + 3);
            uint4 r0 = *(const uint4*)(ft + (size_t)s0 * 256 + lane * 8);
            uint4 r1 = *(const uint4*)(ft + (size_t)s1 * 256 + lane * 8);
            uint4 r2 = *(const uint4*)(ft + (size_t)s2 * 256 + lane * 8);
            uint4 r3 = *(const uint4*)(ft + (size_t)s3 * 256 + lane * 8);
            acc8(acc, a0, r0); acc8(acc, a1, r1);
            acc8(acc, a2, r2); acc8(acc, a3, r3);
        }
        for (; j < n; j++) {
            int s0 = __shfl_sync(0xffffffffu, sidx, j);
            float a0 = __shfl_sync(0xffffffffu, nu, j);
            uint4 r0 = *(const uint4*)(ft + (size_t)s0 * 256 + lane * 8);
            acc8(acc, a0, r0);
        }
        sidx = sidx2; elv = elv2; n = n2; c = c2;
    }

#pragma unroll
    for (int off = 16; off; off >>= 1)
        lsum += __shfl_xor_sync(0xffffffffu, lsum, off);
    float inv = (lsum > 0.f) ? (1.0f / lsum) : 0.0f;

    uint4 hr = *(const uint4*)(h116 + (size_t)d * 256 + lane * 8);
    float2 h0 = __half22float2(*reinterpret_cast<const half2*>(&hr.x));
    float2 h1p = __half22float2(*reinterpret_cast<const half2*>(&hr.y));
    float2 h2 = __half22float2(*reinterpret_cast<const half2*>(&hr.z));
    float2 h3 = __half22float2(*reinterpret_cast<const half2*>(&hr.w));
    float4 bb0 = *(const float4*)(b1 + lane * 8);
    float4 bb1 = *(const float4*)(b1 + lane * 8 + 4);
    float4 o0, o1;
    o0.x = acc[0] * inv + h0.x  + bb0.x;
    o0.y = acc[1] * inv + h0.y  + bb0.y;
    o0.z = acc[2] * inv + h1p.x + bb0.z;
    o0.w = acc[3] * inv + h1p.y + bb0.w;
    o1.x = acc[4] * inv + h2.x  + bb1.x;
    o1.y = acc[5] * inv + h2.y  + bb1.y;
    o1.z = acc[6] * inv + h3.x  + bb1.z;
    o1.w = acc[7] * inv + h3.y  + bb1.w;
    *(float4*)(hout + (size_t)d * 256 + lane * 8)     = o0;
    *(float4*)(hout + (size_t)d * 256 + lane * 8 + 4) = o1;
}

// =================== launch ==================================================
extern "C" void kernel_launch(void* const* d_in, const int* in_sizes, int n_in,
                              void* d_out, int out_size) {
    const float* x   = (const float*)d_in[0];
    const int*   src = (const int*)  d_in[1];
    const int*   dst = (const int*)  d_in[2];
    const float* W0  = (const float*)d_in[3];
    const float* al0 = (const float*)d_in[4];
    const float* ar0 = (const float*)d_in[5];
    const float* b0  = (const float*)d_in[6];
    const float* W1  = (const float*)d_in[7];
    const float* al1 = (const float*)d_in[8];
    const float* ar1 = (const float*)d_in[9];
    const float* b1  = (const float*)d_in[10];
    const float* Wl  = (const float*)d_in[11];
    const float* bl  = (const float*)d_in[12];

    float* out    = (float*)d_out;
    float* logits = out;
    float* hout   = out + (size_t)NN * NCLS;

    __half *ft16, *ft16b, *h116;
    float *el, *er, *el1, *er1, *wel0, *wel1;
    int *cnt, *rowptr, *adj;
    cudaGetSymbolAddress((void**)&ft16,   g_ft16);
    cudaGetSymbolAddress((void**)&ft16b,  g_ft16b);
    cudaGetSymbolAddress((void**)&h116,   g_h116);
    cudaGetSymbolAddress((void**)&el,     g_el);
    cudaGetSymbolAddress((void**)&er,     g_er);
    cudaGetSymbolAddress((void**)&el1,    g_el1);
    cudaGetSymbolAddress((void**)&er1,    g_er1);
    cudaGetSymbolAddress((void**)&wel0,   g_wel0);
    cudaGetSymbolAddress((void**)&wel1,   g_wel1);
    cudaGetSymbolAddress((void**)&cnt,    g_cnt);
    cudaGetSymbolAddress((void**)&rowptr, g_rowptr);
    cudaGetSymbolAddress((void**)&adj,    g_adj);

    static cudaStream_t s1 = nullptr, s2 = nullptr;
    static cudaEvent_t ev_fork = nullptr, ev_csr = nullptr, ev_el0 = nullptr,
                       ev_g0 = nullptr, ev_pa_m = nullptr, ev_pa_s = nullptr,
                       ev_end = nullptr;
    if (s1 == nullptr) {
        cudaStreamCreateWithFlags(&s1, cudaStreamNonBlocking);
        cudaStreamCreateWithFlags(&s2, cudaStreamNonBlocking);
        cudaEventCreateWithFlags(&ev_fork, cudaEventDisableTiming);
        cudaEventCreateWithFlags(&ev_csr,  cudaEventDisableTiming);
        cudaEventCreateWithFlags(&ev_el0,  cudaEventDisableTiming);
        cudaEventCreateWithFlags(&ev_g0,   cudaEventDisableTiming);
        cudaEventCreateWithFlags(&ev_pa_m, cudaEventDisableTiming);
        cudaEventCreateWithFlags(&ev_pa_s, cudaEventDisableTiming);
        cudaEventCreateWithFlags(&ev_end,  cudaEventDisableTiming);
    }

    const int T = 256;
    const int cs[5] = {0, NCHUNK, 2 * NCHUNK, 3 * NCHUNK, NN};

    cudaEventRecord(ev_fork, 0);

    // ---- s1: CSR build (fused scan) ----
    cudaStreamWaitEvent(s1, ev_fork, 0);
    cudaMemsetAsync(cnt, 0, NN * sizeof(int), s1);
    hist_kernel<<<(EE + T - 1) / T, T, 0, s1>>>(dst, cnt);
    scan_fused_kernel<<<1, 1024, 0, s1>>>(cnt, rowptr, cnt);
    csr_fill_kernel<<<(EE + T - 1) / T, T, 0, s1>>>(src, dst, cnt, adj);
    cudaEventRecord(ev_csr, s1);

    // ---- s2: attention projections ----
    cudaStreamWaitEvent(s2, ev_fork, 0);
    prep_wel_kernel<<<64, 256, 0, s2>>>(W0, al0, ar0, W1, al1, ar1, wel0, wel1);
    eler0_kernel<<<(NN + 7) / 8, 256, 0, s2>>>(x, wel0, el, er);
    cudaEventRecord(ev_el0, s2);

    // ---- main: layer 0 projection ----
    {
        dim3 grid(2, (NN + 127) / 128);
        gemm_f16<128, 128, 2, 4, false><<<grid, 256>>>(x, W0, ft16, NN, IND, 256);
    }
    cudaEventRecord(ev_g0, 0);

    // ---- phase A: agg0(Ci) -> GEMM1(Ci), C0/C2 on main, C1/C3 on s2 ----
    cudaStreamWaitEvent(0, ev_csr, 0);
    cudaStreamWaitEvent(0, ev_el0, 0);
    cudaStreamWaitEvent(s2, ev_g0, 0);
    cudaStreamWaitEvent(s2, ev_csr, 0);

    for (int i = 0; i < 4; i++) {
        cudaStream_t st = (i & 1) ? s2 : 0;
        int s = cs[i], e = cs[i + 1], nc = e - s;
        agg0_kernel<<<(nc + 7) / 8, 256, 0, st>>>(rowptr, adj, el, er, ft16, b0,
                                                  wel1, h116, el1, er1, s, e);
        dim3 grid(2, (nc + 127) / 128);
        gemm_f16<128, 128, 2, 4, true><<<grid, 256, 0, st>>>(
            h116 + (size_t)s * 256, W1, ft16b + (size_t)s * 256, nc, 256, 256);
    }
    cudaEventRecord(ev_pa_m, 0);
    cudaEventRecord(ev_pa_s, s2);
    cudaStreamWaitEvent(0, ev_pa_s, 0);
    cudaStreamWaitEvent(s2, ev_pa_m, 0);

    // ---- phase B: agg1(Ci) -> cls(Ci), C0/C2 on main, C1/C3 on s2 ----
    for (int i = 0; i < 4; i++) {
        cudaStream_t st = (i & 1) ? s2 : 0;
        int s = cs[i], e = cs[i + 1], nc = e - s;
        agg1_kernel<<<(nc + 7) / 8, 256, 0, st>>>(rowptr, adj, el1, er1, ft16b,
                                                  h116, b1, hout, s, e);
        dim3 grid(1, (nc + 127) / 128);
        gemm_bf16x3<128, 64, 4, 2><<<grid, 256, 0, st>>>(
            hout + (size_t)s * 256, Wl, logits + (size_t)s * 64, nc, OUT1, NCLS, bl);
    }
    cudaEventRecord(ev_end, s2);
    cudaStreamWaitEvent(0, ev_end, 0);
}

// round 16
// speedup vs baseline: 1.1094x; 1.0077x over previous
#include <cuda_runtime.h>
#include <cuda_fp16.h>
#include <math.h>
#include <stdint.h>

#define NN 50000
#define EE 800000
#define IND 256
#define HIDD 64
#define H0 4
#define OUT1 256
#define NCLS 64
#define NEG 0.2f
#define NCHUNK 12544   // pipeline chunk (98*128)

// ---------------- scratch (device globals; no allocation allowed) ----------
__device__ __half g_ft16[NN * 256];    // layer-0 projected features
__device__ __half g_ft16b[NN * 256];   // layer-1 projected features
__device__ __half g_h116[NN * 256];    // h1 in fp16
__device__ float  g_el[NN * H0];
__device__ float  g_er[NN * H0];
__device__ float  g_el1[NN];
__device__ float  g_er1[NN];
__device__ float  g_wel0[8 * 256];
__device__ float  g_wel1[2 * 256];
__device__ int    g_cnt[NN];
__device__ int    g_rowptr[NN + 1];
__device__ int    g_adj[EE];

// =================== CSR build ==============================================
__global__ void hist_kernel(const int* __restrict__ dst, int* __restrict__ cnt) {
    int e = blockIdx.x * blockDim.x + threadIdx.x;
    if (e < EE) atomicAdd(&cnt[dst[e]], 1);
}

__global__ void __launch_bounds__(1024)
scan_fused_kernel(const int* __restrict__ cnt,
                  int* __restrict__ rowptr, int* __restrict__ cursor) {
    __shared__ int s_warp[32];
    __shared__ int s_off;
    const int t = threadIdx.x;
    const int lane = t & 31;
    const int wid = t >> 5;
    if (t == 0) s_off = 0;
    __syncthreads();

    for (int base = 0; base < NN; base += 1024) {
        int i = base + t;
        int v = (i < NN) ? cnt[i] : 0;
        int ws = v;
#pragma unroll
        for (int o = 1; o < 32; o <<= 1) {
            int u = __shfl_up_sync(0xffffffffu, ws, o);
            if (lane >= o) ws += u;
        }
        if (lane == 31) s_warp[wid] = ws;
        __syncthreads();
        if (wid == 0) {
            int wv = s_warp[lane];
            int wscan = wv;
#pragma unroll
            for (int o = 1; o < 32; o <<= 1) {
                int u = __shfl_up_sync(0xffffffffu, wscan, o);
                if (lane >= o) wscan += u;
            }
            s_warp[lane] = wscan;
        }
        __syncthreads();
        int ex = ws - v + (wid > 0 ? s_warp[wid - 1] : 0) + s_off;
        if (i < NN) { rowptr[i] = ex; cursor[i] = ex; }
        __syncthreads();
        if (t == 0) s_off += s_warp[31];
        __syncthreads();
    }
    if (t == 0) rowptr[NN] = EE;
}

__global__ void csr_fill_kernel(const int* __restrict__ src,
                                const int* __restrict__ dst,
                                int* __restrict__ cursor,
                                int* __restrict__ adj) {
    int e = blockIdx.x * blockDim.x + threadIdx.x;
    if (e >= EE) return;
    int pos = atomicAdd(&cursor[dst[e]], 1);
    adj[pos] = src[e];
}

// =================== attention projection prep (warp-parallel) =============
__global__ void __launch_bounds__(256)
prep_wel_kernel(const float* __restrict__ W0,
                const float* __restrict__ al0,
                const float* __restrict__ ar0,
                const float* __restrict__ W1,
                const float* __restrict__ al1,
                const float* __restrict__ ar1,
                float* __restrict__ wel0,
                float* __restrict__ wel1) {
    const int warp = threadIdx.x >> 5;
    const int lane = threadIdx.x & 31;
    if (blockIdx.x < 32) {
        const int k = blockIdx.x * 8 + warp;
        const float* wrow = W0 + (size_t)k * 256;
#pragma unroll
        for (int j = 0; j < 4; j++) {
            float w0v = wrow[j * 64 + lane];
            float w1v = wrow[j * 64 + 32 + lane];
            float sl = w0v * al0[j * 64 + lane] + w1v * al0[j * 64 + 32 + lane];
            float sr = w0v * ar0[j * 64 + lane] + w1v * ar0[j * 64 + 32 + lane];
#pragma unroll
            for (int o = 16; o; o >>= 1) {
                sl += __shfl_xor_sync(0xffffffffu, sl, o);
                sr += __shfl_xor_sync(0xffffffffu, sr, o);
            }
            if (lane == 0) {
                wel0[j * 256 + k]       = sl;
                wel0[(4 + j) * 256 + k] = sr;
            }
        }
    } else {
        const int k = (blockIdx.x - 32) * 8 + warp;
        const float* wrow = W1 + (size_t)k * 256;
        float sl = 0.f, sr = 0.f;
#pragma unroll
        for (int it = 0; it < 8; it++) {
            float wv = wrow[it * 32 + lane];
            sl += wv * al1[it * 32 + lane];
            sr += wv * ar1[it * 32 + lane];
        }
#pragma unroll
        for (int o = 16; o; o >>= 1) {
            sl += __shfl_xor_sync(0xffffffffu, sl, o);
            sr += __shfl_xor_sync(0xffffffffu, sr, o);
        }
        if (lane == 0) {
            wel1[k]       = sl;
            wel1[256 + k] = sr;
        }
    }
}

__global__ void __launch_bounds__(256)
eler0_kernel(const float* __restrict__ X, const float* __restrict__ WelT,
             float* __restrict__ el, float* __restrict__ er) {
    __shared__ float w[8][256];
    int tid = threadIdx.x;
    for (int i = tid; i < 8 * 256; i += 256) ((float*)w)[i] = WelT[i];
    __syncthreads();
    int n = blockIdx.x * 8 + (tid >> 5);
    int lane = tid & 31;
    if (n >= NN) return;
    const float* xr = X + (size_t)n * 256;
    float acc[8];
#pragma unroll
    for (int j = 0; j < 8; j++) acc[j] = 0.f;
#pragma unroll
    for (int it = 0; it < 8; it++) {
        float xv = xr[lane + it * 32];
#pragma unroll
        for (int j = 0; j < 8; j++) acc[j] += xv * w[j][lane + it * 32];
    }
#pragma unroll
    for (int o = 16; o; o >>= 1)
#pragma unroll
        for (int j = 0; j < 8; j++) acc[j] += __shfl_xor_sync(0xffffffffu, acc[j], o);
    if (lane == 0) {
#pragma unroll
        for (int j = 0; j < 4; j++) el[n * 4 + j] = acc[j];
#pragma unroll
        for (int j = 0; j < 4; j++) er[n * 4 + j] = acc[4 + j];
    }
}

// =================== GEMM helpers ===========================================
__device__ __forceinline__ uint32_t packh(float f0, float f1) {
    uint32_t r;
    asm("cvt.rn.f16x2.f32 %0, %1, %2;" : "=r"(r) : "f"(f1), "f"(f0));
    return r;
}

#define MMA_F16(d, a, b) \
    asm volatile("mma.sync.aligned.m16n8k16.row.col.f32.f16.f16.f32 " \
                 "{%0,%1,%2,%3}, {%4,%5,%6,%7}, {%8,%9}, {%0,%1,%2,%3};" \
                 : "+f"(d[0]), "+f"(d[1]), "+f"(d[2]), "+f"(d[3]) \
                 : "r"(a[0]), "r"(a[1]), "r"(a[2]), "r"(a[3]), \
                   "r"(b[0]), "r"(b[1]))

// ---- fp16 single-term GEMM. AHALF: A fp16. OUT16: fp16 out (no bias),
//      else fp32 out + optional bias.
template<int BM, int BN, int WARPS_M, int WARPS_N, bool AHALF, bool OUT16>
__global__ void __launch_bounds__(256, 2)
gemm_f16(const void* __restrict__ Av, const float* __restrict__ B,
         void* __restrict__ Cv, int Nr, int K, int M,
         const float* __restrict__ bias) {
    constexpr int WM = BM / WARPS_M;
    constexpr int WN = BN / WARPS_N;
    constexpr int MF = WM / 16;
    constexpr int NF = WN / 8;
    constexpr int LD = 136;
    constexpr int STG = 8 * LD;
    constexpr int BQ = BN / 4;

    __shared__ uint32_t Ah[2][STG];
    __shared__ uint32_t Bh[2][STG];

    const float*  Af  = (const float*)Av;
    const __half* A16 = (const __half*)Av;

    const int tid  = threadIdx.x;
    const int lane = tid & 31;
    const int warp = tid >> 5;
    const int wm = warp / WARPS_N;
    const int wn = warp % WARPS_N;
    const int rowBase = blockIdx.y * BM;
    const int colBase = blockIdx.x * BN;
    const int g  = lane >> 2;
    const int tg = lane & 3;

    float acc[MF][NF][4];
#pragma unroll
    for (int i = 0; i < MF; i++)
#pragma unroll
        for (int j = 0; j < NF; j++)
#pragma unroll
            for (int k = 0; k < 4; k++) acc[i][j][k] = 0.0f;

    float4 ra[2];
    uint2  ra16[2];
    float4 rb0, rb1;
    const int am[2]  = { (tid) >> 2, (tid + 256) >> 2 };
    const int akq = (tid & 3) << 2;
    const bool bact = tid < 8 * BQ;
    const int bkp = bact ? tid / BQ : 0;
    const int bnq = bact ? (tid % BQ) << 2 : 0;

    auto ldg_tile = [&](int k0) {
#pragma unroll
        for (int i = 0; i < 2; i++) {
            int gr = rowBase + am[i];
            int grc = (gr < Nr) ? gr : (Nr - 1);
            if (AHALF)
                ra16[i] = *(const uint2*)(A16 + (size_t)grc * K + k0 + akq);
            else
                ra[i] = *(const float4*)(Af + (size_t)grc * K + k0 + akq);
        }
        if (bact) {
            rb0 = *(const float4*)(B + (size_t)(k0 + 2 * bkp)     * M + colBase + bnq);
            rb1 = *(const float4*)(B + (size_t)(k0 + 2 * bkp + 1) * M + colBase + bnq);
        }
    };

    auto sts_tile = [&](int s) {
#pragma unroll
        for (int i = 0; i < 2; i++) {
            int kp0 = (akq >> 1);
            if (AHALF) {
                Ah[s][kp0 * LD + am[i]]       = ra16[i].x;
                Ah[s][(kp0 + 1) * LD + am[i]] = ra16[i].y;
            } else {
                Ah[s][kp0 * LD + am[i]]       = packh(ra[i].x, ra[i].y);
                Ah[s][(kp0 + 1) * LD + am[i]] = packh(ra[i].z, ra[i].w);
            }
        }
        if (bact) {
            const float* p0 = &rb0.x;
            const float* p1 = &rb1.x;
            uint32_t hh[4];
#pragma unroll
            for (int j = 0; j < 4; j++) hh[j] = packh(p0[j], p1[j]);
            *(uint4*)&Bh[s][bkp * LD + bnq] = make_uint4(hh[0], hh[1], hh[2], hh[3]);
        }
    };

    const int NIT = K / 16;
    ldg_tile(0);

    for (int it = 0; it < NIT; it++) {
        const int s = it & 1;
        sts_tile(s);
        __syncthreads();
        if (it + 1 < NIT) ldg_tile((it + 1) * 16);

        uint32_t bh[NF][2];
#pragma unroll
        for (int nf = 0; nf < NF; nf++) {
            int c0 = wn * WN + nf * 8 + g;
            bh[nf][0] = Bh[s][tg * LD + c0];
            bh[nf][1] = Bh[s][(tg + 4) * LD + c0];
        }
#pragma unroll
        for (int mf = 0; mf < MF; mf++) {
            int r0 = wm * WM + mf * 16 + g;
            uint32_t ah[4];
            ah[0] = Ah[s][tg * LD + r0];
            ah[1] = Ah[s][tg * LD + r0 + 8];
            ah[2] = Ah[s][(tg + 4) * LD + r0];
            ah[3] = Ah[s][(tg + 4) * LD + r0 + 8];
#pragma unroll
            for (int nf = 0; nf < NF; nf++)
                MMA_F16(acc[mf][nf], ah, bh[nf]);
        }
    }

#pragma unroll
    for (int mf = 0; mf < MF; mf++) {
#pragma unroll
        for (int nf = 0; nf < NF; nf++) {
            int row = rowBase + wm * WM + mf * 16 + g;
            int col = colBase + wn * WN + nf * 8 + tg * 2;
            if (OUT16) {
                __half* C16 = (__half*)Cv;
                if (row < Nr)
                    *(uint32_t*)(C16 + (size_t)row * M + col) =
                        packh(acc[mf][nf][0], acc[mf][nf][1]);
                if (row + 8 < Nr)
                    *(uint32_t*)(C16 + (size_t)(row + 8) * M + col) =
                        packh(acc[mf][nf][2], acc[mf][nf][3]);
            } else {
                float* C = (float*)Cv;
                float b0v = bias ? bias[col]     : 0.0f;
                float b1v = bias ? bias[col + 1] : 0.0f;
                if (row < Nr) {
                    float2 o = make_float2(acc[mf][nf][0] + b0v, acc[mf][nf][1] + b1v);
                    *(float2*)(C + (size_t)row * M + col) = o;
                }
                if (row + 8 < Nr) {
                    float2 o = make_float2(acc[mf][nf][2] + b0v, acc[mf][nf][3] + b1v);
                    *(float2*)(C + (size_t)(row + 8) * M + col) = o;
                }
            }
        }
    }
}

// =================== aggregation: one WARP per dst node =====================
__device__ __forceinline__ void acc8(float* acc, float a, uint4 r) {
    float2 f0 = __half22float2(*reinterpret_cast<const half2*>(&r.x));
    float2 f1 = __half22float2(*reinterpret_cast<const half2*>(&r.y));
    float2 f2 = __half22float2(*reinterpret_cast<const half2*>(&r.z));
    float2 f3 = __half22float2(*reinterpret_cast<const half2*>(&r.w));
    acc[0] += a * f0.x; acc[1] += a * f0.y;
    acc[2] += a * f1.x; acc[3] += a * f1.y;
    acc[4] += a * f2.x; acc[5] += a * f2.y;
    acc[6] += a * f3.x; acc[7] += a * f3.y;
}

__global__ void __launch_bounds__(256)
agg0_kernel(const int* __restrict__ rowptr, const int* __restrict__ adj,
            const float* __restrict__ el, const float* __restrict__ er,
            const __half* __restrict__ ft, const float* __restrict__ b0,
            const float* __restrict__ wel1,
            __half* __restrict__ h116,
            float* __restrict__ el1, float* __restrict__ er1,
            int nbase, int nend) {
    const int w = threadIdx.x >> 5;
    const int lane = threadIdx.x & 31;
    const int d = nbase + blockIdx.x * 8 + w;
    if (d >= nend) return;
    const int h = lane >> 3;
    const int start = rowptr[d], end = rowptr[d + 1];

    __shared__ float s_num[8][32][4];

    float4 erd = *(const float4*)(er + (size_t)d * 4);
    float lsum[4] = {0.f, 0.f, 0.f, 0.f};
    float acc[8] = {0.f, 0.f, 0.f, 0.f, 0.f, 0.f, 0.f, 0.f};

    int c = start;
    int n = min(32, end - c);
    int sidx = 0;
    float4 e4 = make_float4(0.f, 0.f, 0.f, 0.f);
    if (c < end && lane < n) {
        sidx = adj[c + lane];
        e4 = *(const float4*)(el + (size_t)sidx * 4);
    }

    while (c < end) {
        if (lane < n) {
            float v[4];
            v[0] = e4.x + erd.x; v[1] = e4.y + erd.y;
            v[2] = e4.z + erd.z; v[3] = e4.w + erd.w;
#pragma unroll
            for (int k = 0; k < 4; k++) {
                float vv = (v[k] >= 0.f) ? v[k] : NEG * v[k];
                float nu = __expf(vv);
                s_num[w][lane][k] = nu;
                lsum[k] += nu;
            }
        }
        __syncwarp();

        int c2 = c + 32;
        int n2 = min(32, end - c2);
        int sidx2 = 0;
        float4 e42 = make_float4(0.f, 0.f, 0.f, 0.f);
        if (c2 < end && lane < n2) {
            sidx2 = adj[c2 + lane];
            e42 = *(const float4*)(el + (size_t)sidx2 * 4);
        }

        int j = 0;
        for (; j + 4 <= n; j += 4) {
            int s0 = __shfl_sync(0xffffffffu, sidx, j);
            int s1 = __shfl_sync(0xffffffffu, sidx, j + 1);
            int s2 = __shfl_sync(0xffffffffu, sidx, j + 2);
            int s3 = __shfl_sync(0xffffffffu, sidx, j + 3);
            float a0 = s_num[w][j][h],     a1 = s_num[w][j + 1][h];
            float a2 = s_num[w][j + 2][h], a3 = s_num[w][j + 3][h];
            uint4 r0 = *(const uint4*)(ft + (size_t)s0 * 256 + lane * 8);
            uint4 r1 = *(const uint4*)(ft + (size_t)s1 * 256 + lane * 8);
            uint4 r2 = *(const uint4*)(ft + (size_t)s2 * 256 + lane * 8);
            uint4 r3 = *(const uint4*)(ft + (size_t)s3 * 256 + lane * 8);
            acc8(acc, a0, r0); acc8(acc, a1, r1);
            acc8(acc, a2, r2); acc8(acc, a3, r3);
        }
        for (; j < n; j++) {
            int s0 = __shfl_sync(0xffffffffu, sidx, j);
            float a0 = s_num[w][j][h];
            uint4 r0 = *(const uint4*)(ft + (size_t)s0 * 256 + lane * 8);
            acc8(acc, a0, r0);
        }
        __syncwarp();
        sidx = sidx2; e4 = e42; n = n2; c = c2;
    }

#pragma unroll
    for (int off = 16; off; off >>= 1)
#pragma unroll
        for (int k = 0; k < 4; k++)
            lsum[k] += __shfl_xor_sync(0xffffffffu, lsum[k], off);
    float tot = lsum[h];
    float inv = (tot > 0.f) ? (1.0f / tot) : 0.0f;

    float o[8];
    float sl = 0.f, sr = 0.f;
    const float* bb = b0 + lane * 8;
    const float* wl = wel1 + lane * 8;
    const float* wr = wel1 + 256 + lane * 8;
#pragma unroll
    for (int i = 0; i < 8; i++) {
        float v = acc[i] * inv + bb[i];
        v = (v > 0.f) ? v : expm1f(v);
        o[i] = v;
        sl += v * wl[i];
        sr += v * wr[i];
    }
    uint4 hp;
    hp.x = packh(o[0], o[1]); hp.y = packh(o[2], o[3]);
    hp.z = packh(o[4], o[5]); hp.w = packh(o[6], o[7]);
    *(uint4*)(h116 + (size_t)d * 256 + lane * 8) = hp;
#pragma unroll
    for (int off = 16; off; off >>= 1) {
        sl += __shfl_xor_sync(0xffffffffu, sl, off);
        sr += __shfl_xor_sync(0xffffffffu, sr, off);
    }
    if (lane == 0) { el1[d] = sl; er1[d] = sr; }
}

__global__ void __launch_bounds__(256)
agg1_kernel(const int* __restrict__ rowptr, const int* __restrict__ adj,
            const float* __restrict__ el, const float* __restrict__ er,
            const __half* __restrict__ ft, const __half* __restrict__ h116,
            const float* __restrict__ b1, float* __restrict__ hout,
            int nbase, int nend) {
    const int w = threadIdx.x >> 5;
    const int lane = threadIdx.x & 31;
    const int d = nbase + blockIdx.x * 8 + w;
    if (d >= nend) return;
    const int start = rowptr[d], end = rowptr[d + 1];

    float erd = er[d];
    float lsum = 0.f;
    float acc[8] = {0.f, 0.f, 0.f, 0.f, 0.f, 0.f, 0.f, 0.f};

    int c = start;
    int n = min(32, end - c);
    int sidx = 0;
    float elv = 0.f;
    if (c < end && lane < n) {
        sidx = adj[c + lane];
        elv = el[sidx];
    }

    while (c < end) {
        float nu = 0.f;
        if (lane < n) {
            float v = elv + erd;
            v = (v >= 0.f) ? v : NEG * v;
            nu = __expf(v);
            lsum += nu;
        }

        int c2 = c + 32;
        int n2 = min(32, end - c2);
        int sidx2 = 0;
        float elv2 = 0.f;
        if (c2 < end && lane < n2) {
            sidx2 = adj[c2 + lane];
            elv2 = el[sidx2];
        }

        int j = 0;
        for (; j + 4 <= n; j += 4) {
            int s0 = __shfl_sync(0xffffffffu, sidx, j);
            int s1 = __shfl_sync(0xffffffffu, sidx, j + 1);
            int s2 = __shfl_sync(0xffffffffu, sidx, j + 2);
            int s3 = __shfl_sync(0xffffffffu, sidx, j + 3);
            float a0 = __shfl_sync(0xffffffffu, nu, j);
            float a1 = __shfl_sync(0xffffffffu, nu, j + 1);
            float a2 = __shfl_sync(0xffffffffu, nu, j + 2);
            float a3 = __shfl_sync(0xffffffffu, nu, j + 3);
            uint4 r0 = *(const uint4*)(ft + (size_t)s0 * 256 + lane * 8);
            uint4 r1 = *(const uint4*)(ft + (size_t)s1 * 256 + lane * 8);
            uint4 r2 = *(const uint4*)(ft + (size_t)s2 * 256 + lane * 8);
            uint4 r3 = *(const uint4*)(ft + (size_t)s3 * 256 + lane * 8);
            acc8(acc, a0, r0); acc8(acc, a1, r1);
            acc8(acc, a2, r2); acc8(acc, a3, r3);
        }
        for (; j < n; j++) {
            int s0 = __shfl_sync(0xffffffffu, sidx, j);
            float a0 = __shfl_sync(0xffffffffu, nu, j);
            uint4 r0 = *(const uint4*)(ft + (size_t)s0 * 256 + lane * 8);
            acc8(acc, a0, r0);
        }
        sidx = sidx2; elv = elv2; n = n2; c = c2;
    }

#pragma unroll
    for (int off = 16; off; off >>= 1)
        lsum += __shfl_xor_sync(0xffffffffu, lsum, off);
    float inv = (lsum > 0.f) ? (1.0f / lsum) : 0.0f;

    uint4 hr = *(const uint4*)(h116 + (size_t)d * 256 + lane * 8);
    float2 h0 = __half22float2(*reinterpret_cast<const half2*>(&hr.x));
    float2 h1p = __half22float2(*reinterpret_cast<const half2*>(&hr.y));
    float2 h2 = __half22float2(*reinterpret_cast<const half2*>(&hr.z));
    float2 h3 = __half22float2(*reinterpret_cast<const half2*>(&hr.w));
    float4 bb0 = *(const float4*)(b1 + lane * 8);
    float4 bb1 = *(const float4*)(b1 + lane * 8 + 4);
    float4 o0, o1;
    o0.x = acc[0] * inv + h0.x  + bb0.x;
    o0.y = acc[1] * inv + h0.y  + bb0.y;
    o0.z = acc[2] * inv + h1p.x + bb0.z;
    o0.w = acc[3] * inv + h1p.y + bb0.w;
    o1.x = acc[4] * inv + h2.x  + bb1.x;
    o1.y = acc[5] * inv + h2.y  + bb1.y;
    o1.z = acc[6] * inv + h3.x  + bb1.z;
    o1.w = acc[7] * inv + h3.y  + bb1.w;
    *(float4*)(hout + (size_t)d * 256 + lane * 8)     = o0;
    *(float4*)(hout + (size_t)d * 256 + lane * 8 + 4) = o1;
}

// =================== launch ==================================================
extern "C" void kernel_launch(void* const* d_in, const int* in_sizes, int n_in,
                              void* d_out, int out_size) {
    const float* x   = (const float*)d_in[0];
    const int*   src = (const int*)  d_in[1];
    const int*   dst = (const int*)  d_in[2];
    const float* W0  = (const float*)d_in[3];
    const float* al0 = (const float*)d_in[4];
    const float* ar0 = (const float*)d_in[5];
    const float* b0  = (const float*)d_in[6];
    const float* W1  = (const float*)d_in[7];
    const float* al1 = (const float*)d_in[8];
    const float* ar1 = (const float*)d_in[9];
    const float* b1  = (const float*)d_in[10];
    const float* Wl  = (const float*)d_in[11];
    const float* bl  = (const float*)d_in[12];

    float* out    = (float*)d_out;
    float* logits = out;
    float* hout   = out + (size_t)NN * NCLS;

    __half *ft16, *ft16b, *h116;
    float *el, *er, *el1, *er1, *wel0, *wel1;
    int *cnt, *rowptr, *adj;
    cudaGetSymbolAddress((void**)&ft16,   g_ft16);
    cudaGetSymbolAddress((void**)&ft16b,  g_ft16b);
    cudaGetSymbolAddress((void**)&h116,   g_h116);
    cudaGetSymbolAddress((void**)&el,     g_el);
    cudaGetSymbolAddress((void**)&er,     g_er);
    cudaGetSymbolAddress((void**)&el1,    g_el1);
    cudaGetSymbolAddress((void**)&er1,    g_er1);
    cudaGetSymbolAddress((void**)&wel0,   g_wel0);
    cudaGetSymbolAddress((void**)&wel1,   g_wel1);
    cudaGetSymbolAddress((void**)&cnt,    g_cnt);
    cudaGetSymbolAddress((void**)&rowptr, g_rowptr);
    cudaGetSymbolAddress((void**)&adj,    g_adj);

    static cudaStream_t s1 = nullptr, s2 = nullptr;
    static cudaEvent_t ev_fork = nullptr, ev_csr = nullptr, ev_el0 = nullptr,
                       ev_g0 = nullptr, ev_pa_m = nullptr, ev_pa_s = nullptr,
                       ev_end = nullptr;
    if (s1 == nullptr) {
        cudaStreamCreateWithFlags(&s1, cudaStreamNonBlocking);
        cudaStreamCreateWithFlags(&s2, cudaStreamNonBlocking);
        cudaEventCreateWithFlags(&ev_fork, cudaEventDisableTiming);
        cudaEventCreateWithFlags(&ev_csr,  cudaEventDisableTiming);
        cudaEventCreateWithFlags(&ev_el0,  cudaEventDisableTiming);
        cudaEventCreateWithFlags(&ev_g0,   cudaEventDisableTiming);
        cudaEventCreateWithFlags(&ev_pa_m, cudaEventDisableTiming);
        cudaEventCreateWithFlags(&ev_pa_s, cudaEventDisableTiming);
        cudaEventCreateWithFlags(&ev_end,  cudaEventDisableTiming);
    }

    const int T = 256;
    const int cs[5] = {0, NCHUNK, 2 * NCHUNK, 3 * NCHUNK, NN};

    cudaEventRecord(ev_fork, 0);

    // ---- s1: CSR build (fused scan) ----
    cudaStreamWaitEvent(s1, ev_fork, 0);
    cudaMemsetAsync(cnt, 0, NN * sizeof(int), s1);
    hist_kernel<<<(EE + T - 1) / T, T, 0, s1>>>(dst, cnt);
    scan_fused_kernel<<<1, 1024, 0, s1>>>(cnt, rowptr, cnt);
    csr_fill_kernel<<<(EE + T - 1) / T, T, 0, s1>>>(src, dst, cnt, adj);
    cudaEventRecord(ev_csr, s1);

    // ---- s2: attention projections ----
    cudaStreamWaitEvent(s2, ev_fork, 0);
    prep_wel_kernel<<<64, 256, 0, s2>>>(W0, al0, ar0, W1, al1, ar1, wel0, wel1);
    eler0_kernel<<<(NN + 7) / 8, 256, 0, s2>>>(x, wel0, el, er);
    cudaEventRecord(ev_el0, s2);

    // ---- main: layer 0 projection ----
    {
        dim3 grid(2, (NN + 127) / 128);
        gemm_f16<128, 128, 2, 4, false, true><<<grid, 256>>>(x, W0, ft16, NN, IND, 256, nullptr);
    }
    cudaEventRecord(ev_g0, 0);

    // ---- phase A: agg0(Ci) -> GEMM1(Ci), C0/C2 on main, C1/C3 on s2 ----
    cudaStreamWaitEvent(0, ev_csr, 0);
    cudaStreamWaitEvent(0, ev_el0, 0);
    cudaStreamWaitEvent(s2, ev_g0, 0);
    cudaStreamWaitEvent(s2, ev_csr, 0);

    for (int i = 0; i < 4; i++) {
        cudaStream_t st = (i & 1) ? s2 : 0;
        int s = cs[i], e = cs[i + 1], nc = e - s;
        agg0_kernel<<<(nc + 7) / 8, 256, 0, st>>>(rowptr, adj, el, er, ft16, b0,
                                                  wel1, h116, el1, er1, s, e);
        dim3 grid(2, (nc + 127) / 128);
        gemm_f16<128, 128, 2, 4, true, true><<<grid, 256, 0, st>>>(
            h116 + (size_t)s * 256, W1, ft16b + (size_t)s * 256, nc, 256, 256, nullptr);
    }
    cudaEventRecord(ev_pa_m, 0);
    cudaEventRecord(ev_pa_s, s2);
    cudaStreamWaitEvent(0, ev_pa_s, 0);
    cudaStreamWaitEvent(s2, ev_pa_m, 0);

    // ---- phase B: agg1(Ci) -> cls(Ci), C0/C2 on main, C1/C3 on s2 ----
    for (int i = 0; i < 4; i++) {
        cudaStream_t st = (i & 1) ? s2 : 0;
        int s = cs[i], e = cs[i + 1], nc = e - s;
        agg1_kernel<<<(nc + 7) / 8, 256, 0, st>>>(rowptr, adj, el1, er1, ft16b,
                                                  h116, b1, hout, s, e);
        dim3 grid(1, (nc + 127) / 128);
        gemm_f16<128, 64, 4, 2, false, false><<<grid, 256, 0, st>>>(
            hout + (size_t)s * 256, Wl, logits + (size_t)s * 64, nc, OUT1, NCLS, bl);
    }
    cudaEventRecord(ev_end, s2);
    cudaStreamWaitEvent(0, ev_end, 0);
}

// round 17
// speedup vs baseline: 1.1378x; 1.0256x over previous
#include <cuda_runtime.h>
#include <cuda_fp16.h>
#include <math.h>
#include <stdint.h>

#define NN 50000
#define EE 800000
#define IND 256
#define HIDD 64
#define H0 4
#define OUT1 256
#define NCLS 64
#define NEG 0.2f
#define NCHUNK 12544   // pipeline chunk (98*128)

// ---------------- scratch (device globals; no allocation allowed) ----------
__device__ __half g_ft16[NN * 256];    // layer-0 projected features
__device__ __half g_ft16b[NN * 256];   // layer-1 projected features
__device__ __half g_h116[NN * 256];    // h1 in fp16
__device__ float  g_el[NN * H0];
__device__ float  g_er[NN * H0];
__device__ float  g_el1[NN];
__device__ float  g_er1[NN];
__device__ float  g_wel0[8 * 256];
__device__ float  g_wel1[2 * 256];
__device__ int    g_cnt[NN];
__device__ int    g_rowptr[NN + 1];
__device__ int    g_adj[EE];

// =================== CSR build ==============================================
__global__ void hist_kernel(const int* __restrict__ dst, int* __restrict__ cnt) {
    int e = blockIdx.x * blockDim.x + threadIdx.x;
    if (e < EE) atomicAdd(&cnt[dst[e]], 1);
}

__global__ void __launch_bounds__(1024)
scan_fused_kernel(const int* __restrict__ cnt,
                  int* __restrict__ rowptr, int* __restrict__ cursor) {
    __shared__ int s_warp[32];
    __shared__ int s_off;
    const int t = threadIdx.x;
    const int lane = t & 31;
    const int wid = t >> 5;
    if (t == 0) s_off = 0;
    __syncthreads();

    for (int base = 0; base < NN; base += 1024) {
        int i = base + t;
        int v = (i < NN) ? cnt[i] : 0;
        int ws = v;
#pragma unroll
        for (int o = 1; o < 32; o <<= 1) {
            int u = __shfl_up_sync(0xffffffffu, ws, o);
            if (lane >= o) ws += u;
        }
        if (lane == 31) s_warp[wid] = ws;
        __syncthreads();
        if (wid == 0) {
            int wv = s_warp[lane];
            int wscan = wv;
#pragma unroll
            for (int o = 1; o < 32; o <<= 1) {
                int u = __shfl_up_sync(0xffffffffu, wscan, o);
                if (lane >= o) wscan += u;
            }
            s_warp[lane] = wscan;
        }
        __syncthreads();
        int ex = ws - v + (wid > 0 ? s_warp[wid - 1] : 0) + s_off;
        if (i < NN) { rowptr[i] = ex; cursor[i] = ex; }
        __syncthreads();
        if (t == 0) s_off += s_warp[31];
        __syncthreads();
    }
    if (t == 0) rowptr[NN] = EE;
}

__global__ void csr_fill_kernel(const int* __restrict__ src,
                                const int* __restrict__ dst,
                                int* __restrict__ cursor,
                                int* __restrict__ adj) {
    int e = blockIdx.x * blockDim.x + threadIdx.x;
    if (e >= EE) return;
    int pos = atomicAdd(&cursor[dst[e]], 1);
    adj[pos] = src[e];
}

// =================== attention projection prep (warp-parallel) =============
__global__ void __launch_bounds__(256)
prep_wel_kernel(const float* __restrict__ W0,
                const float* __restrict__ al0,
                const float* __restrict__ ar0,
                const float* __restrict__ W1,
                const float* __restrict__ al1,
                const float* __restrict__ ar1,
                float* __restrict__ wel0,
                float* __restrict__ wel1) {
    const int warp = threadIdx.x >> 5;
    const int lane = threadIdx.x & 31;
    if (blockIdx.x < 32) {
        const int k = blockIdx.x * 8 + warp;
        const float* wrow = W0 + (size_t)k * 256;
#pragma unroll
        for (int j = 0; j < 4; j++) {
            float w0v = wrow[j * 64 + lane];
            float w1v = wrow[j * 64 + 32 + lane];
            float sl = w0v * al0[j * 64 + lane] + w1v * al0[j * 64 + 32 + lane];
            float sr = w0v * ar0[j * 64 + lane] + w1v * ar0[j * 64 + 32 + lane];
#pragma unroll
            for (int o = 16; o; o >>= 1) {
                sl += __shfl_xor_sync(0xffffffffu, sl, o);
                sr += __shfl_xor_sync(0xffffffffu, sr, o);
            }
            if (lane == 0) {
                wel0[j * 256 + k]       = sl;
                wel0[(4 + j) * 256 + k] = sr;
            }
        }
    } else {
        const int k = (blockIdx.x - 32) * 8 + warp;
        const float* wrow = W1 + (size_t)k * 256;
        float sl = 0.f, sr = 0.f;
#pragma unroll
        for (int it = 0; it < 8; it++) {
            float wv = wrow[it * 32 + lane];
            sl += wv * al1[it * 32 + lane];
            sr += wv * ar1[it * 32 + lane];
        }
#pragma unroll
        for (int o = 16; o; o >>= 1) {
            sl += __shfl_xor_sync(0xffffffffu, sl, o);
            sr += __shfl_xor_sync(0xffffffffu, sr, o);
        }
        if (lane == 0) {
            wel1[k]       = sl;
            wel1[256 + k] = sr;
        }
    }
}

__global__ void __launch_bounds__(256)
eler0_kernel(const float* __restrict__ X, const float* __restrict__ WelT,
             float* __restrict__ el, float* __restrict__ er) {
    __shared__ float w[8][256];
    int tid = threadIdx.x;
    for (int i = tid; i < 8 * 256; i += 256) ((float*)w)[i] = WelT[i];
    __syncthreads();
    int n = blockIdx.x * 8 + (tid >> 5);
    int lane = tid & 31;
    if (n >= NN) return;
    const float* xr = X + (size_t)n * 256;
    float acc[8];
#pragma unroll
    for (int j = 0; j < 8; j++) acc[j] = 0.f;
#pragma unroll
    for (int it = 0; it < 8; it++) {
        float xv = xr[lane + it * 32];
#pragma unroll
        for (int j = 0; j < 8; j++) acc[j] += xv * w[j][lane + it * 32];
    }
#pragma unroll
    for (int o = 16; o; o >>= 1)
#pragma unroll
        for (int j = 0; j < 8; j++) acc[j] += __shfl_xor_sync(0xffffffffu, acc[j], o);
    if (lane == 0) {
#pragma unroll
        for (int j = 0; j < 4; j++) el[n * 4 + j] = acc[j];
#pragma unroll
        for (int j = 0; j < 4; j++) er[n * 4 + j] = acc[4 + j];
    }
}

// =================== GEMM helpers ===========================================
__device__ __forceinline__ uint32_t packh(float f0, float f1) {
    uint32_t r;
    asm("cvt.rn.f16x2.f32 %0, %1, %2;" : "=r"(r) : "f"(f1), "f"(f0));
    return r;
}

#define MMA_F16(d, a, b) \
    asm volatile("mma.sync.aligned.m16n8k16.row.col.f32.f16.f16.f32 " \
                 "{%0,%1,%2,%3}, {%4,%5,%6,%7}, {%8,%9}, {%0,%1,%2,%3};" \
                 : "+f"(d[0]), "+f"(d[1]), "+f"(d[2]), "+f"(d[3]) \
                 : "r"(a[0]), "r"(a[1]), "r"(a[2]), "r"(a[3]), \
                   "r"(b[0]), "r"(b[1]))

// ---- fp16 single-term GEMM. AHALF: A fp16. OUT16: fp16 out (no bias),
//      else fp32 out + optional bias.
template<int BM, int BN, int WARPS_M, int WARPS_N, bool AHALF, bool OUT16>
__global__ void __launch_bounds__(256, 2)
gemm_f16(const void* __restrict__ Av, const float* __restrict__ B,
         void* __restrict__ Cv, int Nr, int K, int M,
         const float* __restrict__ bias) {
    constexpr int WM = BM / WARPS_M;
    constexpr int WN = BN / WARPS_N;
    constexpr int MF = WM / 16;
    constexpr int NF = WN / 8;
    constexpr int LD = 136;
    constexpr int STG = 8 * LD;
    constexpr int BQ = BN / 4;

    __shared__ uint32_t Ah[2][STG];
    __shared__ uint32_t Bh[2][STG];

    const float*  Af  = (const float*)Av;
    const __half* A16 = (const __half*)Av;

    const int tid  = threadIdx.x;
    const int lane = tid & 31;
    const int warp = tid >> 5;
    const int wm = warp / WARPS_N;
    const int wn = warp % WARPS_N;
    const int rowBase = blockIdx.y * BM;
    const int colBase = blockIdx.x * BN;
    const int g  = lane >> 2;
    const int tg = lane & 3;

    float acc[MF][NF][4];
#pragma unroll
    for (int i = 0; i < MF; i++)
#pragma unroll
        for (int j = 0; j < NF; j++)
#pragma unroll
            for (int k = 0; k < 4; k++) acc[i][j][k] = 0.0f;

    float4 ra[2];
    uint2  ra16[2];
    float4 rb0, rb1;
    const int am[2]  = { (tid) >> 2, (tid + 256) >> 2 };
    const int akq = (tid & 3) << 2;
    const bool bact = tid < 8 * BQ;
    const int bkp = bact ? tid / BQ : 0;
    const int bnq = bact ? (tid % BQ) << 2 : 0;

    auto ldg_tile = [&](int k0) {
#pragma unroll
        for (int i = 0; i < 2; i++) {
            int gr = rowBase + am[i];
            int grc = (gr < Nr) ? gr : (Nr - 1);
            if (AHALF)
                ra16[i] = *(const uint2*)(A16 + (size_t)grc * K + k0 + akq);
            else
                ra[i] = *(const float4*)(Af + (size_t)grc * K + k0 + akq);
        }
        if (bact) {
            rb0 = *(const float4*)(B + (size_t)(k0 + 2 * bkp)     * M + colBase + bnq);
            rb1 = *(const float4*)(B + (size_t)(k0 + 2 * bkp + 1) * M + colBase + bnq);
        }
    };

    auto sts_tile = [&](int s) {
#pragma unroll
        for (int i = 0; i < 2; i++) {
            int kp0 = (akq >> 1);
            if (AHALF) {
                Ah[s][kp0 * LD + am[i]]       = ra16[i].x;
                Ah[s][(kp0 + 1) * LD + am[i]] = ra16[i].y;
            } else {
                Ah[s][kp0 * LD + am[i]]       = packh(ra[i].x, ra[i].y);
                Ah[s][(kp0 + 1) * LD + am[i]] = packh(ra[i].z, ra[i].w);
            }
        }
        if (bact) {
            const float* p0 = &rb0.x;
            const float* p1 = &rb1.x;
            uint32_t hh[4];
#pragma unroll
            for (int j = 0; j < 4; j++) hh[j] = packh(p0[j], p1[j]);
            *(uint4*)&Bh[s][bkp * LD + bnq] = make_uint4(hh[0], hh[1], hh[2], hh[3]);
        }
    };

    const int NIT = K / 16;
    ldg_tile(0);

    for (int it = 0; it < NIT; it++) {
        const int s = it & 1;
        sts_tile(s);
        __syncthreads();
        if (it + 1 < NIT) ldg_tile((it + 1) * 16);

        uint32_t bh[NF][2];
#pragma unroll
        for (int nf = 0; nf < NF; nf++) {
            int c0 = wn * WN + nf * 8 + g;
            bh[nf][0] = Bh[s][tg * LD + c0];
            bh[nf][1] = Bh[s][(tg + 4) * LD + c0];
        }
#pragma unroll
        for (int mf = 0; mf < MF; mf++) {
            int r0 = wm * WM + mf * 16 + g;
            uint32_t ah[4];
            ah[0] = Ah[s][tg * LD + r0];
            ah[1] = Ah[s][tg * LD + r0 + 8];
            ah[2] = Ah[s][(tg + 4) * LD + r0];
            ah[3] = Ah[s][(tg + 4) * LD + r0 + 8];
#pragma unroll
            for (int nf = 0; nf < NF; nf++)
                MMA_F16(acc[mf][nf], ah, bh[nf]);
        }
    }

#pragma unroll
    for (int mf = 0; mf < MF; mf++) {
#pragma unroll
        for (int nf = 0; nf < NF; nf++) {
            int row = rowBase + wm * WM + mf * 16 + g;
            int col = colBase + wn * WN + nf * 8 + tg * 2;
            if (OUT16) {
                __half* C16 = (__half*)Cv;
                if (row < Nr)
                    *(uint32_t*)(C16 + (size_t)row * M + col) =
                        packh(acc[mf][nf][0], acc[mf][nf][1]);
                if (row + 8 < Nr)
                    *(uint32_t*)(C16 + (size_t)(row + 8) * M + col) =
                        packh(acc[mf][nf][2], acc[mf][nf][3]);
            } else {
                float* C = (float*)Cv;
                float b0v = bias ? bias[col]     : 0.0f;
                float b1v = bias ? bias[col + 1] : 0.0f;
                if (row < Nr) {
                    float2 o = make_float2(acc[mf][nf][0] + b0v, acc[mf][nf][1] + b1v);
                    *(float2*)(C + (size_t)row * M + col) = o;
                }
                if (row + 8 < Nr) {
                    float2 o = make_float2(acc[mf][nf][2] + b0v, acc[mf][nf][3] + b1v);
                    *(float2*)(C + (size_t)(row + 8) * M + col) = o;
                }
            }
        }
    }
}

// =================== aggregation: one WARP per dst node =====================
__device__ __forceinline__ void acc8(float* acc, float a, uint4 r) {
    float2 f0 = __half22float2(*reinterpret_cast<const half2*>(&r.x));
    float2 f1 = __half22float2(*reinterpret_cast<const half2*>(&r.y));
    float2 f2 = __half22float2(*reinterpret_cast<const half2*>(&r.z));
    float2 f3 = __half22float2(*reinterpret_cast<const half2*>(&r.w));
    acc[0] += a * f0.x; acc[1] += a * f0.y;
    acc[2] += a * f1.x; acc[3] += a * f1.y;
    acc[4] += a * f2.x; acc[5] += a * f2.y;
    acc[6] += a * f3.x; acc[7] += a * f3.y;
}

__global__ void __launch_bounds__(256)
agg0_kernel(const int* __restrict__ rowptr, const int* __restrict__ adj,
            const float* __restrict__ el, const float* __restrict__ er,
            const __half* __restrict__ ft, const float* __restrict__ b0,
            const float* __restrict__ wel1,
            __half* __restrict__ h116,
            float* __restrict__ el1, float* __restrict__ er1,
            int nbase, int nend) {
    const int w = threadIdx.x >> 5;
    const int lane = threadIdx.x & 31;
    const int d = nbase + blockIdx.x * 8 + w;
    if (d >= nend) return;
    const int h = lane >> 3;
    const int start = rowptr[d], end = rowptr[d + 1];

    __shared__ float s_num[8][32][4];

    float4 erd = *(const float4*)(er + (size_t)d * 4);
    float lsum[4] = {0.f, 0.f, 0.f, 0.f};
    float acc[8] = {0.f, 0.f, 0.f, 0.f, 0.f, 0.f, 0.f, 0.f};

    int c = start;
    int n = min(32, end - c);
    int sidx = 0;
    float4 e4 = make_float4(0.f, 0.f, 0.f, 0.f);
    if (c < end && lane < n) {
        sidx = adj[c + lane];
        e4 = *(const float4*)(el + (size_t)sidx * 4);
    }

    while (c < end) {
        if (lane < n) {
            float v[4];
            v[0] = e4.x + erd.x; v[1] = e4.y + erd.y;
            v[2] = e4.z + erd.z; v[3] = e4.w + erd.w;
#pragma unroll
            for (int k = 0; k < 4; k++) {
                float vv = (v[k] >= 0.f) ? v[k] : NEG * v[k];
                float nu = __expf(vv);
                s_num[w][lane][k] = nu;
                lsum[k] += nu;
            }
        }
        __syncwarp();

        int c2 = c + 32;
        int n2 = min(32, end - c2);
        int sidx2 = 0;
        float4 e42 = make_float4(0.f, 0.f, 0.f, 0.f);
        if (c2 < end && lane < n2) {
            sidx2 = adj[c2 + lane];
            e42 = *(const float4*)(el + (size_t)sidx2 * 4);
        }

        int j = 0;
        for (; j + 4 <= n; j += 4) {
            int s0 = __shfl_sync(0xffffffffu, sidx, j);
            int s1 = __shfl_sync(0xffffffffu, sidx, j + 1);
            int s2 = __shfl_sync(0xffffffffu, sidx, j + 2);
            int s3 = __shfl_sync(0xffffffffu, sidx, j + 3);
            float a0 = s_num[w][j][h],     a1 = s_num[w][j + 1][h];
            float a2 = s_num[w][j + 2][h], a3 = s_num[w][j + 3][h];
            uint4 r0 = *(const uint4*)(ft + (size_t)s0 * 256 + lane * 8);
            uint4 r1 = *(const uint4*)(ft + (size_t)s1 * 256 + lane * 8);
            uint4 r2 = *(const uint4*)(ft + (size_t)s2 * 256 + lane * 8);
            uint4 r3 = *(const uint4*)(ft + (size_t)s3 * 256 + lane * 8);
            acc8(acc, a0, r0); acc8(acc, a1, r1);
            acc8(acc, a2, r2); acc8(acc, a3, r3);
        }
        for (; j < n; j++) {
            int s0 = __shfl_sync(0xffffffffu, sidx, j);
            float a0 = s_num[w][j][h];
            uint4 r0 = *(const uint4*)(ft + (size_t)s0 * 256 + lane * 8);
            acc8(acc, a0, r0);
        }
        __syncwarp();
        sidx = sidx2; e4 = e42; n = n2; c = c2;
    }

#pragma unroll
    for (int off = 16; off; off >>= 1)
#pragma unroll
        for (int k = 0; k < 4; k++)
            lsum[k] += __shfl_xor_sync(0xffffffffu, lsum[k], off);
    float tot = lsum[h];
    float inv = (tot > 0.f) ? (1.0f / tot) : 0.0f;

    float o[8];
    float sl = 0.f, sr = 0.f;
    const float* bb = b0 + lane * 8;
    const float* wl = wel1 + lane * 8;
    const float* wr = wel1 + 256 + lane * 8;
#pragma unroll
    for (int i = 0; i < 8; i++) {
        float v = acc[i] * inv + bb[i];
        v = (v > 0.f) ? v : (__expf(v) - 1.0f);   // fast ELU (abs err ~1e-7)
        o[i] = v;
        sl += v * wl[i];
        sr += v * wr[i];
    }
    uint4 hp;
    hp.x = packh(o[0], o[1]); hp.y = packh(o[2], o[3]);
    hp.z = packh(o[4], o[5]); hp.w = packh(o[6], o[7]);
    *(uint4*)(h116 + (size_t)d * 256 + lane * 8) = hp;
#pragma unroll
    for (int off = 16; off; off >>= 1) {
        sl += __shfl_xor_sync(0xffffffffu, sl, off);
        sr += __shfl_xor_sync(0xffffffffu, sr, off);
    }
    if (lane == 0) { el1[d] = sl; er1[d] = sr; }
}

__global__ void __launch_bounds__(256)
agg1_kernel(const int* __restrict__ rowptr, const int* __restrict__ adj,
            const float* __restrict__ el, const float* __restrict__ er,
            const __half* __restrict__ ft, const __half* __restrict__ h116,
            const float* __restrict__ b1, float* __restrict__ hout,
            int nbase, int nend) {
    const int w = threadIdx.x >> 5;
    const int lane = threadIdx.x & 31;
    const int d = nbase + blockIdx.x * 8 + w;
    if (d >= nend) return;
    const int start = rowptr[d], end = rowptr[d + 1];

    float erd = er[d];
    float lsum = 0.f;
    float acc[8] = {0.f, 0.f, 0.f, 0.f, 0.f, 0.f, 0.f, 0.f};

    int c = start;
    int n = min(32, end - c);
    int sidx = 0;
    float elv = 0.f;
    if (c < end && lane < n) {
        sidx = adj[c + lane];
        elv = el[sidx];
    }

    while (c < end) {
        float nu = 0.f;
        if (lane < n) {
            float v = elv + erd;
            v = (v >= 0.f) ? v : NEG * v;
            nu = __expf(v);
            lsum += nu;
        }

        int c2 = c + 32;
        int n2 = min(32, end - c2);
        int sidx2 = 0;
        float elv2 = 0.f;
        if (c2 < end && lane < n2) {
            sidx2 = adj[c2 + lane];
            elv2 = el[sidx2];
        }

        int j = 0;
        for (; j + 4 <= n; j += 4) {
            int s0 = __shfl_sync(0xffffffffu, sidx, j);
            int s1 = __shfl_sync(0xffffffffu, sidx, j + 1);
            int s2 = __shfl_sync(0xffffffffu, sidx, j + 2);
            int s3 = __shfl_sync(0xffffffffu, sidx, j + 3);
            float a0 = __shfl_sync(0xffffffffu, nu, j);
            float a1 = __shfl_sync(0xffffffffu, nu, j + 1);
            float a2 = __shfl_sync(0xffffffffu, nu, j + 2);
            float a3 = __shfl_sync(0xffffffffu, nu, j + 3);
            uint4 r0 = *(const uint4*)(ft + (size_t)s0 * 256 + lane * 8);
            uint4 r1 = *(const uint4*)(ft + (size_t)s1 * 256 + lane * 8);
            uint4 r2 = *(const uint4*)(ft + (size_t)s2 * 256 + lane * 8);
            uint4 r3 = *(const uint4*)(ft + (size_t)s3 * 256 + lane * 8);
            acc8(acc, a0, r0); acc8(acc, a1, r1);
            acc8(acc, a2, r2); acc8(acc, a3, r3);
        }
        for (; j < n; j++) {
            int s0 = __shfl_sync(0xffffffffu, sidx, j);
            float a0 = __shfl_sync(0xffffffffu, nu, j);
            uint4 r0 = *(const uint4*)(ft + (size_t)s0 * 256 + lane * 8);
            acc8(acc, a0, r0);
        }
        sidx = sidx2; elv = elv2; n = n2; c = c2;
    }

#pragma unroll
    for (int off = 16; off; off >>= 1)
        lsum += __shfl_xor_sync(0xffffffffu, lsum, off);
    float inv = (lsum > 0.f) ? (1.0f / lsum) : 0.0f;

    uint4 hr = *(const uint4*)(h116 + (size_t)d * 256 + lane * 8);
    float2 h0 = __half22float2(*reinterpret_cast<const half2*>(&hr.x));
    float2 h1p = __half22float2(*reinterpret_cast<const half2*>(&hr.y));
    float2 h2 = __half22float2(*reinterpret_cast<const half2*>(&hr.z));
    float2 h3 = __half22float2(*reinterpret_cast<const half2*>(&hr.w));
    float4 bb0 = *(const float4*)(b1 + lane * 8);
    float4 bb1 = *(const float4*)(b1 + lane * 8 + 4);
    float4 o0, o1;
    o0.x = acc[0] * inv + h0.x  + bb0.x;
    o0.y = acc[1] * inv + h0.y  + bb0.y;
    o0.z = acc[2] * inv + h1p.x + bb0.z;
    o0.w = acc[3] * inv + h1p.y + bb0.w;
    o1.x = acc[4] * inv + h2.x  + bb1.x;
    o1.y = acc[5] * inv + h2.y  + bb1.y;
    o1.z = acc[6] * inv + h3.x  + bb1.z;
    o1.w = acc[7] * inv + h3.y  + bb1.w;
    *(float4*)(hout + (size_t)d * 256 + lane * 8)     = o0;
    *(float4*)(hout + (size_t)d * 256 + lane * 8 + 4) = o1;
}

// =================== launch ==================================================
extern "C" void kernel_launch(void* const* d_in, const int* in_sizes, int n_in,
                              void* d_out, int out_size) {
    const float* x   = (const float*)d_in[0];
    const int*   src = (const int*)  d_in[1];
    const int*   dst = (const int*)  d_in[2];
    const float* W0  = (const float*)d_in[3];
    const float* al0 = (const float*)d_in[4];
    const float* ar0 = (const float*)d_in[5];
    const float* b0  = (const float*)d_in[6];
    const float* W1  = (const float*)d_in[7];
    const float* al1 = (const float*)d_in[8];
    const float* ar1 = (const float*)d_in[9];
    const float* b1  = (const float*)d_in[10];
    const float* Wl  = (const float*)d_in[11];
    const float* bl  = (const float*)d_in[12];

    float* out    = (float*)d_out;
    float* logits = out;
    float* hout   = out + (size_t)NN * NCLS;

    __half *ft16, *ft16b, *h116;
    float *el, *er, *el1, *er1, *wel0, *wel1;
    int *cnt, *rowptr, *adj;
    cudaGetSymbolAddress((void**)&ft16,   g_ft16);
    cudaGetSymbolAddress((void**)&ft16b,  g_ft16b);
    cudaGetSymbolAddress((void**)&h116,   g_h116);
    cudaGetSymbolAddress((void**)&el,     g_el);
    cudaGetSymbolAddress((void**)&er,     g_er);
    cudaGetSymbolAddress((void**)&el1,    g_el1);
    cudaGetSymbolAddress((void**)&er1,    g_er1);
    cudaGetSymbolAddress((void**)&wel0,   g_wel0);
    cudaGetSymbolAddress((void**)&wel1,   g_wel1);
    cudaGetSymbolAddress((void**)&cnt,    g_cnt);
    cudaGetSymbolAddress((void**)&rowptr, g_rowptr);
    cudaGetSymbolAddress((void**)&adj,    g_adj);

    static cudaStream_t s1 = nullptr, s2 = nullptr;
    static cudaEvent_t ev_fork = nullptr, ev_csr = nullptr, ev_el0 = nullptr,
                       ev_g0 = nullptr, ev_pa_m = nullptr, ev_pa_s = nullptr,
                       ev_end = nullptr;
    if (s1 == nullptr) {
        cudaStreamCreateWithFlags(&s1, cudaStreamNonBlocking);
        cudaStreamCreateWithFlags(&s2, cudaStreamNonBlocking);
        cudaEventCreateWithFlags(&ev_fork, cudaEventDisableTiming);
        cudaEventCreateWithFlags(&ev_csr,  cudaEventDisableTiming);
        cudaEventCreateWithFlags(&ev_el0,  cudaEventDisableTiming);
        cudaEventCreateWithFlags(&ev_g0,   cudaEventDisableTiming);
        cudaEventCreateWithFlags(&ev_pa_m, cudaEventDisableTiming);
        cudaEventCreateWithFlags(&ev_pa_s, cudaEventDisableTiming);
        cudaEventCreateWithFlags(&ev_end,  cudaEventDisableTiming);
    }

    const int T = 256;
    const int cs[5] = {0, NCHUNK, 2 * NCHUNK, 3 * NCHUNK, NN};

    cudaEventRecord(ev_fork, 0);

    // ---- s1: CSR build (fused scan) ----
    cudaStreamWaitEvent(s1, ev_fork, 0);
    cudaMemsetAsync(cnt, 0, NN * sizeof(int), s1);
    hist_kernel<<<(EE + T - 1) / T, T, 0, s1>>>(dst, cnt);
    scan_fused_kernel<<<1, 1024, 0, s1>>>(cnt, rowptr, cnt);
    csr_fill_kernel<<<(EE + T - 1) / T, T, 0, s1>>>(src, dst, cnt, adj);
    cudaEventRecord(ev_csr, s1);

    // ---- s2: attention projections ----
    cudaStreamWaitEvent(s2, ev_fork, 0);
    prep_wel_kernel<<<64, 256, 0, s2>>>(W0, al0, ar0, W1, al1, ar1, wel0, wel1);
    eler0_kernel<<<(NN + 7) / 8, 256, 0, s2>>>(x, wel0, el, er);
    cudaEventRecord(ev_el0, s2);

    // ---- main: layer 0 projection ----
    {
        dim3 grid(2, (NN + 127) / 128);
        gemm_f16<128, 128, 2, 4, false, true><<<grid, 256>>>(x, W0, ft16, NN, IND, 256, nullptr);
    }
    cudaEventRecord(ev_g0, 0);

    // ---- phase A: aggs first, then GEMMs (per stream) ----
    cudaStreamWaitEvent(0, ev_csr, 0);
    cudaStreamWaitEvent(0, ev_el0, 0);
    cudaStreamWaitEvent(s2, ev_g0, 0);
    cudaStreamWaitEvent(s2, ev_csr, 0);

    for (int i = 0; i < 4; i++) {
        cudaStream_t st = (i & 1) ? s2 : 0;
        int s = cs[i], e = cs[i + 1], nc = e - s;
        agg0_kernel<<<(nc + 7) / 8, 256, 0, st>>>(rowptr, adj, el, er, ft16, b0,
                                                  wel1, h116, el1, er1, s, e);
    }
    for (int i = 0; i < 4; i++) {
        cudaStream_t st = (i & 1) ? s2 : 0;
        int s = cs[i], e = cs[i + 1], nc = e - s;
        dim3 grid(2, (nc + 127) / 128);
        gemm_f16<128, 128, 2, 4, true, true><<<grid, 256, 0, st>>>(
            h116 + (size_t)s * 256, W1, ft16b + (size_t)s * 256, nc, 256, 256, nullptr);
    }
    cudaEventRecord(ev_pa_m, 0);
    cudaEventRecord(ev_pa_s, s2);
    cudaStreamWaitEvent(0, ev_pa_s, 0);
    cudaStreamWaitEvent(s2, ev_pa_m, 0);

    // ---- phase B: aggs first, then classifiers (per stream) ----
    for (int i = 0; i < 4; i++) {
        cudaStream_t st = (i & 1) ? s2 : 0;
        int s = cs[i], e = cs[i + 1], nc = e - s;
        agg1_kernel<<<(nc + 7) / 8, 256, 0, st>>>(rowptr, adj, el1, er1, ft16b,
                                                  h116, b1, hout, s, e);
    }
    for (int i = 0; i < 4; i++) {
        cudaStream_t st = (i & 1) ? s2 : 0;
        int s = cs[i], e = cs[i + 1], nc = e - s;
        dim3 grid(1, (nc + 127) / 128);
        gemm_f16<128, 64, 4, 2, false, false><<<grid, 256, 0, st>>>(
            hout + (size_t)s * 256, Wl, logits + (size_t)s * 64, nc, OUT1, NCLS, bl);
    }
    cudaEventRecord(ev_end, s2);
    cudaStreamWaitEvent(0, ev_end, 0);
}